// round 1
// baseline (speedup 1.0000x reference)
#include <cuda_runtime.h>
#include <math.h>

// ---------------- problem constants ----------------
#define BATCH  4
#define MQ     1024      // query tokens per batch
#define NKV    2048      // kv tokens per batch
#define DMODEL 1024
#define NHEAD  16
#define HDIM   64
#define DMLP   4096

// ---------------- scratch (device globals; no allocs allowed) ----------------
__device__ float g_qp   [(size_t)BATCH*MQ*DMODEL];   // 16 MB
__device__ float g_kp   [(size_t)BATCH*NKV*DMODEL];  // 32 MB
__device__ float g_vp   [(size_t)BATCH*NKV*DMODEL];  // 32 MB
__device__ float g_ctx  [(size_t)BATCH*MQ*DMODEL];   // 16 MB
__device__ float g_resid[(size_t)BATCH*MQ*DMODEL];   // 16 MB
__device__ float g_h    [(size_t)BATCH*MQ*DMODEL];   // 16 MB
__device__ float g_h1   [(size_t)BATCH*MQ*DMLP];     // 64 MB

// ---------------- generic fp32 tiled GEMM ----------------
// C[m,n] = alpha * sum_k A[m,k] * B'(k,n)  (+bias[n]) (+epilogue)
// TRANS_B=1: B'(k,n) = B[n*ldb + k]  (NT: both operands row-major, K inner)
// TRANS_B=0: B'(k,n) = B[k*ldb + n]  (NN)
// EPI: 0 = none, 1 = add Dadd[m,n], 2 = exact GELU
#define TM 64
#define TN 64
#define TK 16

__device__ __forceinline__ float gelu_exact(float v) {
    return 0.5f * v * (1.0f + erff(v * 0.70710678118654752440f));
}

template<int TRANS_B, int EPI>
__device__ __forceinline__ void gemm_tile(
    const float* __restrict__ A, const float* __restrict__ Bm,
    const float* __restrict__ bias, const float* __restrict__ Dadd,
    float* __restrict__ C,
    int K, int lda, int ldb, int ldc, int ldd, float alpha)
{
    __shared__ float As[TK][TM];
    __shared__ float Bs[TK][TN];

    const int tid = threadIdx.x;          // 256 threads
    const int tx  = tid & 15;             // 16 cols of threads
    const int ty  = tid >> 4;             // 16 rows of threads
    const int m0  = blockIdx.y * TM;
    const int n0  = blockIdx.x * TN;

    float acc[4][4];
    #pragma unroll
    for (int i = 0; i < 4; i++)
        #pragma unroll
        for (int j = 0; j < 4; j++) acc[i][j] = 0.0f;

    for (int k0 = 0; k0 < K; k0 += TK) {
        // load A tile: 64 rows x 16 k
        #pragma unroll
        for (int i = 0; i < 4; i++) {
            int l = tid + i * 256;
            int r = l >> 4, c = l & 15;
            As[c][r] = A[(long long)(m0 + r) * lda + (k0 + c)];
        }
        if (TRANS_B) {
            #pragma unroll
            for (int i = 0; i < 4; i++) {
                int l = tid + i * 256;
                int r = l >> 4, c = l & 15;          // r = out-col, c = k
                Bs[c][r] = Bm[(long long)(n0 + r) * ldb + (k0 + c)];
            }
        } else {
            #pragma unroll
            for (int i = 0; i < 4; i++) {
                int l = tid + i * 256;
                int r = l >> 6, c = l & 63;          // r = k, c = out-col
                Bs[r][c] = Bm[(long long)(k0 + r) * ldb + (n0 + c)];
            }
        }
        __syncthreads();

        #pragma unroll
        for (int kk = 0; kk < TK; kk++) {
            float a[4], b[4];
            #pragma unroll
            for (int i = 0; i < 4; i++) a[i] = As[kk][ty * 4 + i];
            #pragma unroll
            for (int j = 0; j < 4; j++) b[j] = Bs[kk][tx * 4 + j];
            #pragma unroll
            for (int i = 0; i < 4; i++)
                #pragma unroll
                for (int j = 0; j < 4; j++) acc[i][j] = fmaf(a[i], b[j], acc[i][j]);
        }
        __syncthreads();
    }

    #pragma unroll
    for (int i = 0; i < 4; i++) {
        int m = m0 + ty * 4 + i;
        #pragma unroll
        for (int j = 0; j < 4; j++) {
            int n = n0 + tx * 4 + j;
            float v = acc[i][j] * alpha;
            if (bias) v += bias[n];
            if (EPI == 2) v = gelu_exact(v);
            if (EPI == 1) v += Dadd[(long long)m * ldd + n];
            C[(long long)m * ldc + n] = v;
        }
    }
}

template<int TRANS_B, int EPI>
__global__ void __launch_bounds__(256)
k_gemm(const float* __restrict__ A, const float* __restrict__ Bm,
       const float* __restrict__ bias, const float* __restrict__ Dadd,
       float* __restrict__ C, int K, int lda, int ldb, int ldc, int ldd, float alpha)
{
    gemm_tile<TRANS_B, EPI>(A, Bm, bias, Dadd, C, K, lda, ldb, ldc, ldd, alpha);
}

// ---------------- attention scores: attn[h,b,m,n] = (qp . kp) / sqrt(HD) ----------------
__global__ void __launch_bounds__(256)
k_scores(const float* __restrict__ qp, const float* __restrict__ kp,
         float* __restrict__ attn)
{
    int z = blockIdx.z;                  // z = h*BATCH + b
    int h = z / BATCH, b = z % BATCH;
    const float* A  = qp + (long long)b * MQ  * DMODEL + h * HDIM;
    const float* Bm = kp + (long long)b * NKV * DMODEL + h * HDIM;
    float*       C  = attn + (long long)z * MQ * NKV;
    gemm_tile<1, 0>(A, Bm, nullptr, nullptr, C, HDIM, DMODEL, DMODEL, NKV, 0, 0.125f);
}

// ---------------- ctx[b,m,h,:] = attn[h,b,m,:] @ vp[b,:,h,:] ----------------
__global__ void __launch_bounds__(256)
k_ctx(const float* __restrict__ attn, const float* __restrict__ vp,
      float* __restrict__ ctx)
{
    int z = blockIdx.z;                  // z = h*BATCH + b
    int h = z / BATCH, b = z % BATCH;
    const float* A  = attn + (long long)z * MQ * NKV;
    const float* Bm = vp  + (long long)b * NKV * DMODEL + h * HDIM;
    float*       C  = ctx + (long long)b * MQ  * DMODEL + h * HDIM;
    gemm_tile<0, 0>(A, Bm, nullptr, nullptr, C, NKV, NKV, DMODEL, DMODEL, 0, 1.0f);
}

// ---------------- row softmax over last dim (NKV=2048), in place ----------------
__global__ void __launch_bounds__(256)
k_softmax(float* __restrict__ attn)
{
    __shared__ float red[256];
    const long long row = blockIdx.x;
    float* p = attn + row * (long long)NKV;
    const int t = threadIdx.x;

    float v[8];
    float mx = -1e30f;
    #pragma unroll
    for (int i = 0; i < 8; i++) { v[i] = p[t + i * 256]; mx = fmaxf(mx, v[i]); }
    red[t] = mx; __syncthreads();
    for (int s = 128; s > 0; s >>= 1) { if (t < s) red[t] = fmaxf(red[t], red[t + s]); __syncthreads(); }
    mx = red[0]; __syncthreads();

    float sum = 0.0f;
    #pragma unroll
    for (int i = 0; i < 8; i++) { v[i] = expf(v[i] - mx); sum += v[i]; }
    red[t] = sum; __syncthreads();
    for (int s = 128; s > 0; s >>= 1) { if (t < s) red[t] += red[t + s]; __syncthreads(); }
    const float inv = 1.0f / red[0];

    #pragma unroll
    for (int i = 0; i < 8; i++) p[t + i * 256] = v[i] * inv;
}

// ---------------- layernorm over D=1024 ----------------
__global__ void __launch_bounds__(256)
k_ln(const float* __restrict__ x, const float* __restrict__ g,
     const float* __restrict__ b, float* __restrict__ o)
{
    __shared__ float r1[256], r2[256];
    const long long row = blockIdx.x;
    const float* p = x + row * (long long)DMODEL;
    const int t = threadIdx.x;

    float v[4]; float s = 0.0f, s2 = 0.0f;
    #pragma unroll
    for (int i = 0; i < 4; i++) {
        v[i] = p[t + i * 256];
        s += v[i]; s2 += v[i] * v[i];
    }
    r1[t] = s; r2[t] = s2; __syncthreads();
    for (int st = 128; st > 0; st >>= 1) {
        if (t < st) { r1[t] += r1[t + st]; r2[t] += r2[t + st]; }
        __syncthreads();
    }
    const float mu  = r1[0] * (1.0f / DMODEL);
    const float var = r2[0] * (1.0f / DMODEL) - mu * mu;
    const float inv = rsqrtf(var + 1e-5f);

    float* po = o + row * (long long)DMODEL;
    #pragma unroll
    for (int i = 0; i < 4; i++) {
        int c = t + i * 256;
        po[c] = (v[i] - mu) * inv * g[c] + b[c];
    }
}

// ---------------- launch ----------------
extern "C" void kernel_launch(void* const* d_in, const int* in_sizes, int n_in,
                              void* d_out, int out_size)
{
    const float* x    = (const float*)d_in[0];
    const float* q    = (const float*)d_in[1];
    const float* w_q  = (const float*)d_in[2];
    const float* b_q  = (const float*)d_in[3];
    const float* w_k  = (const float*)d_in[4];
    const float* b_k  = (const float*)d_in[5];
    const float* w_v  = (const float*)d_in[6];
    const float* b_v  = (const float*)d_in[7];
    const float* w_o  = (const float*)d_in[8];
    const float* b_o  = (const float*)d_in[9];
    const float* ln2g = (const float*)d_in[10];
    const float* ln2b = (const float*)d_in[11];
    const float* w1   = (const float*)d_in[12];
    const float* b1   = (const float*)d_in[13];
    const float* w2   = (const float*)d_in[14];
    const float* b2   = (const float*)d_in[15];

    float* out  = (float*)d_out;                                     // [B,M,D]
    float* attn = out + (long long)BATCH * MQ * DMODEL;              // [H,B,M,N]

    float *qp, *kp, *vp, *ctx, *resid, *h, *h1;
    cudaGetSymbolAddress((void**)&qp,    g_qp);
    cudaGetSymbolAddress((void**)&kp,    g_kp);
    cudaGetSymbolAddress((void**)&vp,    g_vp);
    cudaGetSymbolAddress((void**)&ctx,   g_ctx);
    cudaGetSymbolAddress((void**)&resid, g_resid);
    cudaGetSymbolAddress((void**)&h,     g_h);
    cudaGetSymbolAddress((void**)&h1,    g_h1);

    const dim3 blk(256);

    // Q/K/V projections (NT, K=1024)
    k_gemm<1,0><<<dim3(DMODEL/64, (BATCH*MQ)/64),  blk>>>(q, w_q, b_q, nullptr, qp,
        DMODEL, DMODEL, DMODEL, DMODEL, 0, 1.0f);
    k_gemm<1,0><<<dim3(DMODEL/64, (BATCH*NKV)/64), blk>>>(x, w_k, b_k, nullptr, kp,
        DMODEL, DMODEL, DMODEL, DMODEL, 0, 1.0f);
    k_gemm<1,0><<<dim3(DMODEL/64, (BATCH*NKV)/64), blk>>>(x, w_v, b_v, nullptr, vp,
        DMODEL, DMODEL, DMODEL, DMODEL, 0, 1.0f);

    // scores -> attn (unnormalized), layout [H,B,M,N]
    k_scores<<<dim3(NKV/64, MQ/64, BATCH*NHEAD), blk>>>(qp, kp, attn);

    // softmax in place
    k_softmax<<<BATCH*NHEAD*MQ, blk>>>(attn);

    // ctx = attn @ V
    k_ctx<<<dim3(HDIM/64, MQ/64, BATCH*NHEAD), blk>>>(attn, vp, ctx);

    // resid = ctx @ w_o^T + b_o + q
    k_gemm<1,1><<<dim3(DMODEL/64, (BATCH*MQ)/64), blk>>>(ctx, w_o, b_o, q, resid,
        DMODEL, DMODEL, DMODEL, DMODEL, DMODEL, 1.0f);

    // h = layernorm(resid)
    k_ln<<<BATCH*MQ, blk>>>(resid, ln2g, ln2b, h);

    // h1 = gelu(h @ w1^T + b1)
    k_gemm<1,2><<<dim3(DMLP/64, (BATCH*MQ)/64), blk>>>(h, w1, b1, nullptr, h1,
        DMODEL, DMODEL, DMODEL, DMLP, 0, 1.0f);

    // out = h1 @ w2^T + b2 + resid
    k_gemm<1,1><<<dim3(DMODEL/64, (BATCH*MQ)/64), blk>>>(h1, w2, b2, resid, out,
        DMLP, DMLP, DMLP, DMODEL, DMODEL, 1.0f);
}

// round 3
// speedup vs baseline: 4.6019x; 4.6019x over previous
#include <cuda_runtime.h>
#include <cuda_bf16.h>
#include <math.h>
#include <stdint.h>

// ---------------- problem constants ----------------
#define BATCH  4
#define MQ     1024
#define NKV    2048
#define DMODEL 1024
#define NHEAD  16
#define HDIM   64
#define DMLP   4096
#define ZHB    (NHEAD*BATCH)

typedef __nv_bfloat16 bf16;

// ---------------- scratch (device globals; no allocs allowed) ----------------
__device__ __align__(1024) float g_vp   [(size_t)BATCH*NKV*DMODEL];
__device__ __align__(1024) float g_resid[(size_t)BATCH*MQ*DMODEL];

__device__ __align__(1024) bf16 g_qh [(size_t)BATCH*MQ*DMODEL];
__device__ __align__(1024) bf16 g_ql [(size_t)BATCH*MQ*DMODEL];
__device__ __align__(1024) bf16 g_xh [(size_t)BATCH*NKV*DMODEL];
__device__ __align__(1024) bf16 g_xl [(size_t)BATCH*NKV*DMODEL];
__device__ __align__(1024) bf16 g_wqh[(size_t)DMODEL*DMODEL];
__device__ __align__(1024) bf16 g_wql[(size_t)DMODEL*DMODEL];
__device__ __align__(1024) bf16 g_wkh[(size_t)DMODEL*DMODEL];
__device__ __align__(1024) bf16 g_wkl[(size_t)DMODEL*DMODEL];
__device__ __align__(1024) bf16 g_wvh[(size_t)DMODEL*DMODEL];
__device__ __align__(1024) bf16 g_wvl[(size_t)DMODEL*DMODEL];
__device__ __align__(1024) bf16 g_woh[(size_t)DMODEL*DMODEL];
__device__ __align__(1024) bf16 g_wol[(size_t)DMODEL*DMODEL];
__device__ __align__(1024) bf16 g_w1h[(size_t)DMLP*DMODEL];
__device__ __align__(1024) bf16 g_w1l[(size_t)DMLP*DMODEL];
__device__ __align__(1024) bf16 g_w2h[(size_t)DMODEL*DMLP];
__device__ __align__(1024) bf16 g_w2l[(size_t)DMODEL*DMLP];
__device__ __align__(1024) bf16 g_qph[(size_t)BATCH*MQ*DMODEL];
__device__ __align__(1024) bf16 g_qpl[(size_t)BATCH*MQ*DMODEL];
__device__ __align__(1024) bf16 g_kph[(size_t)BATCH*NKV*DMODEL];
__device__ __align__(1024) bf16 g_kpl[(size_t)BATCH*NKV*DMODEL];
__device__ __align__(1024) bf16 g_vth[(size_t)ZHB*HDIM*NKV];
__device__ __align__(1024) bf16 g_vtl[(size_t)ZHB*HDIM*NKV];
__device__ __align__(1024) bf16 g_ath[(size_t)ZHB*MQ*NKV];
__device__ __align__(1024) bf16 g_atl[(size_t)ZHB*MQ*NKV];
__device__ __align__(1024) bf16 g_ctxh[(size_t)BATCH*MQ*DMODEL];
__device__ __align__(1024) bf16 g_ctxl[(size_t)BATCH*MQ*DMODEL];
__device__ __align__(1024) bf16 g_hh [(size_t)BATCH*MQ*DMODEL];
__device__ __align__(1024) bf16 g_hl [(size_t)BATCH*MQ*DMODEL];
__device__ __align__(1024) bf16 g_h1h[(size_t)BATCH*MQ*DMLP];
__device__ __align__(1024) bf16 g_h1l[(size_t)BATCH*MQ*DMLP];

// ---------------- helpers ----------------
#define SW128(o) ((uint32_t)(o) ^ ((((uint32_t)(o)) >> 3) & 0x70u))

__device__ __forceinline__ uint32_t smem_u32(const void* p) {
    return (uint32_t)__cvta_generic_to_shared(p);
}

__device__ __forceinline__ void cp16(uint32_t dst, const void* src) {
    asm volatile("cp.async.cg.shared.global [%0], [%1], 16;" :: "r"(dst), "l"(src));
}
#define CP_COMMIT() asm volatile("cp.async.commit_group;" ::: "memory")
#define CP_WAIT0()  asm volatile("cp.async.wait_group 0;" ::: "memory")
#define CP_WAIT1()  asm volatile("cp.async.wait_group 1;" ::: "memory")

#define LDSM4(r0, r1, r2, r3, addr) \
    asm volatile("ldmatrix.sync.aligned.m8n8.x4.shared.b16 {%0,%1,%2,%3}, [%4];" \
        : "=r"(r0), "=r"(r1), "=r"(r2), "=r"(r3) : "r"(addr))

__device__ __forceinline__ void mma_bf16(float* c, const uint32_t* a, const uint32_t* b) {
    asm volatile(
        "mma.sync.aligned.m16n8k16.row.col.f32.bf16.bf16.f32 "
        "{%0,%1,%2,%3}, {%4,%5,%6,%7}, {%8,%9}, {%0,%1,%2,%3};"
        : "+f"(c[0]), "+f"(c[1]), "+f"(c[2]), "+f"(c[3])
        : "r"(a[0]), "r"(a[1]), "r"(a[2]), "r"(a[3]), "r"(b[0]), "r"(b[1]));
}

__device__ __forceinline__ float gelu_exact(float v) {
    return 0.5f * v * (1.0f + erff(v * 0.70710678118654752440f));
}

// ---------------- chunk loader (one 64-elem K slab, hi+lo, SW128 rows) ----------------
template<int TN>
__device__ __forceinline__ void load_chunk(
    uint32_t st, const bf16* __restrict__ Ah, const bf16* __restrict__ Al,
    const bf16* __restrict__ Bh, const bf16* __restrict__ Bl,
    int m0, int n0, long long kc, int lda, int ldb, int tid)
{
    constexpr int A_BYTES = 128 * 128;
    constexpr int B_BYTES = TN * 128;
    #pragma unroll
    for (int it = 0; it < 4; it++) {
        int idx = tid + it * 256;
        int r = idx >> 3, c = idx & 7;
        uint32_t so = SW128(r * 128 + c * 16);
        long long go = (long long)(m0 + r) * lda + kc + c * 8;
        cp16(st + so,           Ah + go);
        cp16(st + A_BYTES + so, Al + go);
    }
    #pragma unroll
    for (int it = 0; it < TN / 32; it++) {
        int idx = tid + it * 256;
        int r = idx >> 3, c = idx & 7;
        uint32_t so = SW128(r * 128 + c * 16);
        long long go = (long long)(n0 + r) * ldb + kc + c * 8;
        cp16(st + 2 * A_BYTES + so,           Bh + go);
        cp16(st + 2 * A_BYTES + B_BYTES + so, Bl + go);
    }
    CP_COMMIT();
}

// ---------------- split-bf16 GEMM via mma.sync (HMMA) ----------------
// C[m0:128, n0:TN] = alpha * A . B^T  (+bias) (+epilogue). A,B K-major bf16 hi/lo.
// EPI: 0 none, 1 +Dadd, 2 gelu. OF32: write fp32 C. OBF16: write bf16 hi/lo.
template<int TN, int EPI, bool OF32, bool OBF16>
__device__ void tc_gemm(
    const bf16* __restrict__ Ah, const bf16* __restrict__ Al,
    const bf16* __restrict__ Bh, const bf16* __restrict__ Bl,
    const float* __restrict__ bias, const float* __restrict__ Dadd,
    float* __restrict__ C, bf16* __restrict__ Chi, bf16* __restrict__ Clo,
    int K, int lda, int ldb, int ldc, int ldd, float alpha)
{
    extern __shared__ char smem[];
    constexpr int A_BYTES = 128 * 128;
    constexpr int B_BYTES = TN * 128;
    constexpr int STAGE   = 2 * A_BYTES + 2 * B_BYTES;
    constexpr int WC = TN / 32;        // warps along N
    constexpr int WR = 8 / WC;         // warps along M
    constexpr int WM = 128 / WR;       // rows per warp
    constexpr int MI = WM / 16;        // m16 tiles per warp

    const uint32_t sb = smem_u32(smem);
    const int tid  = threadIdx.x;
    const int wid  = tid >> 5;
    const int lane = tid & 31;
    const int m0 = blockIdx.y * 128;
    const int n0 = blockIdx.x * TN;
    const int wm0 = (wid / WC) * WM;
    const int wn0 = (wid % WC) * 32;

    float acc[MI][4][4];
    #pragma unroll
    for (int mi = 0; mi < MI; mi++)
        #pragma unroll
        for (int ni = 0; ni < 4; ni++)
            #pragma unroll
            for (int e = 0; e < 4; e++) acc[mi][ni][e] = 0.0f;

    const int NC = K >> 6;
    load_chunk<TN>(sb, Ah, Al, Bh, Bl, m0, n0, 0, lda, ldb, tid);
    if (NC > 1)
        load_chunk<TN>(sb + STAGE, Ah, Al, Bh, Bl, m0, n0, 64, lda, ldb, tid);

    for (int i = 0; i < NC; i++) {
        if (i + 1 < NC) { CP_WAIT1(); } else { CP_WAIT0(); }
        __syncthreads();

        const uint32_t st = sb + (i & 1) * STAGE;
        #pragma unroll
        for (int kk = 0; kk < 4; kk++) {
            uint32_t ah[MI][4], al[MI][4], bh[4][2], bl[4][2];
            const int colA = kk * 32 + ((lane & 16) ? 16 : 0);
            const int rA   = lane & 15;
            #pragma unroll
            for (int mi = 0; mi < MI; mi++) {
                uint32_t off = SW128((uint32_t)(wm0 + mi * 16 + rA) * 128 + colA);
                LDSM4(ah[mi][0], ah[mi][1], ah[mi][2], ah[mi][3], st + off);
                LDSM4(al[mi][0], al[mi][1], al[mi][2], al[mi][3], st + A_BYTES + off);
            }
            const int colB = kk * 32 + ((lane & 8) ? 16 : 0);
            const int rB   = (lane & 7) + ((lane & 16) ? 8 : 0);
            #pragma unroll
            for (int nj = 0; nj < 2; nj++) {
                uint32_t off = SW128((uint32_t)(wn0 + nj * 16 + rB) * 128 + colB);
                LDSM4(bh[nj*2][0], bh[nj*2][1], bh[nj*2+1][0], bh[nj*2+1][1],
                      st + 2 * A_BYTES + off);
                LDSM4(bl[nj*2][0], bl[nj*2][1], bl[nj*2+1][0], bl[nj*2+1][1],
                      st + 2 * A_BYTES + B_BYTES + off);
            }
            #pragma unroll
            for (int mi = 0; mi < MI; mi++)
                #pragma unroll
                for (int ni = 0; ni < 4; ni++) {
                    mma_bf16(acc[mi][ni], ah[mi], bh[ni]);
                    mma_bf16(acc[mi][ni], ah[mi], bl[ni]);
                    mma_bf16(acc[mi][ni], al[mi], bh[ni]);
                }
        }
        __syncthreads();
        if (i + 2 < NC)
            load_chunk<TN>(sb + (i & 1) * STAGE, Ah, Al, Bh, Bl, m0, n0,
                           (long long)(i + 2) * 64, lda, ldb, tid);
    }

    // ---------------- epilogue: regs -> smem -> coalesced gmem ----------------
    constexpr int LDS = TN + 8;
    float* sOut = (float*)smem;
    __syncthreads();   // stage smem no longer needed

    #pragma unroll
    for (int mi = 0; mi < MI; mi++) {
        const int r0 = wm0 + mi * 16 + (lane >> 2);
        #pragma unroll
        for (int ni = 0; ni < 4; ni++) {
            const int c0 = wn0 + ni * 8 + (lane & 3) * 2;
            sOut[r0 * LDS + c0]           = acc[mi][ni][0];
            sOut[r0 * LDS + c0 + 1]       = acc[mi][ni][1];
            sOut[(r0 + 8) * LDS + c0]     = acc[mi][ni][2];
            sOut[(r0 + 8) * LDS + c0 + 1] = acc[mi][ni][3];
        }
    }
    __syncthreads();

    constexpr int RPI = 256 / TN;
    const int c = tid & (TN - 1);
    const int rs = tid / TN;
    const int n = n0 + c;
    #pragma unroll 4
    for (int rr = 0; rr < 128; rr += RPI) {
        const int r = rr + rs;
        float v = sOut[r * LDS + c] * alpha;
        if (bias) v += bias[n];
        if (EPI == 2) v = gelu_exact(v);
        if (EPI == 1) v += Dadd[(long long)(m0 + r) * ldd + n];
        const long long o = (long long)(m0 + r) * ldc + n;
        if (OF32) C[o] = v;
        if (OBF16) {
            bf16 hi = __float2bfloat16(v);
            Chi[o] = hi;
            Clo[o] = __float2bfloat16(v - __bfloat162float(hi));
        }
    }
}

// ---------------- kernel wrappers ----------------
template<int EPI, bool OF32, bool OBF16>
__global__ void __launch_bounds__(256, 1)
k_dense(const bf16* Ah, const bf16* Al, const bf16* Bh, const bf16* Bl,
        const float* bias, const float* Dadd,
        float* C, bf16* Chi, bf16* Clo, int K, int ldc, int ldd)
{
    tc_gemm<128, EPI, OF32, OBF16>(Ah, Al, Bh, Bl, bias, Dadd, C, Chi, Clo,
                                   K, K, K, ldc, ldd, 1.0f);
}

__global__ void __launch_bounds__(256, 1)
k_scores(const bf16* qh, const bf16* ql, const bf16* kh, const bf16* kl, float* attn)
{
    const int z = blockIdx.z;              // h*BATCH + b
    const int h = z / BATCH, b = z % BATCH;
    const long long qa = (long long)b * MQ  * DMODEL + h * HDIM;
    const long long ka = (long long)b * NKV * DMODEL + h * HDIM;
    tc_gemm<128, 0, true, false>(qh + qa, ql + qa, kh + ka, kl + ka, nullptr, nullptr,
                                 attn + (long long)z * MQ * NKV, nullptr, nullptr,
                                 HDIM, DMODEL, DMODEL, NKV, 0, 0.125f);
}

__global__ void __launch_bounds__(256, 1)
k_ctx(const bf16* ah, const bf16* al, const bf16* vth, const bf16* vtl,
      bf16* ctxh, bf16* ctxl)
{
    const int z = blockIdx.z;              // h*BATCH + b
    const int h = z / BATCH, b = z % BATCH;
    const long long aa = (long long)z * MQ * NKV;
    const long long va = (long long)z * HDIM * NKV;
    const long long co = (long long)b * MQ * DMODEL + h * HDIM;
    tc_gemm<64, 0, false, true>(ah + aa, al + aa, vth + va, vtl + va, nullptr, nullptr,
                                nullptr, ctxh + co, ctxl + co,
                                NKV, NKV, NKV, DMODEL, 0, 1.0f);
}

// ---------------- fp32 -> bf16 hi/lo ----------------
__global__ void __launch_bounds__(256)
k_cvt(const float* __restrict__ x, bf16* __restrict__ hi, bf16* __restrict__ lo)
{
    const long long i = ((long long)blockIdx.x * 256 + threadIdx.x) * 4;
    const float4 v = *(const float4*)(x + i);
    bf16 h0 = __float2bfloat16(v.x), h1 = __float2bfloat16(v.y);
    bf16 h2 = __float2bfloat16(v.z), h3 = __float2bfloat16(v.w);
    hi[i+0] = h0; hi[i+1] = h1; hi[i+2] = h2; hi[i+3] = h3;
    lo[i+0] = __float2bfloat16(v.x - __bfloat162float(h0));
    lo[i+1] = __float2bfloat16(v.y - __bfloat162float(h1));
    lo[i+2] = __float2bfloat16(v.z - __bfloat162float(h2));
    lo[i+3] = __float2bfloat16(v.w - __bfloat162float(h3));
}

// vp[b][n][h*64+d] -> vT[(h*B+b)][d][n]  bf16 hi/lo
__global__ void __launch_bounds__(256)
k_cvt_vT(const float* __restrict__ vp, bf16* __restrict__ th, bf16* __restrict__ tl)
{
    const int n = blockIdx.x * 256 + threadIdx.x;
    const int d = blockIdx.y;
    const int z = blockIdx.z;
    const int h = z / BATCH, b = z % BATCH;
    const float v = vp[((long long)b * NKV + n) * DMODEL + h * HDIM + d];
    const bf16 hi = __float2bfloat16(v);
    const long long o = ((long long)z * HDIM + d) * NKV + n;
    th[o] = hi;
    tl[o] = __float2bfloat16(v - __bfloat162float(hi));
}

// ---------------- softmax (fp32 in place) + fused bf16 hi/lo emit ----------------
__global__ void __launch_bounds__(256)
k_softmax(float* __restrict__ attn, bf16* __restrict__ ath, bf16* __restrict__ atl)
{
    __shared__ float red[256];
    const long long row = blockIdx.x;
    float* p = attn + row * (long long)NKV;
    bf16* ph = ath + row * (long long)NKV;
    bf16* pl = atl + row * (long long)NKV;
    const int t = threadIdx.x;

    float v[8];
    float mx = -1e30f;
    #pragma unroll
    for (int i = 0; i < 8; i++) { v[i] = p[t + i * 256]; mx = fmaxf(mx, v[i]); }
    red[t] = mx; __syncthreads();
    for (int s = 128; s > 0; s >>= 1) { if (t < s) red[t] = fmaxf(red[t], red[t + s]); __syncthreads(); }
    mx = red[0]; __syncthreads();

    float sum = 0.0f;
    #pragma unroll
    for (int i = 0; i < 8; i++) { v[i] = expf(v[i] - mx); sum += v[i]; }
    red[t] = sum; __syncthreads();
    for (int s = 128; s > 0; s >>= 1) { if (t < s) red[t] += red[t + s]; __syncthreads(); }
    const float inv = 1.0f / red[0];

    #pragma unroll
    for (int i = 0; i < 8; i++) {
        const int c = t + i * 256;
        const float y = v[i] * inv;
        p[c] = y;
        bf16 hi = __float2bfloat16(y);
        ph[c] = hi;
        pl[c] = __float2bfloat16(y - __bfloat162float(hi));
    }
}

// ---------------- layernorm -> bf16 hi/lo ----------------
__global__ void __launch_bounds__(256)
k_ln(const float* __restrict__ x, const float* __restrict__ g,
     const float* __restrict__ b, bf16* __restrict__ oh, bf16* __restrict__ ol)
{
    __shared__ float r1[256], r2[256];
    const long long row = blockIdx.x;
    const float* p = x + row * (long long)DMODEL;
    const int t = threadIdx.x;

    float v[4]; float s = 0.0f, s2 = 0.0f;
    #pragma unroll
    for (int i = 0; i < 4; i++) {
        v[i] = p[t + i * 256];
        s += v[i]; s2 += v[i] * v[i];
    }
    r1[t] = s; r2[t] = s2; __syncthreads();
    for (int st = 128; st > 0; st >>= 1) {
        if (t < st) { r1[t] += r1[t + st]; r2[t] += r2[t + st]; }
        __syncthreads();
    }
    const float mu  = r1[0] * (1.0f / DMODEL);
    const float var = r2[0] * (1.0f / DMODEL) - mu * mu;
    const float inv = rsqrtf(var + 1e-5f);

    bf16* ph = oh + row * (long long)DMODEL;
    bf16* pl = ol + row * (long long)DMODEL;
    #pragma unroll
    for (int i = 0; i < 4; i++) {
        const int c = t + i * 256;
        const float y = (v[i] - mu) * inv * g[c] + b[c];
        bf16 hi = __float2bfloat16(y);
        ph[c] = hi;
        pl[c] = __float2bfloat16(y - __bfloat162float(hi));
    }
}

// ---------------- host launch ----------------
static void* sym(const void* s) { void* p; cudaGetSymbolAddress(&p, s); return p; }

extern "C" void kernel_launch(void* const* d_in, const int* in_sizes, int n_in,
                              void* d_out, int out_size)
{
    const float* x    = (const float*)d_in[0];
    const float* q    = (const float*)d_in[1];
    const float* w_q  = (const float*)d_in[2];
    const float* b_q  = (const float*)d_in[3];
    const float* w_k  = (const float*)d_in[4];
    const float* b_k  = (const float*)d_in[5];
    const float* w_v  = (const float*)d_in[6];
    const float* b_v  = (const float*)d_in[7];
    const float* w_o  = (const float*)d_in[8];
    const float* b_o  = (const float*)d_in[9];
    const float* ln2g = (const float*)d_in[10];
    const float* ln2b = (const float*)d_in[11];
    const float* w1   = (const float*)d_in[12];
    const float* b1   = (const float*)d_in[13];
    const float* w2   = (const float*)d_in[14];
    const float* b2   = (const float*)d_in[15];

    float* out  = (float*)d_out;
    float* attn = out + (long long)BATCH * MQ * DMODEL;

    float* vp    = (float*)sym(g_vp);
    float* resid = (float*)sym(g_resid);
    bf16 *qh=(bf16*)sym(g_qh), *ql=(bf16*)sym(g_ql);
    bf16 *xh=(bf16*)sym(g_xh), *xl=(bf16*)sym(g_xl);
    bf16 *wqh=(bf16*)sym(g_wqh), *wql=(bf16*)sym(g_wql);
    bf16 *wkh=(bf16*)sym(g_wkh), *wkl=(bf16*)sym(g_wkl);
    bf16 *wvh=(bf16*)sym(g_wvh), *wvl=(bf16*)sym(g_wvl);
    bf16 *woh=(bf16*)sym(g_woh), *wol=(bf16*)sym(g_wol);
    bf16 *w1h=(bf16*)sym(g_w1h), *w1l=(bf16*)sym(g_w1l);
    bf16 *w2h=(bf16*)sym(g_w2h), *w2l=(bf16*)sym(g_w2l);
    bf16 *qph=(bf16*)sym(g_qph), *qpl=(bf16*)sym(g_qpl);
    bf16 *kph=(bf16*)sym(g_kph), *kpl=(bf16*)sym(g_kpl);
    bf16 *vth=(bf16*)sym(g_vth), *vtl=(bf16*)sym(g_vtl);
    bf16 *ath=(bf16*)sym(g_ath), *atl=(bf16*)sym(g_atl);
    bf16 *ctxh=(bf16*)sym(g_ctxh), *ctxl=(bf16*)sym(g_ctxl);
    bf16 *hh=(bf16*)sym(g_hh), *hl=(bf16*)sym(g_hl);
    bf16 *h1h=(bf16*)sym(g_h1h), *h1l=(bf16*)sym(g_h1l);

    const int SMEM128 = 2 * (2 * 16384 + 2 * 16384);  // 131072
    const int SMEM64  = 2 * (2 * 16384 + 2 *  8192);  //  98304
    cudaFuncSetAttribute((const void*)k_dense<0,false,true>, cudaFuncAttributeMaxDynamicSharedMemorySize, SMEM128);
    cudaFuncSetAttribute((const void*)k_dense<0,true,false>, cudaFuncAttributeMaxDynamicSharedMemorySize, SMEM128);
    cudaFuncSetAttribute((const void*)k_dense<1,true,false>, cudaFuncAttributeMaxDynamicSharedMemorySize, SMEM128);
    cudaFuncSetAttribute((const void*)k_dense<2,false,true>, cudaFuncAttributeMaxDynamicSharedMemorySize, SMEM128);
    cudaFuncSetAttribute((const void*)k_scores,               cudaFuncAttributeMaxDynamicSharedMemorySize, SMEM128);
    cudaFuncSetAttribute((const void*)k_ctx,                  cudaFuncAttributeMaxDynamicSharedMemorySize, SMEM64);

    const dim3 blk(256);
    #define CVT(src, hi, lo, nelem) k_cvt<<<(int)((nelem) / 1024), blk>>>(src, hi, lo)

    CVT(q,   qh,  ql,  (size_t)BATCH*MQ*DMODEL);
    CVT(x,   xh,  xl,  (size_t)BATCH*NKV*DMODEL);
    CVT(w_q, wqh, wql, (size_t)DMODEL*DMODEL);
    CVT(w_k, wkh, wkl, (size_t)DMODEL*DMODEL);
    CVT(w_v, wvh, wvl, (size_t)DMODEL*DMODEL);
    CVT(w_o, woh, wol, (size_t)DMODEL*DMODEL);
    CVT(w1,  w1h, w1l, (size_t)DMLP*DMODEL);
    CVT(w2,  w2h, w2l, (size_t)DMODEL*DMLP);

    // Q/K/V projections (qp/kp straight to bf16 hi/lo; vp fp32 for transpose)
    k_dense<0,false,true><<<dim3(8, 32),  blk, SMEM128>>>(qh, ql, wqh, wql, b_q, nullptr,
        nullptr, qph, qpl, DMODEL, DMODEL, 0);
    k_dense<0,false,true><<<dim3(8, 64),  blk, SMEM128>>>(xh, xl, wkh, wkl, b_k, nullptr,
        nullptr, kph, kpl, DMODEL, DMODEL, 0);
    k_dense<0,true,false><<<dim3(8, 64),  blk, SMEM128>>>(xh, xl, wvh, wvl, b_v, nullptr,
        vp, nullptr, nullptr, DMODEL, DMODEL, 0);

    k_cvt_vT<<<dim3(NKV/256, HDIM, ZHB), blk>>>(vp, vth, vtl);

    // scores -> attn [H,B,M,N] (fp32; part of the output)
    k_scores<<<dim3(NKV/128, MQ/128, ZHB), blk, SMEM128>>>(qph, qpl, kph, kpl, attn);

    // softmax in place + bf16 hi/lo emit
    k_softmax<<<ZHB*MQ, blk>>>(attn, ath, atl);

    // ctx = attn @ V  (bf16 hi/lo out)
    k_ctx<<<dim3(1, MQ/128, ZHB), blk, SMEM64>>>(ath, atl, vth, vtl, ctxh, ctxl);

    // resid = ctx @ w_o^T + b_o + q  (fp32)
    k_dense<1,true,false><<<dim3(8, 32), blk, SMEM128>>>(ctxh, ctxl, woh, wol, b_o, q,
        resid, nullptr, nullptr, DMODEL, DMODEL, DMODEL);

    // h = LN(resid) -> bf16 hi/lo
    k_ln<<<BATCH*MQ, blk>>>(resid, ln2g, ln2b, hh, hl);

    // h1 = gelu(h @ w1^T + b1) -> bf16 hi/lo
    k_dense<2,false,true><<<dim3(32, 32), blk, SMEM128>>>(hh, hl, w1h, w1l, b1, nullptr,
        nullptr, h1h, h1l, DMODEL, DMLP, 0);

    // out = h1 @ w2^T + b2 + resid  (fp32)
    k_dense<1,true,false><<<dim3(8, 32), blk, SMEM128>>>(h1h, h1l, w2h, w2l, b2, resid,
        out, nullptr, nullptr, DMLP, DMODEL, DMODEL);

    #undef CVT
}

// round 4
// speedup vs baseline: 5.0925x; 1.1066x over previous
#include <cuda_runtime.h>
#include <cuda_bf16.h>
#include <math.h>
#include <stdint.h>

// ---------------- problem constants ----------------
#define BATCH  4
#define MQ     1024
#define NKV    2048
#define DMODEL 1024
#define NHEAD  16
#define HDIM   64
#define DMLP   4096
#define ZHB    (NHEAD*BATCH)

typedef __nv_bfloat16 bf16;

// ---------------- scratch (device globals; no allocs allowed) ----------------
__device__ __align__(1024) float g_vp   [(size_t)BATCH*NKV*DMODEL];
__device__ __align__(1024) float g_resid[(size_t)BATCH*MQ*DMODEL];
__device__ __align__(1024) float g_linv [(size_t)ZHB*MQ];

__device__ __align__(1024) bf16 g_qh [(size_t)BATCH*MQ*DMODEL];
__device__ __align__(1024) bf16 g_ql [(size_t)BATCH*MQ*DMODEL];
__device__ __align__(1024) bf16 g_xh [(size_t)BATCH*NKV*DMODEL];
__device__ __align__(1024) bf16 g_xl [(size_t)BATCH*NKV*DMODEL];
__device__ __align__(1024) bf16 g_wqh[(size_t)DMODEL*DMODEL];
__device__ __align__(1024) bf16 g_wql[(size_t)DMODEL*DMODEL];
__device__ __align__(1024) bf16 g_wkh[(size_t)DMODEL*DMODEL];
__device__ __align__(1024) bf16 g_wkl[(size_t)DMODEL*DMODEL];
__device__ __align__(1024) bf16 g_wvh[(size_t)DMODEL*DMODEL];
__device__ __align__(1024) bf16 g_wvl[(size_t)DMODEL*DMODEL];
__device__ __align__(1024) bf16 g_woh[(size_t)DMODEL*DMODEL];
__device__ __align__(1024) bf16 g_wol[(size_t)DMODEL*DMODEL];
__device__ __align__(1024) bf16 g_w1h[(size_t)DMLP*DMODEL];
__device__ __align__(1024) bf16 g_w1l[(size_t)DMLP*DMODEL];
__device__ __align__(1024) bf16 g_w2h[(size_t)DMODEL*DMLP];
__device__ __align__(1024) bf16 g_w2l[(size_t)DMODEL*DMLP];
__device__ __align__(1024) bf16 g_qph[(size_t)BATCH*MQ*DMODEL];
__device__ __align__(1024) bf16 g_qpl[(size_t)BATCH*MQ*DMODEL];
__device__ __align__(1024) bf16 g_kph[(size_t)BATCH*NKV*DMODEL];
__device__ __align__(1024) bf16 g_kpl[(size_t)BATCH*NKV*DMODEL];
__device__ __align__(1024) bf16 g_vth[(size_t)ZHB*HDIM*NKV];
__device__ __align__(1024) bf16 g_vtl[(size_t)ZHB*HDIM*NKV];
__device__ __align__(1024) bf16 g_ctxh[(size_t)BATCH*MQ*DMODEL];
__device__ __align__(1024) bf16 g_ctxl[(size_t)BATCH*MQ*DMODEL];
__device__ __align__(1024) bf16 g_hh [(size_t)BATCH*MQ*DMODEL];
__device__ __align__(1024) bf16 g_hl [(size_t)BATCH*MQ*DMODEL];
__device__ __align__(1024) bf16 g_h1h[(size_t)BATCH*MQ*DMLP];
__device__ __align__(1024) bf16 g_h1l[(size_t)BATCH*MQ*DMLP];

// ---------------- helpers ----------------
#define SW128(o) ((uint32_t)(o) ^ ((((uint32_t)(o)) >> 3) & 0x70u))

__device__ __forceinline__ uint32_t smem_u32(const void* p) {
    return (uint32_t)__cvta_generic_to_shared(p);
}

__device__ __forceinline__ void cp16(uint32_t dst, const void* src) {
    asm volatile("cp.async.cg.shared.global [%0], [%1], 16;" :: "r"(dst), "l"(src));
}
#define CP_COMMIT() asm volatile("cp.async.commit_group;" ::: "memory")
#define CP_WAIT0()  asm volatile("cp.async.wait_group 0;" ::: "memory")
#define CP_WAIT1()  asm volatile("cp.async.wait_group 1;" ::: "memory")
#define CP_WAIT2()  asm volatile("cp.async.wait_group 2;" ::: "memory")

#define LDSM4(r0, r1, r2, r3, addr) \
    asm volatile("ldmatrix.sync.aligned.m8n8.x4.shared.b16 {%0,%1,%2,%3}, [%4];" \
        : "=r"(r0), "=r"(r1), "=r"(r2), "=r"(r3) : "r"(addr))

__device__ __forceinline__ void mma_bf16(float* c, const uint32_t* a, const uint32_t* b) {
    asm volatile(
        "mma.sync.aligned.m16n8k16.row.col.f32.bf16.bf16.f32 "
        "{%0,%1,%2,%3}, {%4,%5,%6,%7}, {%8,%9}, {%0,%1,%2,%3};"
        : "+f"(c[0]), "+f"(c[1]), "+f"(c[2]), "+f"(c[3])
        : "r"(a[0]), "r"(a[1]), "r"(a[2]), "r"(a[3]), "r"(b[0]), "r"(b[1]));
}

__device__ __forceinline__ float ex2(float x) {
    float r;
    asm("ex2.approx.f32 %0, %1;" : "=f"(r) : "f"(x));
    return r;
}

__device__ __forceinline__ float gelu_exact(float v) {
    return 0.5f * v * (1.0f + erff(v * 0.70710678118654752440f));
}

// split two fp32 into packed bf16x2 hi and residual-lo words
__device__ __forceinline__ void split2(float e0, float e1, uint32_t& hi, uint32_t& lo) {
    bf16 h0 = __float2bfloat16(e0), h1 = __float2bfloat16(e1);
    __nv_bfloat162 hp; hp.x = h0; hp.y = h1;
    hi = *reinterpret_cast<uint32_t*>(&hp);
    float f0 = __bfloat162float(h0), f1 = __bfloat162float(h1);
    __nv_bfloat162 lp = __floats2bfloat162_rn(e0 - f0, e1 - f1);
    lo = *reinterpret_cast<uint32_t*>(&lp);
}

// ============================================================================
//                       dense split-bf16 GEMM (unchanged)
// ============================================================================
template<int TN>
__device__ __forceinline__ void load_chunk(
    uint32_t st, const bf16* __restrict__ Ah, const bf16* __restrict__ Al,
    const bf16* __restrict__ Bh, const bf16* __restrict__ Bl,
    int m0, int n0, long long kc, int lda, int ldb, int tid)
{
    constexpr int A_BYTES = 128 * 128;
    constexpr int B_BYTES = TN * 128;
    #pragma unroll
    for (int it = 0; it < 4; it++) {
        int idx = tid + it * 256;
        int r = idx >> 3, c = idx & 7;
        uint32_t so = SW128(r * 128 + c * 16);
        long long go = (long long)(m0 + r) * lda + kc + c * 8;
        cp16(st + so,           Ah + go);
        cp16(st + A_BYTES + so, Al + go);
    }
    #pragma unroll
    for (int it = 0; it < TN / 32; it++) {
        int idx = tid + it * 256;
        int r = idx >> 3, c = idx & 7;
        uint32_t so = SW128(r * 128 + c * 16);
        long long go = (long long)(n0 + r) * ldb + kc + c * 8;
        cp16(st + 2 * A_BYTES + so,           Bh + go);
        cp16(st + 2 * A_BYTES + B_BYTES + so, Bl + go);
    }
    CP_COMMIT();
}

template<int TN, int EPI, bool OF32, bool OBF16>
__device__ void tc_gemm(
    const bf16* __restrict__ Ah, const bf16* __restrict__ Al,
    const bf16* __restrict__ Bh, const bf16* __restrict__ Bl,
    const float* __restrict__ bias, const float* __restrict__ Dadd,
    float* __restrict__ C, bf16* __restrict__ Chi, bf16* __restrict__ Clo,
    int K, int lda, int ldb, int ldc, int ldd, float alpha)
{
    extern __shared__ char smem[];
    constexpr int A_BYTES = 128 * 128;
    constexpr int B_BYTES = TN * 128;
    constexpr int STAGE   = 2 * A_BYTES + 2 * B_BYTES;
    constexpr int WC = TN / 32;
    constexpr int WR = 8 / WC;
    constexpr int WM = 128 / WR;
    constexpr int MI = WM / 16;

    const uint32_t sb = smem_u32(smem);
    const int tid  = threadIdx.x;
    const int wid  = tid >> 5;
    const int lane = tid & 31;
    const int m0 = blockIdx.y * 128;
    const int n0 = blockIdx.x * TN;
    const int wm0 = (wid / WC) * WM;
    const int wn0 = (wid % WC) * 32;

    float acc[MI][4][4];
    #pragma unroll
    for (int mi = 0; mi < MI; mi++)
        #pragma unroll
        for (int ni = 0; ni < 4; ni++)
            #pragma unroll
            for (int e = 0; e < 4; e++) acc[mi][ni][e] = 0.0f;

    const int NC = K >> 6;
    load_chunk<TN>(sb, Ah, Al, Bh, Bl, m0, n0, 0, lda, ldb, tid);
    if (NC > 1)
        load_chunk<TN>(sb + STAGE, Ah, Al, Bh, Bl, m0, n0, 64, lda, ldb, tid);

    for (int i = 0; i < NC; i++) {
        if (i + 1 < NC) { CP_WAIT1(); } else { CP_WAIT0(); }
        __syncthreads();

        const uint32_t st = sb + (i & 1) * STAGE;
        #pragma unroll
        for (int kk = 0; kk < 4; kk++) {
            uint32_t ah[MI][4], al[MI][4], bh[4][2], bl[4][2];
            const int colA = kk * 32 + ((lane & 16) ? 16 : 0);
            const int rA   = lane & 15;
            #pragma unroll
            for (int mi = 0; mi < MI; mi++) {
                uint32_t off = SW128((uint32_t)(wm0 + mi * 16 + rA) * 128 + colA);
                LDSM4(ah[mi][0], ah[mi][1], ah[mi][2], ah[mi][3], st + off);
                LDSM4(al[mi][0], al[mi][1], al[mi][2], al[mi][3], st + A_BYTES + off);
            }
            const int colB = kk * 32 + ((lane & 8) ? 16 : 0);
            const int rB   = (lane & 7) + ((lane & 16) ? 8 : 0);
            #pragma unroll
            for (int nj = 0; nj < 2; nj++) {
                uint32_t off = SW128((uint32_t)(wn0 + nj * 16 + rB) * 128 + colB);
                LDSM4(bh[nj*2][0], bh[nj*2][1], bh[nj*2+1][0], bh[nj*2+1][1],
                      st + 2 * A_BYTES + off);
                LDSM4(bl[nj*2][0], bl[nj*2][1], bl[nj*2+1][0], bl[nj*2+1][1],
                      st + 2 * A_BYTES + B_BYTES + off);
            }
            #pragma unroll
            for (int mi = 0; mi < MI; mi++)
                #pragma unroll
                for (int ni = 0; ni < 4; ni++) {
                    mma_bf16(acc[mi][ni], ah[mi], bh[ni]);
                    mma_bf16(acc[mi][ni], ah[mi], bl[ni]);
                    mma_bf16(acc[mi][ni], al[mi], bh[ni]);
                }
        }
        __syncthreads();
        if (i + 2 < NC)
            load_chunk<TN>(sb + (i & 1) * STAGE, Ah, Al, Bh, Bl, m0, n0,
                           (long long)(i + 2) * 64, lda, ldb, tid);
    }

    constexpr int LDS = TN + 8;
    float* sOut = (float*)smem;
    __syncthreads();

    #pragma unroll
    for (int mi = 0; mi < MI; mi++) {
        const int r0 = wm0 + mi * 16 + (lane >> 2);
        #pragma unroll
        for (int ni = 0; ni < 4; ni++) {
            const int c0 = wn0 + ni * 8 + (lane & 3) * 2;
            sOut[r0 * LDS + c0]           = acc[mi][ni][0];
            sOut[r0 * LDS + c0 + 1]       = acc[mi][ni][1];
            sOut[(r0 + 8) * LDS + c0]     = acc[mi][ni][2];
            sOut[(r0 + 8) * LDS + c0 + 1] = acc[mi][ni][3];
        }
    }
    __syncthreads();

    constexpr int RPI = 256 / TN;
    const int c = tid & (TN - 1);
    const int rs = tid / TN;
    const int n = n0 + c;
    #pragma unroll 4
    for (int rr = 0; rr < 128; rr += RPI) {
        const int r = rr + rs;
        float v = sOut[r * LDS + c] * alpha;
        if (bias) v += bias[n];
        if (EPI == 2) v = gelu_exact(v);
        if (EPI == 1) v += Dadd[(long long)(m0 + r) * ldd + n];
        const long long o = (long long)(m0 + r) * ldc + n;
        if (OF32) C[o] = v;
        if (OBF16) {
            bf16 hi = __float2bfloat16(v);
            Chi[o] = hi;
            Clo[o] = __float2bfloat16(v - __bfloat162float(hi));
        }
    }
}

template<int EPI, bool OF32, bool OBF16>
__global__ void __launch_bounds__(256, 1)
k_dense(const bf16* Ah, const bf16* Al, const bf16* Bh, const bf16* Bl,
        const float* bias, const float* Dadd,
        float* C, bf16* Chi, bf16* Clo, int K, int ldc, int ldd)
{
    tc_gemm<128, EPI, OF32, OBF16>(Ah, Al, Bh, Bl, bias, Dadd, C, Chi, Clo,
                                   K, K, K, ldc, ldd, 1.0f);
}

// ============================================================================
//      fused attention: S = QK^T/8 -> p = exp(S) -> attn (unnormalized),
//      ctx = (p/l) @ V  all in one kernel.  Fixup kernel normalizes attn.
// ============================================================================
// smem: [Q hi 16K][Q lo 16K] + 2 stages x ([K hi 16K][K lo 16K][V hi 16K][V lo 16K])
#define ATTN_SMEM (32768 + 2*65536)
#define NCH (NKV/128)

__device__ __forceinline__ void load_kv(
    uint32_t st, const bf16* __restrict__ kh, const bf16* __restrict__ kl,
    const bf16* __restrict__ vh, const bf16* __restrict__ vl, int ci, int tid)
{
    #pragma unroll
    for (int it = 0; it < 4; it++) {
        int idx = tid + it * 256;
        int r = idx >> 3, c = idx & 7;
        uint32_t so = SW128((uint32_t)r * 128 + c * 16);
        long long go = (long long)(ci * 128 + r) * DMODEL + c * 8;
        cp16(st + so,         kh + go);
        cp16(st + 16384 + so, kl + go);
    }
    #pragma unroll
    for (int it = 0; it < 4; it++) {
        int idx = tid + it * 256;
        int hf = idx >> 9, d = (idx >> 3) & 63, c = idx & 7;
        uint32_t so = (uint32_t)hf * 8192 + SW128((uint32_t)d * 128 + c * 16);
        long long go = (long long)d * NKV + ci * 128 + hf * 64 + c * 8;
        cp16(st + 32768 + so, vh + go);
        cp16(st + 49152 + so, vl + go);
    }
    CP_COMMIT();
}

__global__ void __launch_bounds__(256, 1)
k_attn(const bf16* __restrict__ qph, const bf16* __restrict__ qpl,
       const bf16* __restrict__ kph, const bf16* __restrict__ kpl,
       const bf16* __restrict__ vth, const bf16* __restrict__ vtl,
       float* __restrict__ attn, float* __restrict__ linv,
       bf16* __restrict__ ctxh, bf16* __restrict__ ctxl)
{
    extern __shared__ char smem[];
    const uint32_t sb = smem_u32(smem);
    const int tid = threadIdx.x, wid = tid >> 5, lane = tid & 31;
    const int z  = blockIdx.x;            // h*BATCH + b
    const int h  = z / BATCH, b = z % BATCH;
    const int m0 = blockIdx.y * 128;
    const int wm0 = wid * 16;

    const bf16* qhb = qph + ((long long)(b * MQ + m0 + wm0)) * DMODEL + h * HDIM;
    const bf16* qlb = qpl + ((long long)(b * MQ + m0 + wm0)) * DMODEL + h * HDIM;
    const bf16* khb = kph + (long long)b * NKV * DMODEL + h * HDIM;
    const bf16* klb = kpl + (long long)b * NKV * DMODEL + h * HDIM;
    const bf16* vhb = vth + (long long)z * HDIM * NKV;
    const bf16* vlb = vtl + (long long)z * HDIM * NKV;
    float* attn_w = attn + ((long long)z * MQ + m0 + wm0) * NKV;

    const uint32_t sQ = sb;                 // hi; +16384 lo
    const uint32_t sS = sb + 32768;         // stage base

    // load Q tile (note: per-warp rows loaded by all threads cooperatively,
    // so use CTA-tile addressing instead)
    {
        const bf16* qh0 = qph + ((long long)(b * MQ + m0)) * DMODEL + h * HDIM;
        const bf16* ql0 = qpl + ((long long)(b * MQ + m0)) * DMODEL + h * HDIM;
        #pragma unroll
        for (int it = 0; it < 4; it++) {
            int idx = tid + it * 256;
            int r = idx >> 3, c = idx & 7;
            uint32_t so = SW128((uint32_t)r * 128 + c * 16);
            long long go = (long long)r * DMODEL + c * 8;
            cp16(sQ + so,         qh0 + go);
            cp16(sQ + 16384 + so, ql0 + go);
        }
        CP_COMMIT();
    }
    load_kv(sS,         khb, klb, vhb, vlb, 0, tid);
    load_kv(sS + 65536, khb, klb, vhb, vlb, 1, tid);

    CP_WAIT2();                 // Q tile ready
    __syncthreads();

    // preload Q fragments (persistent)
    uint32_t qfh[4][4], qfl[4][4];
    {
        const int rA = lane & 15;
        #pragma unroll
        for (int kk = 0; kk < 4; kk++) {
            const int colA = kk * 32 + ((lane & 16) ? 16 : 0);
            uint32_t off = SW128((uint32_t)(wm0 + rA) * 128 + colA);
            LDSM4(qfh[kk][0], qfh[kk][1], qfh[kk][2], qfh[kk][3], sQ + off);
            LDSM4(qfl[kk][0], qfl[kk][1], qfl[kk][2], qfl[kk][3], sQ + 16384 + off);
        }
    }

    float cacc[8][4];
    #pragma unroll
    for (int i = 0; i < 8; i++)
        #pragma unroll
        for (int e = 0; e < 4; e++) cacc[i][e] = 0.0f;
    float lp0 = 0.0f, lp1 = 0.0f;

    const int rB   = (lane & 7) + ((lane & 16) ? 8 : 0);
    const int r    = lane >> 2;
    const int c2   = (lane & 3) * 2;
    const float CE = 0.125f * 1.4426950408889634f;   // 1/8 * log2(e)

    for (int ci = 0; ci < NCH; ci++) {
        if (ci + 1 < NCH) { CP_WAIT1(); } else { CP_WAIT0(); }
        __syncthreads();
        const uint32_t st = sS + (ci & 1) * 65536;

        // ---- S = Q K^T (3-term split bf16) ----
        float sacc[16][4];
        #pragma unroll
        for (int t = 0; t < 16; t++)
            #pragma unroll
            for (int e = 0; e < 4; e++) sacc[t][e] = 0.0f;

        #pragma unroll
        for (int kk = 0; kk < 4; kk++) {
            const int colB = kk * 32 + ((lane & 8) ? 16 : 0);
            #pragma unroll
            for (int nt = 0; nt < 8; nt++) {
                uint32_t off = SW128((uint32_t)(nt * 16 + rB) * 128 + colB);
                uint32_t bh[4], bl[4];
                LDSM4(bh[0], bh[1], bh[2], bh[3], st + off);
                LDSM4(bl[0], bl[1], bl[2], bl[3], st + 16384 + off);
                mma_bf16(sacc[2*nt],   qfh[kk], bh);
                mma_bf16(sacc[2*nt],   qfh[kk], bl);
                mma_bf16(sacc[2*nt],   qfl[kk], bh);
                mma_bf16(sacc[2*nt+1], qfh[kk], bh + 2);
                mma_bf16(sacc[2*nt+1], qfh[kk], bl + 2);
                mma_bf16(sacc[2*nt+1], qfl[kk], bh + 2);
            }
        }

        // ---- p = exp(S/8); write unnormalized attn; accumulate row sums ----
        float* a0 = attn_w + (long long)r * NKV + ci * 128;
        float* a1 = a0 + 8 * NKV;
        #pragma unroll
        for (int t = 0; t < 16; t++) {
            float p0 = ex2(sacc[t][0] * CE);
            float p1 = ex2(sacc[t][1] * CE);
            float p2 = ex2(sacc[t][2] * CE);
            float p3 = ex2(sacc[t][3] * CE);
            sacc[t][0] = p0; sacc[t][1] = p1; sacc[t][2] = p2; sacc[t][3] = p3;
            lp0 += p0 + p1;  lp1 += p2 + p3;
            float2 w0 = make_float2(p0, p1);
            float2 w1 = make_float2(p2, p3);
            *(float2*)(a0 + t * 8 + c2) = w0;
            *(float2*)(a1 + t * 8 + c2) = w1;
        }

        // ---- ctx += P V (P repacked in-register to bf16 hi/lo A-frags) ----
        #pragma unroll
        for (int ks = 0; ks < 8; ks++) {
            uint32_t ah[4], al[4];
            split2(sacc[2*ks][0],   sacc[2*ks][1],   ah[0], al[0]);
            split2(sacc[2*ks][2],   sacc[2*ks][3],   ah[1], al[1]);
            split2(sacc[2*ks+1][0], sacc[2*ks+1][1], ah[2], al[2]);
            split2(sacc[2*ks+1][2], sacc[2*ks+1][3], ah[3], al[3]);

            const int hf = ks >> 2;
            const int colB = (ks & 3) * 32 + ((lane & 8) ? 16 : 0);
            const uint32_t vh_base = st + 32768 + hf * 8192;
            const uint32_t vl_base = st + 49152 + hf * 8192;
            #pragma unroll
            for (int dt = 0; dt < 4; dt++) {
                uint32_t off = SW128((uint32_t)(dt * 16 + rB) * 128 + colB);
                uint32_t bh[4], bl[4];
                LDSM4(bh[0], bh[1], bh[2], bh[3], vh_base + off);
                LDSM4(bl[0], bl[1], bl[2], bl[3], vl_base + off);
                mma_bf16(cacc[2*dt],   ah, bh);
                mma_bf16(cacc[2*dt],   ah, bl);
                mma_bf16(cacc[2*dt],   al, bh);
                mma_bf16(cacc[2*dt+1], ah, bh + 2);
                mma_bf16(cacc[2*dt+1], ah, bl + 2);
                mma_bf16(cacc[2*dt+1], al, bh + 2);
            }
        }

        __syncthreads();
        if (ci + 2 < NCH)
            load_kv(sS + (ci & 1) * 65536, khb, klb, vhb, vlb, ci + 2, tid);
    }

    // ---- finalize: row sums, write 1/l, normalized ctx as bf16 hi/lo ----
    lp0 += __shfl_xor_sync(0xFFFFFFFFu, lp0, 1);
    lp0 += __shfl_xor_sync(0xFFFFFFFFu, lp0, 2);
    lp1 += __shfl_xor_sync(0xFFFFFFFFu, lp1, 1);
    lp1 += __shfl_xor_sync(0xFFFFFFFFu, lp1, 2);
    const float il0 = 1.0f / lp0, il1 = 1.0f / lp1;

    if ((lane & 3) == 0) {
        linv[(long long)z * MQ + m0 + wm0 + r]     = il0;
        linv[(long long)z * MQ + m0 + wm0 + r + 8] = il1;
    }

    const long long cb = ((long long)(b * MQ + m0 + wm0)) * DMODEL + h * HDIM;
    #pragma unroll
    for (int dt = 0; dt < 8; dt++) {
        const int d0 = dt * 8 + c2;
        uint32_t hi, lo;
        split2(cacc[dt][0] * il0, cacc[dt][1] * il0, hi, lo);
        *(uint32_t*)(ctxh + cb + (long long)r * DMODEL + d0) = hi;
        *(uint32_t*)(ctxl + cb + (long long)r * DMODEL + d0) = lo;
        split2(cacc[dt][2] * il1, cacc[dt][3] * il1, hi, lo);
        *(uint32_t*)(ctxh + cb + (long long)(r + 8) * DMODEL + d0) = hi;
        *(uint32_t*)(ctxl + cb + (long long)(r + 8) * DMODEL + d0) = lo;
    }
}

// normalize attn rows by 1/l
__global__ void __launch_bounds__(256)
k_norm(float* __restrict__ attn, const float* __restrict__ linv)
{
    const long long row = blockIdx.x;
    const float s = linv[row];
    float4* p = (float4*)(attn + row * (long long)NKV);
    const int t = threadIdx.x;
    #pragma unroll
    for (int i = 0; i < 2; i++) {
        float4 v = p[t + i * 256];
        v.x *= s; v.y *= s; v.z *= s; v.w *= s;
        p[t + i * 256] = v;
    }
}

// ---------------- fp32 -> bf16 hi/lo ----------------
__global__ void __launch_bounds__(256)
k_cvt(const float* __restrict__ x, bf16* __restrict__ hi, bf16* __restrict__ lo)
{
    const long long i = ((long long)blockIdx.x * 256 + threadIdx.x) * 4;
    const float4 v = *(const float4*)(x + i);
    bf16 h0 = __float2bfloat16(v.x), h1 = __float2bfloat16(v.y);
    bf16 h2 = __float2bfloat16(v.z), h3 = __float2bfloat16(v.w);
    hi[i+0] = h0; hi[i+1] = h1; hi[i+2] = h2; hi[i+3] = h3;
    lo[i+0] = __float2bfloat16(v.x - __bfloat162float(h0));
    lo[i+1] = __float2bfloat16(v.y - __bfloat162float(h1));
    lo[i+2] = __float2bfloat16(v.z - __bfloat162float(h2));
    lo[i+3] = __float2bfloat16(v.w - __bfloat162float(h3));
}

// vp[b][n][h*64+d] -> vT[(h*B+b)][d][n]  bf16 hi/lo
__global__ void __launch_bounds__(256)
k_cvt_vT(const float* __restrict__ vp, bf16* __restrict__ th, bf16* __restrict__ tl)
{
    const int n = blockIdx.x * 256 + threadIdx.x;
    const int d = blockIdx.y;
    const int z = blockIdx.z;
    const int h = z / BATCH, b = z % BATCH;
    const float v = vp[((long long)b * NKV + n) * DMODEL + h * HDIM + d];
    const bf16 hi = __float2bfloat16(v);
    const long long o = ((long long)z * HDIM + d) * NKV + n;
    th[o] = hi;
    tl[o] = __float2bfloat16(v - __bfloat162float(hi));
}

// ---------------- layernorm -> bf16 hi/lo ----------------
__global__ void __launch_bounds__(256)
k_ln(const float* __restrict__ x, const float* __restrict__ g,
     const float* __restrict__ b, bf16* __restrict__ oh, bf16* __restrict__ ol)
{
    __shared__ float r1[256], r2[256];
    const long long row = blockIdx.x;
    const float* p = x + row * (long long)DMODEL;
    const int t = threadIdx.x;

    float v[4]; float s = 0.0f, s2 = 0.0f;
    #pragma unroll
    for (int i = 0; i < 4; i++) {
        v[i] = p[t + i * 256];
        s += v[i]; s2 += v[i] * v[i];
    }
    r1[t] = s; r2[t] = s2; __syncthreads();
    for (int st = 128; st > 0; st >>= 1) {
        if (t < st) { r1[t] += r1[t + st]; r2[t] += r2[t + st]; }
        __syncthreads();
    }
    const float mu  = r1[0] * (1.0f / DMODEL);
    const float var = r2[0] * (1.0f / DMODEL) - mu * mu;
    const float inv = rsqrtf(var + 1e-5f);

    bf16* ph = oh + row * (long long)DMODEL;
    bf16* pl = ol + row * (long long)DMODEL;
    #pragma unroll
    for (int i = 0; i < 4; i++) {
        const int c = t + i * 256;
        const float y = (v[i] - mu) * inv * g[c] + b[c];
        bf16 hi = __float2bfloat16(y);
        ph[c] = hi;
        pl[c] = __float2bfloat16(y - __bfloat162float(hi));
    }
}

// ---------------- host launch ----------------
static void* sym(const void* s) { void* p; cudaGetSymbolAddress(&p, s); return p; }

extern "C" void kernel_launch(void* const* d_in, const int* in_sizes, int n_in,
                              void* d_out, int out_size)
{
    const float* x    = (const float*)d_in[0];
    const float* q    = (const float*)d_in[1];
    const float* w_q  = (const float*)d_in[2];
    const float* b_q  = (const float*)d_in[3];
    const float* w_k  = (const float*)d_in[4];
    const float* b_k  = (const float*)d_in[5];
    const float* w_v  = (const float*)d_in[6];
    const float* b_v  = (const float*)d_in[7];
    const float* w_o  = (const float*)d_in[8];
    const float* b_o  = (const float*)d_in[9];
    const float* ln2g = (const float*)d_in[10];
    const float* ln2b = (const float*)d_in[11];
    const float* w1   = (const float*)d_in[12];
    const float* b1   = (const float*)d_in[13];
    const float* w2   = (const float*)d_in[14];
    const float* b2   = (const float*)d_in[15];

    float* out  = (float*)d_out;
    float* attn = out + (long long)BATCH * MQ * DMODEL;

    float* vp    = (float*)sym(g_vp);
    float* resid = (float*)sym(g_resid);
    float* linv  = (float*)sym(g_linv);
    bf16 *qh=(bf16*)sym(g_qh), *ql=(bf16*)sym(g_ql);
    bf16 *xh=(bf16*)sym(g_xh), *xl=(bf16*)sym(g_xl);
    bf16 *wqh=(bf16*)sym(g_wqh), *wql=(bf16*)sym(g_wql);
    bf16 *wkh=(bf16*)sym(g_wkh), *wkl=(bf16*)sym(g_wkl);
    bf16 *wvh=(bf16*)sym(g_wvh), *wvl=(bf16*)sym(g_wvl);
    bf16 *woh=(bf16*)sym(g_woh), *wol=(bf16*)sym(g_wol);
    bf16 *w1h=(bf16*)sym(g_w1h), *w1l=(bf16*)sym(g_w1l);
    bf16 *w2h=(bf16*)sym(g_w2h), *w2l=(bf16*)sym(g_w2l);
    bf16 *qph=(bf16*)sym(g_qph), *qpl=(bf16*)sym(g_qpl);
    bf16 *kph=(bf16*)sym(g_kph), *kpl=(bf16*)sym(g_kpl);
    bf16 *vth=(bf16*)sym(g_vth), *vtl=(bf16*)sym(g_vtl);
    bf16 *ctxh=(bf16*)sym(g_ctxh), *ctxl=(bf16*)sym(g_ctxl);
    bf16 *hh=(bf16*)sym(g_hh), *hl=(bf16*)sym(g_hl);
    bf16 *h1h=(bf16*)sym(g_h1h), *h1l=(bf16*)sym(g_h1l);

    const int SMEM128 = 2 * (2 * 16384 + 2 * 16384);  // 131072
    cudaFuncSetAttribute((const void*)k_dense<0,false,true>, cudaFuncAttributeMaxDynamicSharedMemorySize, SMEM128);
    cudaFuncSetAttribute((const void*)k_dense<0,true,false>, cudaFuncAttributeMaxDynamicSharedMemorySize, SMEM128);
    cudaFuncSetAttribute((const void*)k_dense<1,true,false>, cudaFuncAttributeMaxDynamicSharedMemorySize, SMEM128);
    cudaFuncSetAttribute((const void*)k_dense<2,false,true>, cudaFuncAttributeMaxDynamicSharedMemorySize, SMEM128);
    cudaFuncSetAttribute((const void*)k_attn, cudaFuncAttributeMaxDynamicSharedMemorySize, ATTN_SMEM);

    const dim3 blk(256);
    #define CVT(src, hi, lo, nelem) k_cvt<<<(int)((nelem) / 1024), blk>>>(src, hi, lo)

    CVT(q,   qh,  ql,  (size_t)BATCH*MQ*DMODEL);
    CVT(x,   xh,  xl,  (size_t)BATCH*NKV*DMODEL);
    CVT(w_q, wqh, wql, (size_t)DMODEL*DMODEL);
    CVT(w_k, wkh, wkl, (size_t)DMODEL*DMODEL);
    CVT(w_v, wvh, wvl, (size_t)DMODEL*DMODEL);
    CVT(w_o, woh, wol, (size_t)DMODEL*DMODEL);
    CVT(w1,  w1h, w1l, (size_t)DMLP*DMODEL);
    CVT(w2,  w2h, w2l, (size_t)DMODEL*DMLP);

    // Q/K/V projections
    k_dense<0,false,true><<<dim3(8, 32), blk, SMEM128>>>(qh, ql, wqh, wql, b_q, nullptr,
        nullptr, qph, qpl, DMODEL, DMODEL, 0);
    k_dense<0,false,true><<<dim3(8, 64), blk, SMEM128>>>(xh, xl, wkh, wkl, b_k, nullptr,
        nullptr, kph, kpl, DMODEL, DMODEL, 0);
    k_dense<0,true,false><<<dim3(8, 64), blk, SMEM128>>>(xh, xl, wvh, wvl, b_v, nullptr,
        vp, nullptr, nullptr, DMODEL, DMODEL, 0);

    k_cvt_vT<<<dim3(NKV/256, HDIM, ZHB), blk>>>(vp, vth, vtl);

    // fused attention: writes unnormalized attn, 1/l, and ctx (bf16 hi/lo)
    k_attn<<<dim3(ZHB, MQ/128), blk, ATTN_SMEM>>>(qph, qpl, kph, kpl, vth, vtl,
                                                  attn, linv, ctxh, ctxl);
    // normalize attn rows
    k_norm<<<ZHB*MQ, blk>>>(attn, linv);

    // resid = ctx @ w_o^T + b_o + q  (fp32)
    k_dense<1,true,false><<<dim3(8, 32), blk, SMEM128>>>(ctxh, ctxl, woh, wol, b_o, q,
        resid, nullptr, nullptr, DMODEL, DMODEL, DMODEL);

    // h = LN(resid) -> bf16 hi/lo
    k_ln<<<BATCH*MQ, blk>>>(resid, ln2g, ln2b, hh, hl);

    // h1 = gelu(h @ w1^T + b1) -> bf16 hi/lo
    k_dense<2,false,true><<<dim3(32, 32), blk, SMEM128>>>(hh, hl, w1h, w1l, b1, nullptr,
        nullptr, h1h, h1l, DMODEL, DMLP, 0);

    // out = h1 @ w2^T + b2 + resid  (fp32)
    k_dense<1,true,false><<<dim3(8, 32), blk, SMEM128>>>(h1h, h1l, w2h, w2l, b2, resid,
        out, nullptr, nullptr, DMLP, DMODEL, DMODEL);

    #undef CVT
}

// round 6
// speedup vs baseline: 5.2230x; 1.0256x over previous
#include <cuda_runtime.h>
#include <cuda_bf16.h>
#include <math.h>
#include <stdint.h>

// ---------------- problem constants ----------------
#define BATCH  4
#define MQ     1024
#define NKV    2048
#define DMODEL 1024
#define NHEAD  16
#define HDIM   64
#define DMLP   4096
#define ZHB    (NHEAD*BATCH)

typedef __nv_bfloat16 bf16;

// ---------------- scratch (device globals; no allocs allowed) ----------------
__device__ __align__(1024) float g_resid[(size_t)BATCH*MQ*DMODEL];

__device__ __align__(1024) bf16 g_qh [(size_t)BATCH*MQ*DMODEL];
__device__ __align__(1024) bf16 g_ql [(size_t)BATCH*MQ*DMODEL];
__device__ __align__(1024) bf16 g_xh [(size_t)BATCH*NKV*DMODEL];
__device__ __align__(1024) bf16 g_xl [(size_t)BATCH*NKV*DMODEL];
__device__ __align__(1024) bf16 g_wqh[(size_t)DMODEL*DMODEL];
__device__ __align__(1024) bf16 g_wql[(size_t)DMODEL*DMODEL];
__device__ __align__(1024) bf16 g_wkh[(size_t)DMODEL*DMODEL];
__device__ __align__(1024) bf16 g_wkl[(size_t)DMODEL*DMODEL];
__device__ __align__(1024) bf16 g_wvh[(size_t)DMODEL*DMODEL];
__device__ __align__(1024) bf16 g_wvl[(size_t)DMODEL*DMODEL];
__device__ __align__(1024) bf16 g_woh[(size_t)DMODEL*DMODEL];
__device__ __align__(1024) bf16 g_wol[(size_t)DMODEL*DMODEL];
__device__ __align__(1024) bf16 g_w1h[(size_t)DMLP*DMODEL];
__device__ __align__(1024) bf16 g_w1l[(size_t)DMLP*DMODEL];
__device__ __align__(1024) bf16 g_w2h[(size_t)DMODEL*DMLP];
__device__ __align__(1024) bf16 g_w2l[(size_t)DMODEL*DMLP];
__device__ __align__(1024) bf16 g_qph[(size_t)BATCH*MQ*DMODEL];
__device__ __align__(1024) bf16 g_qpl[(size_t)BATCH*MQ*DMODEL];
__device__ __align__(1024) bf16 g_kph[(size_t)BATCH*NKV*DMODEL];
__device__ __align__(1024) bf16 g_kpl[(size_t)BATCH*NKV*DMODEL];
__device__ __align__(1024) bf16 g_vth[(size_t)ZHB*HDIM*NKV];
__device__ __align__(1024) bf16 g_vtl[(size_t)ZHB*HDIM*NKV];
__device__ __align__(1024) bf16 g_ctxh[(size_t)BATCH*MQ*DMODEL];
__device__ __align__(1024) bf16 g_ctxl[(size_t)BATCH*MQ*DMODEL];
__device__ __align__(1024) bf16 g_hh [(size_t)BATCH*MQ*DMODEL];
__device__ __align__(1024) bf16 g_hl [(size_t)BATCH*MQ*DMODEL];
__device__ __align__(1024) bf16 g_h1h[(size_t)BATCH*MQ*DMLP];
__device__ __align__(1024) bf16 g_h1l[(size_t)BATCH*MQ*DMLP];

// ---------------- helpers ----------------
#define SW128(o) ((uint32_t)(o) ^ ((((uint32_t)(o)) >> 3) & 0x70u))

__device__ __forceinline__ uint32_t smem_u32(const void* p) {
    return (uint32_t)__cvta_generic_to_shared(p);
}

__device__ __forceinline__ void cp16(uint32_t dst, const void* src) {
    asm volatile("cp.async.cg.shared.global [%0], [%1], 16;" :: "r"(dst), "l"(src));
}
#define CP_COMMIT() asm volatile("cp.async.commit_group;" ::: "memory")
#define CP_WAIT0()  asm volatile("cp.async.wait_group 0;" ::: "memory")
#define CP_WAIT1()  asm volatile("cp.async.wait_group 1;" ::: "memory")
#define CP_WAIT2()  asm volatile("cp.async.wait_group 2;" ::: "memory")

#define LDSM4(r0, r1, r2, r3, addr) \
    asm volatile("ldmatrix.sync.aligned.m8n8.x4.shared.b16 {%0,%1,%2,%3}, [%4];" \
        : "=r"(r0), "=r"(r1), "=r"(r2), "=r"(r3) : "r"(addr))

__device__ __forceinline__ void mma_bf16(float* c, const uint32_t* a, const uint32_t* b) {
    asm volatile(
        "mma.sync.aligned.m16n8k16.row.col.f32.bf16.bf16.f32 "
        "{%0,%1,%2,%3}, {%4,%5,%6,%7}, {%8,%9}, {%0,%1,%2,%3};"
        : "+f"(c[0]), "+f"(c[1]), "+f"(c[2]), "+f"(c[3])
        : "r"(a[0]), "r"(a[1]), "r"(a[2]), "r"(a[3]), "r"(b[0]), "r"(b[1]));
}

__device__ __forceinline__ float ex2(float x) {
    float r;
    asm("ex2.approx.f32 %0, %1;" : "=f"(r) : "f"(x));
    return r;
}

__device__ __forceinline__ float gelu_exact(float v) {
    return 0.5f * v * (1.0f + erff(v * 0.70710678118654752440f));
}

// split two fp32 into packed bf16x2 hi and residual-lo words
__device__ __forceinline__ void split2(float e0, float e1, uint32_t& hi, uint32_t& lo) {
    bf16 h0 = __float2bfloat16(e0), h1 = __float2bfloat16(e1);
    __nv_bfloat162 hp; hp.x = h0; hp.y = h1;
    hi = *reinterpret_cast<uint32_t*>(&hp);
    float f0 = __bfloat162float(h0), f1 = __bfloat162float(h1);
    __nv_bfloat162 lp = __floats2bfloat162_rn(e0 - f0, e1 - f1);
    lo = *reinterpret_cast<uint32_t*>(&lp);
}

// ============================================================================
//                       dense split-bf16 GEMM
// ============================================================================
template<int TN>
__device__ __forceinline__ void load_chunk(
    uint32_t st, const bf16* __restrict__ Ah, const bf16* __restrict__ Al,
    const bf16* __restrict__ Bh, const bf16* __restrict__ Bl,
    int m0, int n0, long long kc, int lda, int ldb, int tid)
{
    constexpr int A_BYTES = 128 * 128;
    constexpr int B_BYTES = TN * 128;
    #pragma unroll
    for (int it = 0; it < 4; it++) {
        int idx = tid + it * 256;
        int r = idx >> 3, c = idx & 7;
        uint32_t so = SW128(r * 128 + c * 16);
        long long go = (long long)(m0 + r) * lda + kc + c * 8;
        cp16(st + so,           Ah + go);
        cp16(st + A_BYTES + so, Al + go);
    }
    #pragma unroll
    for (int it = 0; it < TN / 32; it++) {
        int idx = tid + it * 256;
        int r = idx >> 3, c = idx & 7;
        uint32_t so = SW128(r * 128 + c * 16);
        long long go = (long long)(n0 + r) * ldb + kc + c * 8;
        cp16(st + 2 * A_BYTES + so,           Bh + go);
        cp16(st + 2 * A_BYTES + B_BYTES + so, Bl + go);
    }
    CP_COMMIT();
}

// EPI: 0 none, 1 +Dadd, 2 gelu. OF32: fp32 C. OBF16: bf16 hi/lo C.
// OVT: write transposed per-head bf16 hi/lo (V projection)
template<int TN, int EPI, bool OF32, bool OBF16, bool OVT>
__device__ void tc_gemm(
    const bf16* __restrict__ Ah, const bf16* __restrict__ Al,
    const bf16* __restrict__ Bh, const bf16* __restrict__ Bl,
    const float* __restrict__ bias, const float* __restrict__ Dadd,
    float* __restrict__ C, bf16* __restrict__ Chi, bf16* __restrict__ Clo,
    int K, int lda, int ldb, int ldc, int ldd, float alpha)
{
    extern __shared__ char smem[];
    constexpr int A_BYTES = 128 * 128;
    constexpr int B_BYTES = TN * 128;
    constexpr int STAGE   = 2 * A_BYTES + 2 * B_BYTES;
    constexpr int WC = TN / 32;
    constexpr int WR = 8 / WC;
    constexpr int WM = 128 / WR;
    constexpr int MI = WM / 16;

    const uint32_t sb = smem_u32(smem);
    const int tid  = threadIdx.x;
    const int wid  = tid >> 5;
    const int lane = tid & 31;
    const int m0 = blockIdx.y * 128;
    const int n0 = blockIdx.x * TN;
    const int wm0 = (wid / WC) * WM;
    const int wn0 = (wid % WC) * 32;

    float acc[MI][4][4];
    #pragma unroll
    for (int mi = 0; mi < MI; mi++)
        #pragma unroll
        for (int ni = 0; ni < 4; ni++)
            #pragma unroll
            for (int e = 0; e < 4; e++) acc[mi][ni][e] = 0.0f;

    const int NC = K >> 6;
    load_chunk<TN>(sb, Ah, Al, Bh, Bl, m0, n0, 0, lda, ldb, tid);
    if (NC > 1)
        load_chunk<TN>(sb + STAGE, Ah, Al, Bh, Bl, m0, n0, 64, lda, ldb, tid);

    for (int i = 0; i < NC; i++) {
        if (i + 1 < NC) { CP_WAIT1(); } else { CP_WAIT0(); }
        __syncthreads();

        const uint32_t st = sb + (i & 1) * STAGE;
        #pragma unroll
        for (int kk = 0; kk < 4; kk++) {
            uint32_t ah[MI][4], al[MI][4], bh[4][2], bl[4][2];
            const int colA = kk * 32 + ((lane & 16) ? 16 : 0);
            const int rA   = lane & 15;
            #pragma unroll
            for (int mi = 0; mi < MI; mi++) {
                uint32_t off = SW128((uint32_t)(wm0 + mi * 16 + rA) * 128 + colA);
                LDSM4(ah[mi][0], ah[mi][1], ah[mi][2], ah[mi][3], st + off);
                LDSM4(al[mi][0], al[mi][1], al[mi][2], al[mi][3], st + A_BYTES + off);
            }
            const int colB = kk * 32 + ((lane & 8) ? 16 : 0);
            const int rB   = (lane & 7) + ((lane & 16) ? 8 : 0);
            #pragma unroll
            for (int nj = 0; nj < 2; nj++) {
                uint32_t off = SW128((uint32_t)(wn0 + nj * 16 + rB) * 128 + colB);
                LDSM4(bh[nj*2][0], bh[nj*2][1], bh[nj*2+1][0], bh[nj*2+1][1],
                      st + 2 * A_BYTES + off);
                LDSM4(bl[nj*2][0], bl[nj*2][1], bl[nj*2+1][0], bl[nj*2+1][1],
                      st + 2 * A_BYTES + B_BYTES + off);
            }
            #pragma unroll
            for (int mi = 0; mi < MI; mi++)
                #pragma unroll
                for (int ni = 0; ni < 4; ni++) {
                    mma_bf16(acc[mi][ni], ah[mi], bh[ni]);
                    mma_bf16(acc[mi][ni], ah[mi], bl[ni]);
                    mma_bf16(acc[mi][ni], al[mi], bh[ni]);
                }
        }
        __syncthreads();
        if (i + 2 < NC)
            load_chunk<TN>(sb + (i & 1) * STAGE, Ah, Al, Bh, Bl, m0, n0,
                           (long long)(i + 2) * 64, lda, ldb, tid);
    }

    constexpr int LDS = OVT ? (TN + 1) : (TN + 8);
    float* sOut = (float*)smem;
    __syncthreads();

    #pragma unroll
    for (int mi = 0; mi < MI; mi++) {
        const int r0 = wm0 + mi * 16 + (lane >> 2);
        #pragma unroll
        for (int ni = 0; ni < 4; ni++) {
            const int c0 = wn0 + ni * 8 + (lane & 3) * 2;
            sOut[r0 * LDS + c0]           = acc[mi][ni][0];
            sOut[r0 * LDS + c0 + 1]       = acc[mi][ni][1];
            sOut[(r0 + 8) * LDS + c0]     = acc[mi][ni][2];
            sOut[(r0 + 8) * LDS + c0 + 1] = acc[mi][ni][3];
        }
    }
    __syncthreads();

    if (OVT) {
        // V projection: write C^T per head as bf16 hi/lo.
        // token tile m0 (never crosses a batch), feature e = n0 + col.
        // 128 rows per tile: each thread covers both row halves.
        const int bb = m0 / NKV;
        const int nb = m0 % NKV;
        const int colw = tid >> 5;             // warp -> column group
        #pragma unroll
        for (int cp = 0; cp < 16; cp++) {
            const int col = colw + cp * 8;
            const int e = n0 + col;
            const int hh2 = e >> 6, dd = e & 63;
            const long long base =
                ((long long)(hh2 * BATCH + bb) * HDIM + dd) * NKV + nb;
            const float bv = bias[e];
            #pragma unroll
            for (int rh = 0; rh < 2; rh++) {
                const int row0 = rh * 64 + 2 * lane;
                const float v0 = sOut[row0       * LDS + col] + bv;
                const float v1 = sOut[(row0 + 1) * LDS + col] + bv;
                uint32_t hiw, low;
                split2(v0, v1, hiw, low);
                *(uint32_t*)(Chi + base + row0) = hiw;
                *(uint32_t*)(Clo + base + row0) = low;
            }
        }
        return;
    }

    constexpr int RPI = 256 / TN;
    const int c = tid & (TN - 1);
    const int rs = tid / TN;
    const int n = n0 + c;
    #pragma unroll 4
    for (int rr = 0; rr < 128; rr += RPI) {
        const int r = rr + rs;
        float v = sOut[r * LDS + c] * alpha;
        if (bias) v += bias[n];
        if (EPI == 2) v = gelu_exact(v);
        if (EPI == 1) v += Dadd[(long long)(m0 + r) * ldd + n];
        const long long o = (long long)(m0 + r) * ldc + n;
        if (OF32) C[o] = v;
        if (OBF16) {
            bf16 hi = __float2bfloat16(v);
            Chi[o] = hi;
            Clo[o] = __float2bfloat16(v - __bfloat162float(hi));
        }
    }
}

template<int EPI, bool OF32, bool OBF16>
__global__ void __launch_bounds__(256, 1)
k_dense(const bf16* Ah, const bf16* Al, const bf16* Bh, const bf16* Bl,
        const float* bias, const float* Dadd,
        float* C, bf16* Chi, bf16* Clo, int K, int ldc, int ldd)
{
    tc_gemm<128, EPI, OF32, OBF16, false>(Ah, Al, Bh, Bl, bias, Dadd, C, Chi, Clo,
                                          K, K, K, ldc, ldd, 1.0f);
}

__global__ void __launch_bounds__(256, 1)
k_dense_vT(const bf16* Ah, const bf16* Al, const bf16* Bh, const bf16* Bl,
           const float* bias, bf16* Vth, bf16* Vtl)
{
    tc_gemm<128, 0, false, false, true>(Ah, Al, Bh, Bl, bias, nullptr,
                                        nullptr, Vth, Vtl,
                                        DMODEL, DMODEL, DMODEL, 0, 0, 1.0f);
}

// ============================================================================
//   fused attention: S = QK^T/8 -> p = exp(S) -> attn, ctx = (p/l)@V,
//   attn normalized in-kernel at the tail (CTA-local re-read, L2-friendly).
// ============================================================================
#define ATTN_SMEM (32768 + 2*65536)
#define NCH (NKV/128)

__device__ __forceinline__ void load_kv(
    uint32_t st, const bf16* __restrict__ kh, const bf16* __restrict__ kl,
    const bf16* __restrict__ vh, const bf16* __restrict__ vl, int ci, int tid)
{
    #pragma unroll
    for (int it = 0; it < 4; it++) {
        int idx = tid + it * 256;
        int r = idx >> 3, c = idx & 7;
        uint32_t so = SW128((uint32_t)r * 128 + c * 16);
        long long go = (long long)(ci * 128 + r) * DMODEL + c * 8;
        cp16(st + so,         kh + go);
        cp16(st + 16384 + so, kl + go);
    }
    #pragma unroll
    for (int it = 0; it < 4; it++) {
        int idx = tid + it * 256;
        int hf = idx >> 9, d = (idx >> 3) & 63, c = idx & 7;
        uint32_t so = (uint32_t)hf * 8192 + SW128((uint32_t)d * 128 + c * 16);
        long long go = (long long)d * NKV + ci * 128 + hf * 64 + c * 8;
        cp16(st + 32768 + so, vh + go);
        cp16(st + 49152 + so, vl + go);
    }
    CP_COMMIT();
}

__global__ void __launch_bounds__(256, 1)
k_attn(const bf16* __restrict__ qph, const bf16* __restrict__ qpl,
       const bf16* __restrict__ kph, const bf16* __restrict__ kpl,
       const bf16* __restrict__ vth, const bf16* __restrict__ vtl,
       float* __restrict__ attn,
       bf16* __restrict__ ctxh, bf16* __restrict__ ctxl)
{
    extern __shared__ char smem[];
    const uint32_t sb = smem_u32(smem);
    const int tid = threadIdx.x, wid = tid >> 5, lane = tid & 31;
    const int z  = blockIdx.x;            // h*BATCH + b
    const int h  = z / BATCH, b = z % BATCH;
    const int m0 = blockIdx.y * 128;
    const int wm0 = wid * 16;

    const bf16* khb = kph + (long long)b * NKV * DMODEL + h * HDIM;
    const bf16* klb = kpl + (long long)b * NKV * DMODEL + h * HDIM;
    const bf16* vhb = vth + (long long)z * HDIM * NKV;
    const bf16* vlb = vtl + (long long)z * HDIM * NKV;
    float* attn_w = attn + ((long long)z * MQ + m0 + wm0) * NKV;

    const uint32_t sQ = sb;                 // hi; +16384 lo
    const uint32_t sS = sb + 32768;         // stage base

    {
        const bf16* qh0 = qph + ((long long)(b * MQ + m0)) * DMODEL + h * HDIM;
        const bf16* ql0 = qpl + ((long long)(b * MQ + m0)) * DMODEL + h * HDIM;
        #pragma unroll
        for (int it = 0; it < 4; it++) {
            int idx = tid + it * 256;
            int r = idx >> 3, c = idx & 7;
            uint32_t so = SW128((uint32_t)r * 128 + c * 16);
            long long go = (long long)r * DMODEL + c * 8;
            cp16(sQ + so,         qh0 + go);
            cp16(sQ + 16384 + so, ql0 + go);
        }
        CP_COMMIT();
    }
    load_kv(sS,         khb, klb, vhb, vlb, 0, tid);
    load_kv(sS + 65536, khb, klb, vhb, vlb, 1, tid);

    CP_WAIT2();
    __syncthreads();

    // preload Q fragments (persistent)
    uint32_t qfh[4][4], qfl[4][4];
    {
        const int rA = lane & 15;
        #pragma unroll
        for (int kk = 0; kk < 4; kk++) {
            const int colA = kk * 32 + ((lane & 16) ? 16 : 0);
            uint32_t off = SW128((uint32_t)(wm0 + rA) * 128 + colA);
            LDSM4(qfh[kk][0], qfh[kk][1], qfh[kk][2], qfh[kk][3], sQ + off);
            LDSM4(qfl[kk][0], qfl[kk][1], qfl[kk][2], qfl[kk][3], sQ + 16384 + off);
        }
    }

    float cacc[8][4];
    #pragma unroll
    for (int i = 0; i < 8; i++)
        #pragma unroll
        for (int e = 0; e < 4; e++) cacc[i][e] = 0.0f;
    float lp0 = 0.0f, lp1 = 0.0f;

    const int rB   = (lane & 7) + ((lane & 16) ? 8 : 0);
    const int r    = lane >> 2;
    const int c2   = (lane & 3) * 2;
    const float CE = 0.125f * 1.4426950408889634f;

    for (int ci = 0; ci < NCH; ci++) {
        if (ci + 1 < NCH) { CP_WAIT1(); } else { CP_WAIT0(); }
        __syncthreads();
        const uint32_t st = sS + (ci & 1) * 65536;

        // ---- S = Q K^T ----
        float sacc[16][4];
        #pragma unroll
        for (int t = 0; t < 16; t++)
            #pragma unroll
            for (int e = 0; e < 4; e++) sacc[t][e] = 0.0f;

        #pragma unroll
        for (int kk = 0; kk < 4; kk++) {
            const int colB = kk * 32 + ((lane & 8) ? 16 : 0);
            #pragma unroll
            for (int nt = 0; nt < 8; nt++) {
                uint32_t off = SW128((uint32_t)(nt * 16 + rB) * 128 + colB);
                uint32_t bh[4], bl[4];
                LDSM4(bh[0], bh[1], bh[2], bh[3], st + off);
                LDSM4(bl[0], bl[1], bl[2], bl[3], st + 16384 + off);
                mma_bf16(sacc[2*nt],   qfh[kk], bh);
                mma_bf16(sacc[2*nt],   qfh[kk], bl);
                mma_bf16(sacc[2*nt],   qfl[kk], bh);
                mma_bf16(sacc[2*nt+1], qfh[kk], bh + 2);
                mma_bf16(sacc[2*nt+1], qfh[kk], bl + 2);
                mma_bf16(sacc[2*nt+1], qfl[kk], bh + 2);
            }
        }

        // ---- p = exp(S/8); write unnormalized attn; row sums ----
        float* a0 = attn_w + (long long)r * NKV + ci * 128;
        float* a1 = a0 + 8 * NKV;
        #pragma unroll
        for (int t = 0; t < 16; t++) {
            float p0 = ex2(sacc[t][0] * CE);
            float p1 = ex2(sacc[t][1] * CE);
            float p2 = ex2(sacc[t][2] * CE);
            float p3 = ex2(sacc[t][3] * CE);
            sacc[t][0] = p0; sacc[t][1] = p1; sacc[t][2] = p2; sacc[t][3] = p3;
            lp0 += p0 + p1;  lp1 += p2 + p3;
            *(float2*)(a0 + t * 8 + c2) = make_float2(p0, p1);
            *(float2*)(a1 + t * 8 + c2) = make_float2(p2, p3);
        }

        // ---- ctx += P V ----
        #pragma unroll
        for (int ks = 0; ks < 8; ks++) {
            uint32_t ah[4], al[4];
            split2(sacc[2*ks][0],   sacc[2*ks][1],   ah[0], al[0]);
            split2(sacc[2*ks][2],   sacc[2*ks][3],   ah[1], al[1]);
            split2(sacc[2*ks+1][0], sacc[2*ks+1][1], ah[2], al[2]);
            split2(sacc[2*ks+1][2], sacc[2*ks+1][3], ah[3], al[3]);

            const int hf = ks >> 2;
            const int colB = (ks & 3) * 32 + ((lane & 8) ? 16 : 0);
            const uint32_t vh_base = st + 32768 + hf * 8192;
            const uint32_t vl_base = st + 49152 + hf * 8192;
            #pragma unroll
            for (int dt = 0; dt < 4; dt++) {
                uint32_t off = SW128((uint32_t)(dt * 16 + rB) * 128 + colB);
                uint32_t bh[4], bl[4];
                LDSM4(bh[0], bh[1], bh[2], bh[3], vh_base + off);
                LDSM4(bl[0], bl[1], bl[2], bl[3], vl_base + off);
                mma_bf16(cacc[2*dt],   ah, bh);
                mma_bf16(cacc[2*dt],   ah, bl);
                mma_bf16(cacc[2*dt],   al, bh);
                mma_bf16(cacc[2*dt+1], ah, bh + 2);
                mma_bf16(cacc[2*dt+1], ah, bl + 2);
                mma_bf16(cacc[2*dt+1], al, bh + 2);
            }
        }

        __syncthreads();
        if (ci + 2 < NCH)
            load_kv(sS + (ci & 1) * 65536, khb, klb, vhb, vlb, ci + 2, tid);
    }

    // ---- row sums -> inverse; ctx write; in-kernel attn normalize ----
    lp0 += __shfl_xor_sync(0xFFFFFFFFu, lp0, 1);
    lp0 += __shfl_xor_sync(0xFFFFFFFFu, lp0, 2);
    lp1 += __shfl_xor_sync(0xFFFFFFFFu, lp1, 1);
    lp1 += __shfl_xor_sync(0xFFFFFFFFu, lp1, 2);
    const float il0 = 1.0f / lp0, il1 = 1.0f / lp1;

    float* ssum = (float*)smem;          // stage smem retired
    if ((lane & 3) == 0) {
        ssum[wm0 + r]     = il0;
        ssum[wm0 + r + 8] = il1;
    }

    const long long cb = ((long long)(b * MQ + m0 + wm0)) * DMODEL + h * HDIM;
    #pragma unroll
    for (int dt = 0; dt < 8; dt++) {
        const int d0 = dt * 8 + c2;
        uint32_t hi, lo;
        split2(cacc[dt][0] * il0, cacc[dt][1] * il0, hi, lo);
        *(uint32_t*)(ctxh + cb + (long long)r * DMODEL + d0) = hi;
        *(uint32_t*)(ctxl + cb + (long long)r * DMODEL + d0) = lo;
        split2(cacc[dt][2] * il1, cacc[dt][3] * il1, hi, lo);
        *(uint32_t*)(ctxh + cb + (long long)(r + 8) * DMODEL + d0) = hi;
        *(uint32_t*)(ctxl + cb + (long long)(r + 8) * DMODEL + d0) = lo;
    }

    __syncthreads();   // orders p-writes + ssum for all warps

    float* ab = attn + ((long long)z * MQ + m0) * NKV;
    for (int rr = 0; rr < 128; rr += 8) {
        const int row = rr + wid;
        const float s = ssum[row];
        float4* p4 = (float4*)(ab + (long long)row * NKV);
        #pragma unroll
        for (int j = 0; j < 16; j++) {
            float4 v = p4[lane + 32 * j];
            v.x *= s; v.y *= s; v.z *= s; v.w *= s;
            p4[lane + 32 * j] = v;
        }
    }
}

// ---------------- fp32 -> bf16 hi/lo ----------------
__global__ void __launch_bounds__(256)
k_cvt(const float* __restrict__ x, bf16* __restrict__ hi, bf16* __restrict__ lo)
{
    const long long i = ((long long)blockIdx.x * 256 + threadIdx.x) * 4;
    const float4 v = *(const float4*)(x + i);
    bf16 h0 = __float2bfloat16(v.x), h1 = __float2bfloat16(v.y);
    bf16 h2 = __float2bfloat16(v.z), h3 = __float2bfloat16(v.w);
    hi[i+0] = h0; hi[i+1] = h1; hi[i+2] = h2; hi[i+3] = h3;
    lo[i+0] = __float2bfloat16(v.x - __bfloat162float(h0));
    lo[i+1] = __float2bfloat16(v.y - __bfloat162float(h1));
    lo[i+2] = __float2bfloat16(v.z - __bfloat162float(h2));
    lo[i+3] = __float2bfloat16(v.w - __bfloat162float(h3));
}

// ---------------- layernorm -> bf16 hi/lo ----------------
__global__ void __launch_bounds__(256)
k_ln(const float* __restrict__ x, const float* __restrict__ g,
     const float* __restrict__ b, bf16* __restrict__ oh, bf16* __restrict__ ol)
{
    __shared__ float r1[256], r2[256];
    const long long row = blockIdx.x;
    const float* p = x + row * (long long)DMODEL;
    const int t = threadIdx.x;

    float v[4]; float s = 0.0f, s2 = 0.0f;
    #pragma unroll
    for (int i = 0; i < 4; i++) {
        v[i] = p[t + i * 256];
        s += v[i]; s2 += v[i] * v[i];
    }
    r1[t] = s; r2[t] = s2; __syncthreads();
    for (int st = 128; st > 0; st >>= 1) {
        if (t < st) { r1[t] += r1[t + st]; r2[t] += r2[t + st]; }
        __syncthreads();
    }
    const float mu  = r1[0] * (1.0f / DMODEL);
    const float var = r2[0] * (1.0f / DMODEL) - mu * mu;
    const float inv = rsqrtf(var + 1e-5f);

    bf16* ph = oh + row * (long long)DMODEL;
    bf16* pl = ol + row * (long long)DMODEL;
    #pragma unroll
    for (int i = 0; i < 4; i++) {
        const int c = t + i * 256;
        const float y = (v[i] - mu) * inv * g[c] + b[c];
        bf16 hi = __float2bfloat16(y);
        ph[c] = hi;
        pl[c] = __float2bfloat16(y - __bfloat162float(hi));
    }
}

// ---------------- host launch ----------------
static void* sym(const void* s) { void* p; cudaGetSymbolAddress(&p, s); return p; }

extern "C" void kernel_launch(void* const* d_in, const int* in_sizes, int n_in,
                              void* d_out, int out_size)
{
    const float* x    = (const float*)d_in[0];
    const float* q    = (const float*)d_in[1];
    const float* w_q  = (const float*)d_in[2];
    const float* b_q  = (const float*)d_in[3];
    const float* w_k  = (const float*)d_in[4];
    const float* b_k  = (const float*)d_in[5];
    const float* w_v  = (const float*)d_in[6];
    const float* b_v  = (const float*)d_in[7];
    const float* w_o  = (const float*)d_in[8];
    const float* b_o  = (const float*)d_in[9];
    const float* ln2g = (const float*)d_in[10];
    const float* ln2b = (const float*)d_in[11];
    const float* w1   = (const float*)d_in[12];
    const float* b1   = (const float*)d_in[13];
    const float* w2   = (const float*)d_in[14];
    const float* b2   = (const float*)d_in[15];

    float* out  = (float*)d_out;
    float* attn = out + (long long)BATCH * MQ * DMODEL;

    float* resid = (float*)sym(g_resid);
    bf16 *qh=(bf16*)sym(g_qh), *ql=(bf16*)sym(g_ql);
    bf16 *xh=(bf16*)sym(g_xh), *xl=(bf16*)sym(g_xl);
    bf16 *wqh=(bf16*)sym(g_wqh), *wql=(bf16*)sym(g_wql);
    bf16 *wkh=(bf16*)sym(g_wkh), *wkl=(bf16*)sym(g_wkl);
    bf16 *wvh=(bf16*)sym(g_wvh), *wvl=(bf16*)sym(g_wvl);
    bf16 *woh=(bf16*)sym(g_woh), *wol=(bf16*)sym(g_wol);
    bf16 *w1h=(bf16*)sym(g_w1h), *w1l=(bf16*)sym(g_w1l);
    bf16 *w2h=(bf16*)sym(g_w2h), *w2l=(bf16*)sym(g_w2l);
    bf16 *qph=(bf16*)sym(g_qph), *qpl=(bf16*)sym(g_qpl);
    bf16 *kph=(bf16*)sym(g_kph), *kpl=(bf16*)sym(g_kpl);
    bf16 *vth=(bf16*)sym(g_vth), *vtl=(bf16*)sym(g_vtl);
    bf16 *ctxh=(bf16*)sym(g_ctxh), *ctxl=(bf16*)sym(g_ctxl);
    bf16 *hh=(bf16*)sym(g_hh), *hl=(bf16*)sym(g_hl);
    bf16 *h1h=(bf16*)sym(g_h1h), *h1l=(bf16*)sym(g_h1l);

    const int SMEM128 = 2 * (2 * 16384 + 2 * 16384);  // 131072
    cudaFuncSetAttribute((const void*)k_dense<0,false,true>, cudaFuncAttributeMaxDynamicSharedMemorySize, SMEM128);
    cudaFuncSetAttribute((const void*)k_dense<1,true,false>, cudaFuncAttributeMaxDynamicSharedMemorySize, SMEM128);
    cudaFuncSetAttribute((const void*)k_dense<2,false,true>, cudaFuncAttributeMaxDynamicSharedMemorySize, SMEM128);
    cudaFuncSetAttribute((const void*)k_dense_vT, cudaFuncAttributeMaxDynamicSharedMemorySize, SMEM128);
    cudaFuncSetAttribute((const void*)k_attn, cudaFuncAttributeMaxDynamicSharedMemorySize, ATTN_SMEM);

    const dim3 blk(256);
    #define CVT(src, hi, lo, nelem) k_cvt<<<(int)((nelem) / 1024), blk>>>(src, hi, lo)

    // launches 0-4 (so launch #5 = Q projection GEMM for ncu -s 5 -c 1)
    CVT(q,   qh,  ql,  (size_t)BATCH*MQ*DMODEL);
    CVT(x,   xh,  xl,  (size_t)BATCH*NKV*DMODEL);
    CVT(w_q, wqh, wql, (size_t)DMODEL*DMODEL);
    CVT(w_k, wkh, wkl, (size_t)DMODEL*DMODEL);
    CVT(w_v, wvh, wvl, (size_t)DMODEL*DMODEL);

    // launch 5: Q projection
    k_dense<0,false,true><<<dim3(8, 32), blk, SMEM128>>>(qh, ql, wqh, wql, b_q, nullptr,
        nullptr, qph, qpl, DMODEL, DMODEL, 0);
    // K projection
    k_dense<0,false,true><<<dim3(8, 64), blk, SMEM128>>>(xh, xl, wkh, wkl, b_k, nullptr,
        nullptr, kph, kpl, DMODEL, DMODEL, 0);
    // V projection -> transposed bf16 hi/lo directly
    k_dense_vT<<<dim3(8, 64), blk, SMEM128>>>(xh, xl, wvh, wvl, b_v, vth, vtl);

    // fused attention (attn normalized in-kernel)
    k_attn<<<dim3(ZHB, MQ/128), blk, ATTN_SMEM>>>(qph, qpl, kph, kpl, vth, vtl,
                                                  attn, ctxh, ctxl);

    // remaining weight conversions (independent of attention)
    CVT(w_o, woh, wol, (size_t)DMODEL*DMODEL);
    CVT(w1,  w1h, w1l, (size_t)DMLP*DMODEL);
    CVT(w2,  w2h, w2l, (size_t)DMODEL*DMLP);

    // resid = ctx @ w_o^T + b_o + q
    k_dense<1,true,false><<<dim3(8, 32), blk, SMEM128>>>(ctxh, ctxl, woh, wol, b_o, q,
        resid, nullptr, nullptr, DMODEL, DMODEL, DMODEL);

    // h = LN(resid) -> bf16 hi/lo
    k_ln<<<BATCH*MQ, blk>>>(resid, ln2g, ln2b, hh, hl);

    // h1 = gelu(h @ w1^T + b1) -> bf16 hi/lo
    k_dense<2,false,true><<<dim3(32, 32), blk, SMEM128>>>(hh, hl, w1h, w1l, b1, nullptr,
        nullptr, h1h, h1l, DMODEL, DMLP, 0);

    // out = h1 @ w2^T + b2 + resid
    k_dense<1,true,false><<<dim3(8, 32), blk, SMEM128>>>(h1h, h1l, w2h, w2l, b2, resid,
        out, nullptr, nullptr, DMLP, DMODEL, DMODEL);

    #undef CVT
}

// round 7
// speedup vs baseline: 5.3246x; 1.0194x over previous
#include <cuda_runtime.h>
#include <cuda_bf16.h>
#include <math.h>
#include <stdint.h>

// ---------------- problem constants ----------------
#define BATCH  4
#define MQ     1024
#define NKV    2048
#define DMODEL 1024
#define NHEAD  16
#define HDIM   64
#define DMLP   4096
#define ZHB    (NHEAD*BATCH)

typedef __nv_bfloat16 bf16;

// ---------------- scratch (device globals; no allocs allowed) ----------------
__device__ __align__(1024) float g_resid[(size_t)BATCH*MQ*DMODEL];

__device__ __align__(1024) bf16 g_qh [(size_t)BATCH*MQ*DMODEL];
__device__ __align__(1024) bf16 g_ql [(size_t)BATCH*MQ*DMODEL];
__device__ __align__(1024) bf16 g_xh [(size_t)BATCH*NKV*DMODEL];
__device__ __align__(1024) bf16 g_xl [(size_t)BATCH*NKV*DMODEL];
__device__ __align__(1024) bf16 g_wqh[(size_t)DMODEL*DMODEL];
__device__ __align__(1024) bf16 g_wql[(size_t)DMODEL*DMODEL];
__device__ __align__(1024) bf16 g_wkh[(size_t)DMODEL*DMODEL];
__device__ __align__(1024) bf16 g_wkl[(size_t)DMODEL*DMODEL];
__device__ __align__(1024) bf16 g_wvh[(size_t)DMODEL*DMODEL];
__device__ __align__(1024) bf16 g_wvl[(size_t)DMODEL*DMODEL];
__device__ __align__(1024) bf16 g_woh[(size_t)DMODEL*DMODEL];
__device__ __align__(1024) bf16 g_wol[(size_t)DMODEL*DMODEL];
__device__ __align__(1024) bf16 g_w1h[(size_t)DMLP*DMODEL];
__device__ __align__(1024) bf16 g_w1l[(size_t)DMLP*DMODEL];
__device__ __align__(1024) bf16 g_w2h[(size_t)DMODEL*DMLP];
__device__ __align__(1024) bf16 g_w2l[(size_t)DMODEL*DMLP];
__device__ __align__(1024) bf16 g_qph[(size_t)BATCH*MQ*DMODEL];
__device__ __align__(1024) bf16 g_qpl[(size_t)BATCH*MQ*DMODEL];
__device__ __align__(1024) bf16 g_kph[(size_t)BATCH*NKV*DMODEL];
__device__ __align__(1024) bf16 g_kpl[(size_t)BATCH*NKV*DMODEL];
__device__ __align__(1024) bf16 g_vth[(size_t)ZHB*HDIM*NKV];
__device__ __align__(1024) bf16 g_vtl[(size_t)ZHB*HDIM*NKV];
__device__ __align__(1024) bf16 g_ctxh[(size_t)BATCH*MQ*DMODEL];
__device__ __align__(1024) bf16 g_ctxl[(size_t)BATCH*MQ*DMODEL];
__device__ __align__(1024) bf16 g_hh [(size_t)BATCH*MQ*DMODEL];
__device__ __align__(1024) bf16 g_hl [(size_t)BATCH*MQ*DMODEL];
__device__ __align__(1024) bf16 g_h1h[(size_t)BATCH*MQ*DMLP];
__device__ __align__(1024) bf16 g_h1l[(size_t)BATCH*MQ*DMLP];

// ---------------- helpers ----------------
#define SW128(o) ((uint32_t)(o) ^ ((((uint32_t)(o)) >> 3) & 0x70u))

__device__ __forceinline__ uint32_t smem_u32(const void* p) {
    return (uint32_t)__cvta_generic_to_shared(p);
}

__device__ __forceinline__ void cp16(uint32_t dst, const void* src) {
    asm volatile("cp.async.cg.shared.global [%0], [%1], 16;" :: "r"(dst), "l"(src));
}
#define CP_COMMIT() asm volatile("cp.async.commit_group;" ::: "memory")
#define CP_WAIT0()  asm volatile("cp.async.wait_group 0;" ::: "memory")
#define CP_WAIT1()  asm volatile("cp.async.wait_group 1;" ::: "memory")
#define CP_WAIT2()  asm volatile("cp.async.wait_group 2;" ::: "memory")

#define LDSM4(r0, r1, r2, r3, addr) \
    asm volatile("ldmatrix.sync.aligned.m8n8.x4.shared.b16 {%0,%1,%2,%3}, [%4];" \
        : "=r"(r0), "=r"(r1), "=r"(r2), "=r"(r3) : "r"(addr))

__device__ __forceinline__ void mma_bf16(float* c, const uint32_t* a, const uint32_t* b) {
    asm volatile(
        "mma.sync.aligned.m16n8k16.row.col.f32.bf16.bf16.f32 "
        "{%0,%1,%2,%3}, {%4,%5,%6,%7}, {%8,%9}, {%0,%1,%2,%3};"
        : "+f"(c[0]), "+f"(c[1]), "+f"(c[2]), "+f"(c[3])
        : "r"(a[0]), "r"(a[1]), "r"(a[2]), "r"(a[3]), "r"(b[0]), "r"(b[1]));
}

__device__ __forceinline__ float ex2(float x) {
    float r;
    asm("ex2.approx.f32 %0, %1;" : "=f"(r) : "f"(x));
    return r;
}

__device__ __forceinline__ float gelu_exact(float v) {
    return 0.5f * v * (1.0f + erff(v * 0.70710678118654752440f));
}

// split two fp32 into packed bf16x2 hi and residual-lo words
__device__ __forceinline__ void split2(float e0, float e1, uint32_t& hi, uint32_t& lo) {
    bf16 h0 = __float2bfloat16(e0), h1 = __float2bfloat16(e1);
    __nv_bfloat162 hp; hp.x = h0; hp.y = h1;
    hi = *reinterpret_cast<uint32_t*>(&hp);
    float f0 = __bfloat162float(h0), f1 = __bfloat162float(h1);
    __nv_bfloat162 lp = __floats2bfloat162_rn(e0 - f0, e1 - f1);
    lo = *reinterpret_cast<uint32_t*>(&lp);
}

// ============================================================================
//        dense split-bf16 GEMM: TN=64, 512 threads, 96KB -> 2 CTAs/SM
// ============================================================================
#define DNT 512                 // threads per dense-GEMM CTA
#define DTN 64                  // N tile

template<int TN, int NT>
__device__ __forceinline__ void load_chunk(
    uint32_t st, const bf16* __restrict__ Ah, const bf16* __restrict__ Al,
    const bf16* __restrict__ Bh, const bf16* __restrict__ Bl,
    int m0, int n0, long long kc, int lda, int ldb, int tid)
{
    constexpr int A_BYTES = 128 * 128;
    constexpr int B_BYTES = TN * 128;
    #pragma unroll
    for (int it = 0; it < 1024 / NT; it++) {
        int idx = tid + it * NT;
        int r = idx >> 3, c = idx & 7;
        uint32_t so = SW128(r * 128 + c * 16);
        long long go = (long long)(m0 + r) * lda + kc + c * 8;
        cp16(st + so,           Ah + go);
        cp16(st + A_BYTES + so, Al + go);
    }
    #pragma unroll
    for (int it = 0; it < TN * 8 / NT; it++) {
        int idx = tid + it * NT;
        int r = idx >> 3, c = idx & 7;
        uint32_t so = SW128(r * 128 + c * 16);
        long long go = (long long)(n0 + r) * ldb + kc + c * 8;
        cp16(st + 2 * A_BYTES + so,           Bh + go);
        cp16(st + 2 * A_BYTES + B_BYTES + so, Bl + go);
    }
    CP_COMMIT();
}

// EPI: 0 none, 1 +Dadd, 2 gelu. OF32: fp32 C. OBF16: bf16 hi/lo C.
// OVT: write transposed per-head bf16 hi/lo (V projection)
template<int TN, int NT, int EPI, bool OF32, bool OBF16, bool OVT>
__device__ void tc_gemm(
    const bf16* __restrict__ Ah, const bf16* __restrict__ Al,
    const bf16* __restrict__ Bh, const bf16* __restrict__ Bl,
    const float* __restrict__ bias, const float* __restrict__ Dadd,
    float* __restrict__ C, bf16* __restrict__ Chi, bf16* __restrict__ Clo,
    int K, int lda, int ldb, int ldc, int ldd, float alpha)
{
    extern __shared__ char smem[];
    constexpr int A_BYTES = 128 * 128;
    constexpr int B_BYTES = TN * 128;
    constexpr int STAGE   = 2 * A_BYTES + 2 * B_BYTES;
    constexpr int NW = NT / 32;
    constexpr int WC = TN / 32;       // warps along N
    constexpr int WR = NW / WC;       // warps along M
    constexpr int WM = 128 / WR;      // rows per warp
    constexpr int MI = WM / 16;       // m16 tiles per warp

    const uint32_t sb = smem_u32(smem);
    const int tid  = threadIdx.x;
    const int wid  = tid >> 5;
    const int lane = tid & 31;
    const int m0 = blockIdx.y * 128;
    const int n0 = blockIdx.x * TN;
    const int wm0 = (wid / WC) * WM;
    const int wn0 = (wid % WC) * 32;

    float acc[MI][4][4];
    #pragma unroll
    for (int mi = 0; mi < MI; mi++)
        #pragma unroll
        for (int ni = 0; ni < 4; ni++)
            #pragma unroll
            for (int e = 0; e < 4; e++) acc[mi][ni][e] = 0.0f;

    const int NC = K >> 6;
    load_chunk<TN, NT>(sb, Ah, Al, Bh, Bl, m0, n0, 0, lda, ldb, tid);
    if (NC > 1)
        load_chunk<TN, NT>(sb + STAGE, Ah, Al, Bh, Bl, m0, n0, 64, lda, ldb, tid);

    for (int i = 0; i < NC; i++) {
        if (i + 1 < NC) { CP_WAIT1(); } else { CP_WAIT0(); }
        __syncthreads();

        const uint32_t st = sb + (i & 1) * STAGE;
        #pragma unroll
        for (int kk = 0; kk < 4; kk++) {
            uint32_t ah[MI][4], al[MI][4], bh[4][2], bl[4][2];
            const int colA = kk * 32 + ((lane & 16) ? 16 : 0);
            const int rA   = lane & 15;
            #pragma unroll
            for (int mi = 0; mi < MI; mi++) {
                uint32_t off = SW128((uint32_t)(wm0 + mi * 16 + rA) * 128 + colA);
                LDSM4(ah[mi][0], ah[mi][1], ah[mi][2], ah[mi][3], st + off);
                LDSM4(al[mi][0], al[mi][1], al[mi][2], al[mi][3], st + A_BYTES + off);
            }
            const int colB = kk * 32 + ((lane & 8) ? 16 : 0);
            const int rB   = (lane & 7) + ((lane & 16) ? 8 : 0);
            #pragma unroll
            for (int nj = 0; nj < 2; nj++) {
                uint32_t off = SW128((uint32_t)(wn0 + nj * 16 + rB) * 128 + colB);
                LDSM4(bh[nj*2][0], bh[nj*2][1], bh[nj*2+1][0], bh[nj*2+1][1],
                      st + 2 * A_BYTES + off);
                LDSM4(bl[nj*2][0], bl[nj*2][1], bl[nj*2+1][0], bl[nj*2+1][1],
                      st + 2 * A_BYTES + B_BYTES + off);
            }
            #pragma unroll
            for (int mi = 0; mi < MI; mi++)
                #pragma unroll
                for (int ni = 0; ni < 4; ni++) {
                    mma_bf16(acc[mi][ni], ah[mi], bh[ni]);
                    mma_bf16(acc[mi][ni], ah[mi], bl[ni]);
                    mma_bf16(acc[mi][ni], al[mi], bh[ni]);
                }
        }
        __syncthreads();
        if (i + 2 < NC)
            load_chunk<TN, NT>(sb + (i & 1) * STAGE, Ah, Al, Bh, Bl, m0, n0,
                               (long long)(i + 2) * 64, lda, ldb, tid);
    }

    constexpr int LDS = OVT ? (TN + 1) : (TN + 8);
    float* sOut = (float*)smem;
    __syncthreads();

    #pragma unroll
    for (int mi = 0; mi < MI; mi++) {
        const int r0 = wm0 + mi * 16 + (lane >> 2);
        #pragma unroll
        for (int ni = 0; ni < 4; ni++) {
            const int c0 = wn0 + ni * 8 + (lane & 3) * 2;
            sOut[r0 * LDS + c0]           = acc[mi][ni][0];
            sOut[r0 * LDS + c0 + 1]       = acc[mi][ni][1];
            sOut[(r0 + 8) * LDS + c0]     = acc[mi][ni][2];
            sOut[(r0 + 8) * LDS + c0 + 1] = acc[mi][ni][3];
        }
    }
    __syncthreads();

    if (OVT) {
        // V projection: write C^T per head as bf16 hi/lo.
        // 16 warps cover 64 columns in 4 passes; lanes cover 128 rows in 2 halves.
        const int bb = m0 / NKV;
        const int nb = m0 % NKV;
        const int colw = tid >> 5;             // 0..15
        #pragma unroll
        for (int cp = 0; cp < TN / (NT / 32); cp++) {
            const int col = colw + cp * (NT / 32);
            const int e = n0 + col;
            const int hh2 = e >> 6, dd = e & 63;
            const long long base =
                ((long long)(hh2 * BATCH + bb) * HDIM + dd) * NKV + nb;
            const float bv = bias[e];
            #pragma unroll
            for (int rh = 0; rh < 2; rh++) {
                const int row0 = rh * 64 + 2 * lane;
                const float v0 = sOut[row0       * LDS + col] + bv;
                const float v1 = sOut[(row0 + 1) * LDS + col] + bv;
                uint32_t hiw, low;
                split2(v0, v1, hiw, low);
                *(uint32_t*)(Chi + base + row0) = hiw;
                *(uint32_t*)(Clo + base + row0) = low;
            }
        }
        return;
    }

    constexpr int RPI = NT / TN;
    const int c = tid & (TN - 1);
    const int rs = tid / TN;
    const int n = n0 + c;
    #pragma unroll 4
    for (int rr = 0; rr < 128; rr += RPI) {
        const int r = rr + rs;
        float v = sOut[r * LDS + c] * alpha;
        if (bias) v += bias[n];
        if (EPI == 2) v = gelu_exact(v);
        if (EPI == 1) v += Dadd[(long long)(m0 + r) * ldd + n];
        const long long o = (long long)(m0 + r) * ldc + n;
        if (OF32) C[o] = v;
        if (OBF16) {
            bf16 hi = __float2bfloat16(v);
            Chi[o] = hi;
            Clo[o] = __float2bfloat16(v - __bfloat162float(hi));
        }
    }
}

template<int EPI, bool OF32, bool OBF16>
__global__ void __launch_bounds__(DNT, 2)
k_dense(const bf16* Ah, const bf16* Al, const bf16* Bh, const bf16* Bl,
        const float* bias, const float* Dadd,
        float* C, bf16* Chi, bf16* Clo, int K, int ldc, int ldd)
{
    tc_gemm<DTN, DNT, EPI, OF32, OBF16, false>(Ah, Al, Bh, Bl, bias, Dadd, C, Chi, Clo,
                                               K, K, K, ldc, ldd, 1.0f);
}

__global__ void __launch_bounds__(DNT, 2)
k_dense_vT(const bf16* Ah, const bf16* Al, const bf16* Bh, const bf16* Bl,
           const float* bias, bf16* Vth, bf16* Vtl)
{
    tc_gemm<DTN, DNT, 0, false, false, true>(Ah, Al, Bh, Bl, bias, nullptr,
                                             nullptr, Vth, Vtl,
                                             DMODEL, DMODEL, DMODEL, 0, 0, 1.0f);
}

#define DSMEM (2 * (2 * 16384 + 2 * DTN * 128))   // 98304

// ============================================================================
//   fused attention: S = QK^T/8 -> p = exp(S) -> attn, ctx = (p/l)@V,
//   attn normalized in-kernel at the tail (CTA-local re-read, L2-friendly).
// ============================================================================
#define ATTN_SMEM (32768 + 2*65536)
#define NCH (NKV/128)

__device__ __forceinline__ void load_kv(
    uint32_t st, const bf16* __restrict__ kh, const bf16* __restrict__ kl,
    const bf16* __restrict__ vh, const bf16* __restrict__ vl, int ci, int tid)
{
    #pragma unroll
    for (int it = 0; it < 4; it++) {
        int idx = tid + it * 256;
        int r = idx >> 3, c = idx & 7;
        uint32_t so = SW128((uint32_t)r * 128 + c * 16);
        long long go = (long long)(ci * 128 + r) * DMODEL + c * 8;
        cp16(st + so,         kh + go);
        cp16(st + 16384 + so, kl + go);
    }
    #pragma unroll
    for (int it = 0; it < 4; it++) {
        int idx = tid + it * 256;
        int hf = idx >> 9, d = (idx >> 3) & 63, c = idx & 7;
        uint32_t so = (uint32_t)hf * 8192 + SW128((uint32_t)d * 128 + c * 16);
        long long go = (long long)d * NKV + ci * 128 + hf * 64 + c * 8;
        cp16(st + 32768 + so, vh + go);
        cp16(st + 49152 + so, vl + go);
    }
    CP_COMMIT();
}

__global__ void __launch_bounds__(256, 1)
k_attn(const bf16* __restrict__ qph, const bf16* __restrict__ qpl,
       const bf16* __restrict__ kph, const bf16* __restrict__ kpl,
       const bf16* __restrict__ vth, const bf16* __restrict__ vtl,
       float* __restrict__ attn,
       bf16* __restrict__ ctxh, bf16* __restrict__ ctxl)
{
    extern __shared__ char smem[];
    const uint32_t sb = smem_u32(smem);
    const int tid = threadIdx.x, wid = tid >> 5, lane = tid & 31;
    const int z  = blockIdx.x;            // h*BATCH + b
    const int h  = z / BATCH, b = z % BATCH;
    const int m0 = blockIdx.y * 128;
    const int wm0 = wid * 16;

    const bf16* khb = kph + (long long)b * NKV * DMODEL + h * HDIM;
    const bf16* klb = kpl + (long long)b * NKV * DMODEL + h * HDIM;
    const bf16* vhb = vth + (long long)z * HDIM * NKV;
    const bf16* vlb = vtl + (long long)z * HDIM * NKV;
    float* attn_w = attn + ((long long)z * MQ + m0 + wm0) * NKV;

    const uint32_t sQ = sb;                 // hi; +16384 lo
    const uint32_t sS = sb + 32768;         // stage base

    {
        const bf16* qh0 = qph + ((long long)(b * MQ + m0)) * DMODEL + h * HDIM;
        const bf16* ql0 = qpl + ((long long)(b * MQ + m0)) * DMODEL + h * HDIM;
        #pragma unroll
        for (int it = 0; it < 4; it++) {
            int idx = tid + it * 256;
            int r = idx >> 3, c = idx & 7;
            uint32_t so = SW128((uint32_t)r * 128 + c * 16);
            long long go = (long long)r * DMODEL + c * 8;
            cp16(sQ + so,         qh0 + go);
            cp16(sQ + 16384 + so, ql0 + go);
        }
        CP_COMMIT();
    }
    load_kv(sS,         khb, klb, vhb, vlb, 0, tid);
    load_kv(sS + 65536, khb, klb, vhb, vlb, 1, tid);

    CP_WAIT2();
    __syncthreads();

    // preload Q fragments (persistent)
    uint32_t qfh[4][4], qfl[4][4];
    {
        const int rA = lane & 15;
        #pragma unroll
        for (int kk = 0; kk < 4; kk++) {
            const int colA = kk * 32 + ((lane & 16) ? 16 : 0);
            uint32_t off = SW128((uint32_t)(wm0 + rA) * 128 + colA);
            LDSM4(qfh[kk][0], qfh[kk][1], qfh[kk][2], qfh[kk][3], sQ + off);
            LDSM4(qfl[kk][0], qfl[kk][1], qfl[kk][2], qfl[kk][3], sQ + 16384 + off);
        }
    }

    float cacc[8][4];
    #pragma unroll
    for (int i = 0; i < 8; i++)
        #pragma unroll
        for (int e = 0; e < 4; e++) cacc[i][e] = 0.0f;
    float lp0 = 0.0f, lp1 = 0.0f;

    const int rB   = (lane & 7) + ((lane & 16) ? 8 : 0);
    const int r    = lane >> 2;
    const int c2   = (lane & 3) * 2;
    const float CE = 0.125f * 1.4426950408889634f;

    for (int ci = 0; ci < NCH; ci++) {
        if (ci + 1 < NCH) { CP_WAIT1(); } else { CP_WAIT0(); }
        __syncthreads();
        const uint32_t st = sS + (ci & 1) * 65536;

        // ---- S = Q K^T ----
        float sacc[16][4];
        #pragma unroll
        for (int t = 0; t < 16; t++)
            #pragma unroll
            for (int e = 0; e < 4; e++) sacc[t][e] = 0.0f;

        #pragma unroll
        for (int kk = 0; kk < 4; kk++) {
            const int colB = kk * 32 + ((lane & 8) ? 16 : 0);
            #pragma unroll
            for (int nt = 0; nt < 8; nt++) {
                uint32_t off = SW128((uint32_t)(nt * 16 + rB) * 128 + colB);
                uint32_t bh[4], bl[4];
                LDSM4(bh[0], bh[1], bh[2], bh[3], st + off);
                LDSM4(bl[0], bl[1], bl[2], bl[3], st + 16384 + off);
                mma_bf16(sacc[2*nt],   qfh[kk], bh);
                mma_bf16(sacc[2*nt],   qfh[kk], bl);
                mma_bf16(sacc[2*nt],   qfl[kk], bh);
                mma_bf16(sacc[2*nt+1], qfh[kk], bh + 2);
                mma_bf16(sacc[2*nt+1], qfh[kk], bl + 2);
                mma_bf16(sacc[2*nt+1], qfl[kk], bh + 2);
            }
        }

        // ---- p = exp(S/8); write unnormalized attn; row sums ----
        float* a0 = attn_w + (long long)r * NKV + ci * 128;
        float* a1 = a0 + 8 * NKV;
        #pragma unroll
        for (int t = 0; t < 16; t++) {
            float p0 = ex2(sacc[t][0] * CE);
            float p1 = ex2(sacc[t][1] * CE);
            float p2 = ex2(sacc[t][2] * CE);
            float p3 = ex2(sacc[t][3] * CE);
            sacc[t][0] = p0; sacc[t][1] = p1; sacc[t][2] = p2; sacc[t][3] = p3;
            lp0 += p0 + p1;  lp1 += p2 + p3;
            *(float2*)(a0 + t * 8 + c2) = make_float2(p0, p1);
            *(float2*)(a1 + t * 8 + c2) = make_float2(p2, p3);
        }

        // ---- ctx += P V ----
        #pragma unroll
        for (int ks = 0; ks < 8; ks++) {
            uint32_t ah[4], al[4];
            split2(sacc[2*ks][0],   sacc[2*ks][1],   ah[0], al[0]);
            split2(sacc[2*ks][2],   sacc[2*ks][3],   ah[1], al[1]);
            split2(sacc[2*ks+1][0], sacc[2*ks+1][1], ah[2], al[2]);
            split2(sacc[2*ks+1][2], sacc[2*ks+1][3], ah[3], al[3]);

            const int hf = ks >> 2;
            const int colB = (ks & 3) * 32 + ((lane & 8) ? 16 : 0);
            const uint32_t vh_base = st + 32768 + hf * 8192;
            const uint32_t vl_base = st + 49152 + hf * 8192;
            #pragma unroll
            for (int dt = 0; dt < 4; dt++) {
                uint32_t off = SW128((uint32_t)(dt * 16 + rB) * 128 + colB);
                uint32_t bh[4], bl[4];
                LDSM4(bh[0], bh[1], bh[2], bh[3], vh_base + off);
                LDSM4(bl[0], bl[1], bl[2], bl[3], vl_base + off);
                mma_bf16(cacc[2*dt],   ah, bh);
                mma_bf16(cacc[2*dt],   ah, bl);
                mma_bf16(cacc[2*dt],   al, bh);
                mma_bf16(cacc[2*dt+1], ah, bh + 2);
                mma_bf16(cacc[2*dt+1], ah, bl + 2);
                mma_bf16(cacc[2*dt+1], al, bh + 2);
            }
        }

        __syncthreads();
        if (ci + 2 < NCH)
            load_kv(sS + (ci & 1) * 65536, khb, klb, vhb, vlb, ci + 2, tid);
    }

    // ---- row sums -> inverse; ctx write; in-kernel attn normalize ----
    lp0 += __shfl_xor_sync(0xFFFFFFFFu, lp0, 1);
    lp0 += __shfl_xor_sync(0xFFFFFFFFu, lp0, 2);
    lp1 += __shfl_xor_sync(0xFFFFFFFFu, lp1, 1);
    lp1 += __shfl_xor_sync(0xFFFFFFFFu, lp1, 2);
    const float il0 = 1.0f / lp0, il1 = 1.0f / lp1;

    float* ssum = (float*)smem;          // stage smem retired
    if ((lane & 3) == 0) {
        ssum[wm0 + r]     = il0;
        ssum[wm0 + r + 8] = il1;
    }

    const long long cb = ((long long)(b * MQ + m0 + wm0)) * DMODEL + h * HDIM;
    #pragma unroll
    for (int dt = 0; dt < 8; dt++) {
        const int d0 = dt * 8 + c2;
        uint32_t hi, lo;
        split2(cacc[dt][0] * il0, cacc[dt][1] * il0, hi, lo);
        *(uint32_t*)(ctxh + cb + (long long)r * DMODEL + d0) = hi;
        *(uint32_t*)(ctxl + cb + (long long)r * DMODEL + d0) = lo;
        split2(cacc[dt][2] * il1, cacc[dt][3] * il1, hi, lo);
        *(uint32_t*)(ctxh + cb + (long long)(r + 8) * DMODEL + d0) = hi;
        *(uint32_t*)(ctxl + cb + (long long)(r + 8) * DMODEL + d0) = lo;
    }

    __syncthreads();   // orders p-writes + ssum for all warps

    float* ab = attn + ((long long)z * MQ + m0) * NKV;
    for (int rr = 0; rr < 128; rr += 8) {
        const int row = rr + wid;
        const float s = ssum[row];
        float4* p4 = (float4*)(ab + (long long)row * NKV);
        #pragma unroll
        for (int j = 0; j < 16; j++) {
            float4 v = p4[lane + 32 * j];
            v.x *= s; v.y *= s; v.z *= s; v.w *= s;
            p4[lane + 32 * j] = v;
        }
    }
}

// ---------------- fp32 -> bf16 hi/lo ----------------
__global__ void __launch_bounds__(256)
k_cvt(const float* __restrict__ x, bf16* __restrict__ hi, bf16* __restrict__ lo)
{
    const long long i = ((long long)blockIdx.x * 256 + threadIdx.x) * 4;
    const float4 v = *(const float4*)(x + i);
    bf16 h0 = __float2bfloat16(v.x), h1 = __float2bfloat16(v.y);
    bf16 h2 = __float2bfloat16(v.z), h3 = __float2bfloat16(v.w);
    hi[i+0] = h0; hi[i+1] = h1; hi[i+2] = h2; hi[i+3] = h3;
    lo[i+0] = __float2bfloat16(v.x - __bfloat162float(h0));
    lo[i+1] = __float2bfloat16(v.y - __bfloat162float(h1));
    lo[i+2] = __float2bfloat16(v.z - __bfloat162float(h2));
    lo[i+3] = __float2bfloat16(v.w - __bfloat162float(h3));
}

// ---------------- layernorm -> bf16 hi/lo ----------------
__global__ void __launch_bounds__(256)
k_ln(const float* __restrict__ x, const float* __restrict__ g,
     const float* __restrict__ b, bf16* __restrict__ oh, bf16* __restrict__ ol)
{
    __shared__ float r1[256], r2[256];
    const long long row = blockIdx.x;
    const float* p = x + row * (long long)DMODEL;
    const int t = threadIdx.x;

    float v[4]; float s = 0.0f, s2 = 0.0f;
    #pragma unroll
    for (int i = 0; i < 4; i++) {
        v[i] = p[t + i * 256];
        s += v[i]; s2 += v[i] * v[i];
    }
    r1[t] = s; r2[t] = s2; __syncthreads();
    for (int st = 128; st > 0; st >>= 1) {
        if (t < st) { r1[t] += r1[t + st]; r2[t] += r2[t + st]; }
        __syncthreads();
    }
    const float mu  = r1[0] * (1.0f / DMODEL);
    const float var = r2[0] * (1.0f / DMODEL) - mu * mu;
    const float inv = rsqrtf(var + 1e-5f);

    bf16* ph = oh + row * (long long)DMODEL;
    bf16* pl = ol + row * (long long)DMODEL;
    #pragma unroll
    for (int i = 0; i < 4; i++) {
        const int c = t + i * 256;
        const float y = (v[i] - mu) * inv * g[c] + b[c];
        bf16 hi = __float2bfloat16(y);
        ph[c] = hi;
        pl[c] = __float2bfloat16(y - __bfloat162float(hi));
    }
}

// ---------------- host launch ----------------
static void* sym(const void* s) { void* p; cudaGetSymbolAddress(&p, s); return p; }

extern "C" void kernel_launch(void* const* d_in, const int* in_sizes, int n_in,
                              void* d_out, int out_size)
{
    const float* x    = (const float*)d_in[0];
    const float* q    = (const float*)d_in[1];
    const float* w_q  = (const float*)d_in[2];
    const float* b_q  = (const float*)d_in[3];
    const float* w_k  = (const float*)d_in[4];
    const float* b_k  = (const float*)d_in[5];
    const float* w_v  = (const float*)d_in[6];
    const float* b_v  = (const float*)d_in[7];
    const float* w_o  = (const float*)d_in[8];
    const float* b_o  = (const float*)d_in[9];
    const float* ln2g = (const float*)d_in[10];
    const float* ln2b = (const float*)d_in[11];
    const float* w1   = (const float*)d_in[12];
    const float* b1   = (const float*)d_in[13];
    const float* w2   = (const float*)d_in[14];
    const float* b2   = (const float*)d_in[15];

    float* out  = (float*)d_out;
    float* attn = out + (long long)BATCH * MQ * DMODEL;

    float* resid = (float*)sym(g_resid);
    bf16 *qh=(bf16*)sym(g_qh), *ql=(bf16*)sym(g_ql);
    bf16 *xh=(bf16*)sym(g_xh), *xl=(bf16*)sym(g_xl);
    bf16 *wqh=(bf16*)sym(g_wqh), *wql=(bf16*)sym(g_wql);
    bf16 *wkh=(bf16*)sym(g_wkh), *wkl=(bf16*)sym(g_wkl);
    bf16 *wvh=(bf16*)sym(g_wvh), *wvl=(bf16*)sym(g_wvl);
    bf16 *woh=(bf16*)sym(g_woh), *wol=(bf16*)sym(g_wol);
    bf16 *w1h=(bf16*)sym(g_w1h), *w1l=(bf16*)sym(g_w1l);
    bf16 *w2h=(bf16*)sym(g_w2h), *w2l=(bf16*)sym(g_w2l);
    bf16 *qph=(bf16*)sym(g_qph), *qpl=(bf16*)sym(g_qpl);
    bf16 *kph=(bf16*)sym(g_kph), *kpl=(bf16*)sym(g_kpl);
    bf16 *vth=(bf16*)sym(g_vth), *vtl=(bf16*)sym(g_vtl);
    bf16 *ctxh=(bf16*)sym(g_ctxh), *ctxl=(bf16*)sym(g_ctxl);
    bf16 *hh=(bf16*)sym(g_hh), *hl=(bf16*)sym(g_hl);
    bf16 *h1h=(bf16*)sym(g_h1h), *h1l=(bf16*)sym(g_h1l);

    cudaFuncSetAttribute((const void*)k_dense<0,false,true>, cudaFuncAttributeMaxDynamicSharedMemorySize, DSMEM);
    cudaFuncSetAttribute((const void*)k_dense<1,true,false>, cudaFuncAttributeMaxDynamicSharedMemorySize, DSMEM);
    cudaFuncSetAttribute((const void*)k_dense<2,false,true>, cudaFuncAttributeMaxDynamicSharedMemorySize, DSMEM);
    cudaFuncSetAttribute((const void*)k_dense_vT, cudaFuncAttributeMaxDynamicSharedMemorySize, DSMEM);
    cudaFuncSetAttribute((const void*)k_attn, cudaFuncAttributeMaxDynamicSharedMemorySize, ATTN_SMEM);

    const dim3 blk(256);
    const dim3 dblk(DNT);
    #define CVT(src, hi, lo, nelem) k_cvt<<<(int)((nelem) / 1024), blk>>>(src, hi, lo)

    CVT(q,   qh,  ql,  (size_t)BATCH*MQ*DMODEL);
    CVT(x,   xh,  xl,  (size_t)BATCH*NKV*DMODEL);
    CVT(w_q, wqh, wql, (size_t)DMODEL*DMODEL);
    CVT(w_k, wkh, wkl, (size_t)DMODEL*DMODEL);
    CVT(w_v, wvh, wvl, (size_t)DMODEL*DMODEL);

    // Q projection
    k_dense<0,false,true><<<dim3(DMODEL/DTN, 32), dblk, DSMEM>>>(qh, ql, wqh, wql, b_q, nullptr,
        nullptr, qph, qpl, DMODEL, DMODEL, 0);
    // K projection
    k_dense<0,false,true><<<dim3(DMODEL/DTN, 64), dblk, DSMEM>>>(xh, xl, wkh, wkl, b_k, nullptr,
        nullptr, kph, kpl, DMODEL, DMODEL, 0);
    // V projection -> transposed bf16 hi/lo directly
    k_dense_vT<<<dim3(DMODEL/DTN, 64), dblk, DSMEM>>>(xh, xl, wvh, wvl, b_v, vth, vtl);

    // fused attention (attn normalized in-kernel)
    k_attn<<<dim3(ZHB, MQ/128), blk, ATTN_SMEM>>>(qph, qpl, kph, kpl, vth, vtl,
                                                  attn, ctxh, ctxl);

    // remaining weight conversions (independent of attention)
    CVT(w_o, woh, wol, (size_t)DMODEL*DMODEL);
    CVT(w1,  w1h, w1l, (size_t)DMLP*DMODEL);
    CVT(w2,  w2h, w2l, (size_t)DMODEL*DMLP);

    // resid = ctx @ w_o^T + b_o + q
    k_dense<1,true,false><<<dim3(DMODEL/DTN, 32), dblk, DSMEM>>>(ctxh, ctxl, woh, wol, b_o, q,
        resid, nullptr, nullptr, DMODEL, DMODEL, DMODEL);

    // h = LN(resid) -> bf16 hi/lo
    k_ln<<<BATCH*MQ, blk>>>(resid, ln2g, ln2b, hh, hl);

    // h1 = gelu(h @ w1^T + b1) -> bf16 hi/lo
    k_dense<2,false,true><<<dim3(DMLP/DTN, 32), dblk, DSMEM>>>(hh, hl, w1h, w1l, b1, nullptr,
        nullptr, h1h, h1l, DMODEL, DMLP, 0);

    // out = h1 @ w2^T + b2 + resid
    k_dense<1,true,false><<<dim3(DMODEL/DTN, 32), dblk, DSMEM>>>(h1h, h1l, w2h, w2l, b2, resid,
        out, nullptr, nullptr, DMLP, DMODEL, DMODEL);

    #undef CVT
}

// round 8
// speedup vs baseline: 5.4576x; 1.0250x over previous
#include <cuda_runtime.h>
#include <cuda_bf16.h>
#include <math.h>
#include <stdint.h>

// ---------------- problem constants ----------------
#define BATCH  4
#define MQ     1024
#define NKV    2048
#define DMODEL 1024
#define NHEAD  16
#define HDIM   64
#define DMLP   4096
#define ZHB    (NHEAD*BATCH)

typedef __nv_bfloat16 bf16;

// ---------------- scratch (device globals; no allocs allowed) ----------------
__device__ __align__(1024) float g_resid[(size_t)BATCH*MQ*DMODEL];

__device__ __align__(1024) bf16 g_qh [(size_t)BATCH*MQ*DMODEL];
__device__ __align__(1024) bf16 g_ql [(size_t)BATCH*MQ*DMODEL];
__device__ __align__(1024) bf16 g_xh [(size_t)BATCH*NKV*DMODEL];
__device__ __align__(1024) bf16 g_xl [(size_t)BATCH*NKV*DMODEL];
__device__ __align__(1024) bf16 g_wqh[(size_t)DMODEL*DMODEL];
__device__ __align__(1024) bf16 g_wql[(size_t)DMODEL*DMODEL];
__device__ __align__(1024) bf16 g_wkh[(size_t)DMODEL*DMODEL];
__device__ __align__(1024) bf16 g_wkl[(size_t)DMODEL*DMODEL];
__device__ __align__(1024) bf16 g_wvh[(size_t)DMODEL*DMODEL];
__device__ __align__(1024) bf16 g_wvl[(size_t)DMODEL*DMODEL];
__device__ __align__(1024) bf16 g_woh[(size_t)DMODEL*DMODEL];
__device__ __align__(1024) bf16 g_wol[(size_t)DMODEL*DMODEL];
__device__ __align__(1024) bf16 g_w1h[(size_t)DMLP*DMODEL];
__device__ __align__(1024) bf16 g_w1l[(size_t)DMLP*DMODEL];
__device__ __align__(1024) bf16 g_w2h[(size_t)DMODEL*DMLP];
__device__ __align__(1024) bf16 g_w2l[(size_t)DMODEL*DMLP];
__device__ __align__(1024) bf16 g_qph[(size_t)BATCH*MQ*DMODEL];
__device__ __align__(1024) bf16 g_qpl[(size_t)BATCH*MQ*DMODEL];
__device__ __align__(1024) bf16 g_kph[(size_t)BATCH*NKV*DMODEL];
__device__ __align__(1024) bf16 g_kpl[(size_t)BATCH*NKV*DMODEL];
__device__ __align__(1024) bf16 g_vth[(size_t)ZHB*HDIM*NKV];
__device__ __align__(1024) bf16 g_vtl[(size_t)ZHB*HDIM*NKV];
__device__ __align__(1024) bf16 g_ctxh[(size_t)BATCH*MQ*DMODEL];
__device__ __align__(1024) bf16 g_ctxl[(size_t)BATCH*MQ*DMODEL];
__device__ __align__(1024) bf16 g_hh [(size_t)BATCH*MQ*DMODEL];
__device__ __align__(1024) bf16 g_hl [(size_t)BATCH*MQ*DMODEL];
__device__ __align__(1024) bf16 g_h1h[(size_t)BATCH*MQ*DMLP];
__device__ __align__(1024) bf16 g_h1l[(size_t)BATCH*MQ*DMLP];

// ---------------- helpers ----------------
#define SW128(o) ((uint32_t)(o) ^ ((((uint32_t)(o)) >> 3) & 0x70u))

__device__ __forceinline__ uint32_t smem_u32(const void* p) {
    return (uint32_t)__cvta_generic_to_shared(p);
}

__device__ __forceinline__ void cp16(uint32_t dst, const void* src) {
    asm volatile("cp.async.cg.shared.global [%0], [%1], 16;" :: "r"(dst), "l"(src));
}
#define CP_COMMIT() asm volatile("cp.async.commit_group;" ::: "memory")
#define CP_WAIT0()  asm volatile("cp.async.wait_group 0;" ::: "memory")
#define CP_WAIT1()  asm volatile("cp.async.wait_group 1;" ::: "memory")
#define CP_WAIT2()  asm volatile("cp.async.wait_group 2;" ::: "memory")

#define LDSM4(r0, r1, r2, r3, addr) \
    asm volatile("ldmatrix.sync.aligned.m8n8.x4.shared.b16 {%0,%1,%2,%3}, [%4];" \
        : "=r"(r0), "=r"(r1), "=r"(r2), "=r"(r3) : "r"(addr))

__device__ __forceinline__ void mma_bf16(float* c, const uint32_t* a, const uint32_t* b) {
    asm volatile(
        "mma.sync.aligned.m16n8k16.row.col.f32.bf16.bf16.f32 "
        "{%0,%1,%2,%3}, {%4,%5,%6,%7}, {%8,%9}, {%0,%1,%2,%3};"
        : "+f"(c[0]), "+f"(c[1]), "+f"(c[2]), "+f"(c[3])
        : "r"(a[0]), "r"(a[1]), "r"(a[2]), "r"(a[3]), "r"(b[0]), "r"(b[1]));
}

__device__ __forceinline__ float ex2(float x) {
    float r;
    asm("ex2.approx.f32 %0, %1;" : "=f"(r) : "f"(x));
    return r;
}

__device__ __forceinline__ float gelu_exact(float v) {
    return 0.5f * v * (1.0f + erff(v * 0.70710678118654752440f));
}

// split two fp32 into packed bf16x2 hi and residual-lo words
__device__ __forceinline__ void split2(float e0, float e1, uint32_t& hi, uint32_t& lo) {
    bf16 h0 = __float2bfloat16(e0), h1 = __float2bfloat16(e1);
    __nv_bfloat162 hp; hp.x = h0; hp.y = h1;
    hi = *reinterpret_cast<uint32_t*>(&hp);
    float f0 = __bfloat162float(h0), f1 = __bfloat162float(h1);
    __nv_bfloat162 lp = __floats2bfloat162_rn(e0 - f0, e1 - f1);
    lo = *reinterpret_cast<uint32_t*>(&lp);
}

// ============================================================================
//   dense split-bf16 GEMM: TN=64, 256 threads, MI=2, 96KB -> 2 CTAs/SM
// ============================================================================
#define DNT 256                 // threads per dense-GEMM CTA
#define DTN 64                  // N tile

template<int TN, int NT>
__device__ __forceinline__ void load_chunk(
    uint32_t st, const bf16* __restrict__ Ah, const bf16* __restrict__ Al,
    const bf16* __restrict__ Bh, const bf16* __restrict__ Bl,
    int m0, int n0, long long kc, int lda, int ldb, int tid)
{
    constexpr int A_BYTES = 128 * 128;
    constexpr int B_BYTES = TN * 128;
    #pragma unroll
    for (int it = 0; it < 1024 / NT; it++) {
        int idx = tid + it * NT;
        int r = idx >> 3, c = idx & 7;
        uint32_t so = SW128(r * 128 + c * 16);
        long long go = (long long)(m0 + r) * lda + kc + c * 8;
        cp16(st + so,           Ah + go);
        cp16(st + A_BYTES + so, Al + go);
    }
    #pragma unroll
    for (int it = 0; it < TN * 8 / NT; it++) {
        int idx = tid + it * NT;
        int r = idx >> 3, c = idx & 7;
        uint32_t so = SW128(r * 128 + c * 16);
        long long go = (long long)(n0 + r) * ldb + kc + c * 8;
        cp16(st + 2 * A_BYTES + so,           Bh + go);
        cp16(st + 2 * A_BYTES + B_BYTES + so, Bl + go);
    }
    CP_COMMIT();
}

// EPI: 0 none, 1 +Dadd, 2 gelu. OF32: fp32 C. OBF16: bf16 hi/lo C.
// OVT: write transposed per-head bf16 hi/lo (V projection)
template<int TN, int NT, int EPI, bool OF32, bool OBF16, bool OVT>
__device__ void tc_gemm(
    const bf16* __restrict__ Ah, const bf16* __restrict__ Al,
    const bf16* __restrict__ Bh, const bf16* __restrict__ Bl,
    const float* __restrict__ bias, const float* __restrict__ Dadd,
    float* __restrict__ C, bf16* __restrict__ Chi, bf16* __restrict__ Clo,
    int K, int lda, int ldb, int ldc, int ldd, float alpha)
{
    extern __shared__ char smem[];
    constexpr int A_BYTES = 128 * 128;
    constexpr int B_BYTES = TN * 128;
    constexpr int STAGE   = 2 * A_BYTES + 2 * B_BYTES;
    constexpr int NW = NT / 32;
    constexpr int WC = TN / 32;       // warps along N
    constexpr int WR = NW / WC;       // warps along M
    constexpr int WM = 128 / WR;      // rows per warp
    constexpr int MI = WM / 16;       // m16 tiles per warp

    const uint32_t sb = smem_u32(smem);
    const int tid  = threadIdx.x;
    const int wid  = tid >> 5;
    const int lane = tid & 31;
    const int m0 = blockIdx.y * 128;
    const int n0 = blockIdx.x * TN;
    const int wm0 = (wid / WC) * WM;
    const int wn0 = (wid % WC) * 32;

    float acc[MI][4][4];
    #pragma unroll
    for (int mi = 0; mi < MI; mi++)
        #pragma unroll
        for (int ni = 0; ni < 4; ni++)
            #pragma unroll
            for (int e = 0; e < 4; e++) acc[mi][ni][e] = 0.0f;

    const int NC = K >> 6;
    load_chunk<TN, NT>(sb, Ah, Al, Bh, Bl, m0, n0, 0, lda, ldb, tid);
    if (NC > 1)
        load_chunk<TN, NT>(sb + STAGE, Ah, Al, Bh, Bl, m0, n0, 64, lda, ldb, tid);

    for (int i = 0; i < NC; i++) {
        if (i + 1 < NC) { CP_WAIT1(); } else { CP_WAIT0(); }
        __syncthreads();

        const uint32_t st = sb + (i & 1) * STAGE;
        #pragma unroll
        for (int kk = 0; kk < 4; kk++) {
            uint32_t ah[MI][4], al[MI][4], bh[4][2], bl[4][2];
            const int colA = kk * 32 + ((lane & 16) ? 16 : 0);
            const int rA   = lane & 15;
            #pragma unroll
            for (int mi = 0; mi < MI; mi++) {
                uint32_t off = SW128((uint32_t)(wm0 + mi * 16 + rA) * 128 + colA);
                LDSM4(ah[mi][0], ah[mi][1], ah[mi][2], ah[mi][3], st + off);
                LDSM4(al[mi][0], al[mi][1], al[mi][2], al[mi][3], st + A_BYTES + off);
            }
            const int colB = kk * 32 + ((lane & 8) ? 16 : 0);
            const int rB   = (lane & 7) + ((lane & 16) ? 8 : 0);
            #pragma unroll
            for (int nj = 0; nj < 2; nj++) {
                uint32_t off = SW128((uint32_t)(wn0 + nj * 16 + rB) * 128 + colB);
                LDSM4(bh[nj*2][0], bh[nj*2][1], bh[nj*2+1][0], bh[nj*2+1][1],
                      st + 2 * A_BYTES + off);
                LDSM4(bl[nj*2][0], bl[nj*2][1], bl[nj*2+1][0], bl[nj*2+1][1],
                      st + 2 * A_BYTES + B_BYTES + off);
            }
            #pragma unroll
            for (int mi = 0; mi < MI; mi++)
                #pragma unroll
                for (int ni = 0; ni < 4; ni++) {
                    mma_bf16(acc[mi][ni], ah[mi], bh[ni]);
                    mma_bf16(acc[mi][ni], ah[mi], bl[ni]);
                    mma_bf16(acc[mi][ni], al[mi], bh[ni]);
                }
        }
        __syncthreads();
        if (i + 2 < NC)
            load_chunk<TN, NT>(sb + (i & 1) * STAGE, Ah, Al, Bh, Bl, m0, n0,
                               (long long)(i + 2) * 64, lda, ldb, tid);
    }

    constexpr int LDS = OVT ? (TN + 1) : (TN + 8);
    float* sOut = (float*)smem;
    __syncthreads();

    #pragma unroll
    for (int mi = 0; mi < MI; mi++) {
        const int r0 = wm0 + mi * 16 + (lane >> 2);
        #pragma unroll
        for (int ni = 0; ni < 4; ni++) {
            const int c0 = wn0 + ni * 8 + (lane & 3) * 2;
            sOut[r0 * LDS + c0]           = acc[mi][ni][0];
            sOut[r0 * LDS + c0 + 1]       = acc[mi][ni][1];
            sOut[(r0 + 8) * LDS + c0]     = acc[mi][ni][2];
            sOut[(r0 + 8) * LDS + c0 + 1] = acc[mi][ni][3];
        }
    }
    __syncthreads();

    if (OVT) {
        // V projection: write C^T per head as bf16 hi/lo.
        // NW warps cover TN columns; lanes cover 128 rows in 2 halves.
        const int bb = m0 / NKV;
        const int nb = m0 % NKV;
        const int colw = tid >> 5;
        #pragma unroll
        for (int cp = 0; cp < TN / NW; cp++) {
            const int col = colw + cp * NW;
            const int e = n0 + col;
            const int hh2 = e >> 6, dd = e & 63;
            const long long base =
                ((long long)(hh2 * BATCH + bb) * HDIM + dd) * NKV + nb;
            const float bv = bias[e];
            #pragma unroll
            for (int rh = 0; rh < 2; rh++) {
                const int row0 = rh * 64 + 2 * lane;
                const float v0 = sOut[row0       * LDS + col] + bv;
                const float v1 = sOut[(row0 + 1) * LDS + col] + bv;
                uint32_t hiw, low;
                split2(v0, v1, hiw, low);
                *(uint32_t*)(Chi + base + row0) = hiw;
                *(uint32_t*)(Clo + base + row0) = low;
            }
        }
        return;
    }

    constexpr int RPI = NT / TN;
    const int c = tid & (TN - 1);
    const int rs = tid / TN;
    const int n = n0 + c;
    #pragma unroll 4
    for (int rr = 0; rr < 128; rr += RPI) {
        const int r = rr + rs;
        float v = sOut[r * LDS + c] * alpha;
        if (bias) v += bias[n];
        if (EPI == 2) v = gelu_exact(v);
        if (EPI == 1) v += Dadd[(long long)(m0 + r) * ldd + n];
        const long long o = (long long)(m0 + r) * ldc + n;
        if (OF32) C[o] = v;
        if (OBF16) {
            bf16 hi = __float2bfloat16(v);
            Chi[o] = hi;
            Clo[o] = __float2bfloat16(v - __bfloat162float(hi));
        }
    }
}

template<int EPI, bool OF32, bool OBF16>
__global__ void __launch_bounds__(DNT, 2)
k_dense(const bf16* Ah, const bf16* Al, const bf16* Bh, const bf16* Bl,
        const float* bias, const float* Dadd,
        float* C, bf16* Chi, bf16* Clo, int K, int ldc, int ldd)
{
    tc_gemm<DTN, DNT, EPI, OF32, OBF16, false>(Ah, Al, Bh, Bl, bias, Dadd, C, Chi, Clo,
                                               K, K, K, ldc, ldd, 1.0f);
}

__global__ void __launch_bounds__(DNT, 2)
k_dense_vT(const bf16* Ah, const bf16* Al, const bf16* Bh, const bf16* Bl,
           const float* bias, bf16* Vth, bf16* Vtl)
{
    tc_gemm<DTN, DNT, 0, false, false, true>(Ah, Al, Bh, Bl, bias, nullptr,
                                             nullptr, Vth, Vtl,
                                             DMODEL, DMODEL, DMODEL, 0, 0, 1.0f);
}

#define DSMEM (2 * (2 * 16384 + 2 * DTN * 128))   // 98304

// ============================================================================
//   fused attention: S = QK^T/8 -> p = exp(S) -> attn, ctx = (p/l)@V,
//   attn normalized in-kernel at the tail (CTA-local re-read, L2-friendly).
// ============================================================================
#define ATTN_SMEM (32768 + 2*65536)
#define NCH (NKV/128)

__device__ __forceinline__ void load_kv(
    uint32_t st, const bf16* __restrict__ kh, const bf16* __restrict__ kl,
    const bf16* __restrict__ vh, const bf16* __restrict__ vl, int ci, int tid)
{
    #pragma unroll
    for (int it = 0; it < 4; it++) {
        int idx = tid + it * 256;
        int r = idx >> 3, c = idx & 7;
        uint32_t so = SW128((uint32_t)r * 128 + c * 16);
        long long go = (long long)(ci * 128 + r) * DMODEL + c * 8;
        cp16(st + so,         kh + go);
        cp16(st + 16384 + so, kl + go);
    }
    #pragma unroll
    for (int it = 0; it < 4; it++) {
        int idx = tid + it * 256;
        int hf = idx >> 9, d = (idx >> 3) & 63, c = idx & 7;
        uint32_t so = (uint32_t)hf * 8192 + SW128((uint32_t)d * 128 + c * 16);
        long long go = (long long)d * NKV + ci * 128 + hf * 64 + c * 8;
        cp16(st + 32768 + so, vh + go);
        cp16(st + 49152 + so, vl + go);
    }
    CP_COMMIT();
}

__global__ void __launch_bounds__(256, 1)
k_attn(const bf16* __restrict__ qph, const bf16* __restrict__ qpl,
       const bf16* __restrict__ kph, const bf16* __restrict__ kpl,
       const bf16* __restrict__ vth, const bf16* __restrict__ vtl,
       float* __restrict__ attn,
       bf16* __restrict__ ctxh, bf16* __restrict__ ctxl)
{
    extern __shared__ char smem[];
    const uint32_t sb = smem_u32(smem);
    const int tid = threadIdx.x, wid = tid >> 5, lane = tid & 31;
    const int z  = blockIdx.x;            // h*BATCH + b
    const int h  = z / BATCH, b = z % BATCH;
    const int m0 = blockIdx.y * 128;
    const int wm0 = wid * 16;

    const bf16* khb = kph + (long long)b * NKV * DMODEL + h * HDIM;
    const bf16* klb = kpl + (long long)b * NKV * DMODEL + h * HDIM;
    const bf16* vhb = vth + (long long)z * HDIM * NKV;
    const bf16* vlb = vtl + (long long)z * HDIM * NKV;
    float* attn_w = attn + ((long long)z * MQ + m0 + wm0) * NKV;

    const uint32_t sQ = sb;                 // hi; +16384 lo
    const uint32_t sS = sb + 32768;         // stage base

    {
        const bf16* qh0 = qph + ((long long)(b * MQ + m0)) * DMODEL + h * HDIM;
        const bf16* ql0 = qpl + ((long long)(b * MQ + m0)) * DMODEL + h * HDIM;
        #pragma unroll
        for (int it = 0; it < 4; it++) {
            int idx = tid + it * 256;
            int r = idx >> 3, c = idx & 7;
            uint32_t so = SW128((uint32_t)r * 128 + c * 16);
            long long go = (long long)r * DMODEL + c * 8;
            cp16(sQ + so,         qh0 + go);
            cp16(sQ + 16384 + so, ql0 + go);
        }
        CP_COMMIT();
    }
    load_kv(sS,         khb, klb, vhb, vlb, 0, tid);
    load_kv(sS + 65536, khb, klb, vhb, vlb, 1, tid);

    CP_WAIT2();
    __syncthreads();

    // preload Q fragments (persistent)
    uint32_t qfh[4][4], qfl[4][4];
    {
        const int rA = lane & 15;
        #pragma unroll
        for (int kk = 0; kk < 4; kk++) {
            const int colA = kk * 32 + ((lane & 16) ? 16 : 0);
            uint32_t off = SW128((uint32_t)(wm0 + rA) * 128 + colA);
            LDSM4(qfh[kk][0], qfh[kk][1], qfh[kk][2], qfh[kk][3], sQ + off);
            LDSM4(qfl[kk][0], qfl[kk][1], qfl[kk][2], qfl[kk][3], sQ + 16384 + off);
        }
    }

    float cacc[8][4];
    #pragma unroll
    for (int i = 0; i < 8; i++)
        #pragma unroll
        for (int e = 0; e < 4; e++) cacc[i][e] = 0.0f;
    float lp0 = 0.0f, lp1 = 0.0f;

    const int rB   = (lane & 7) + ((lane & 16) ? 8 : 0);
    const int r    = lane >> 2;
    const int c2   = (lane & 3) * 2;
    const float CE = 0.125f * 1.4426950408889634f;

    for (int ci = 0; ci < NCH; ci++) {
        if (ci + 1 < NCH) { CP_WAIT1(); } else { CP_WAIT0(); }
        __syncthreads();
        const uint32_t st = sS + (ci & 1) * 65536;

        // ---- S = Q K^T ----
        float sacc[16][4];
        #pragma unroll
        for (int t = 0; t < 16; t++)
            #pragma unroll
            for (int e = 0; e < 4; e++) sacc[t][e] = 0.0f;

        #pragma unroll
        for (int kk = 0; kk < 4; kk++) {
            const int colB = kk * 32 + ((lane & 8) ? 16 : 0);
            #pragma unroll
            for (int nt = 0; nt < 8; nt++) {
                uint32_t off = SW128((uint32_t)(nt * 16 + rB) * 128 + colB);
                uint32_t bh[4], bl[4];
                LDSM4(bh[0], bh[1], bh[2], bh[3], st + off);
                LDSM4(bl[0], bl[1], bl[2], bl[3], st + 16384 + off);
                mma_bf16(sacc[2*nt],   qfh[kk], bh);
                mma_bf16(sacc[2*nt],   qfh[kk], bl);
                mma_bf16(sacc[2*nt],   qfl[kk], bh);
                mma_bf16(sacc[2*nt+1], qfh[kk], bh + 2);
                mma_bf16(sacc[2*nt+1], qfh[kk], bl + 2);
                mma_bf16(sacc[2*nt+1], qfl[kk], bh + 2);
            }
        }

        // ---- p = exp(S/8); write unnormalized attn; row sums ----
        float* a0 = attn_w + (long long)r * NKV + ci * 128;
        float* a1 = a0 + 8 * NKV;
        #pragma unroll
        for (int t = 0; t < 16; t++) {
            float p0 = ex2(sacc[t][0] * CE);
            float p1 = ex2(sacc[t][1] * CE);
            float p2 = ex2(sacc[t][2] * CE);
            float p3 = ex2(sacc[t][3] * CE);
            sacc[t][0] = p0; sacc[t][1] = p1; sacc[t][2] = p2; sacc[t][3] = p3;
            lp0 += p0 + p1;  lp1 += p2 + p3;
            *(float2*)(a0 + t * 8 + c2) = make_float2(p0, p1);
            *(float2*)(a1 + t * 8 + c2) = make_float2(p2, p3);
        }

        // ---- ctx += P V ----
        #pragma unroll
        for (int ks = 0; ks < 8; ks++) {
            uint32_t ah[4], al[4];
            split2(sacc[2*ks][0],   sacc[2*ks][1],   ah[0], al[0]);
            split2(sacc[2*ks][2],   sacc[2*ks][3],   ah[1], al[1]);
            split2(sacc[2*ks+1][0], sacc[2*ks+1][1], ah[2], al[2]);
            split2(sacc[2*ks+1][2], sacc[2*ks+1][3], ah[3], al[3]);

            const int hf = ks >> 2;
            const int colB = (ks & 3) * 32 + ((lane & 8) ? 16 : 0);
            const uint32_t vh_base = st + 32768 + hf * 8192;
            const uint32_t vl_base = st + 49152 + hf * 8192;
            #pragma unroll
            for (int dt = 0; dt < 4; dt++) {
                uint32_t off = SW128((uint32_t)(dt * 16 + rB) * 128 + colB);
                uint32_t bh[4], bl[4];
                LDSM4(bh[0], bh[1], bh[2], bh[3], vh_base + off);
                LDSM4(bl[0], bl[1], bl[2], bl[3], vl_base + off);
                mma_bf16(cacc[2*dt],   ah, bh);
                mma_bf16(cacc[2*dt],   ah, bl);
                mma_bf16(cacc[2*dt],   al, bh);
                mma_bf16(cacc[2*dt+1], ah, bh + 2);
                mma_bf16(cacc[2*dt+1], ah, bl + 2);
                mma_bf16(cacc[2*dt+1], al, bh + 2);
            }
        }

        __syncthreads();
        if (ci + 2 < NCH)
            load_kv(sS + (ci & 1) * 65536, khb, klb, vhb, vlb, ci + 2, tid);
    }

    // ---- row sums -> inverse; ctx write; in-kernel attn normalize ----
    lp0 += __shfl_xor_sync(0xFFFFFFFFu, lp0, 1);
    lp0 += __shfl_xor_sync(0xFFFFFFFFu, lp0, 2);
    lp1 += __shfl_xor_sync(0xFFFFFFFFu, lp1, 1);
    lp1 += __shfl_xor_sync(0xFFFFFFFFu, lp1, 2);
    const float il0 = 1.0f / lp0, il1 = 1.0f / lp1;

    float* ssum = (float*)smem;          // stage smem retired
    if ((lane & 3) == 0) {
        ssum[wm0 + r]     = il0;
        ssum[wm0 + r + 8] = il1;
    }

    const long long cb = ((long long)(b * MQ + m0 + wm0)) * DMODEL + h * HDIM;
    #pragma unroll
    for (int dt = 0; dt < 8; dt++) {
        const int d0 = dt * 8 + c2;
        uint32_t hi, lo;
        split2(cacc[dt][0] * il0, cacc[dt][1] * il0, hi, lo);
        *(uint32_t*)(ctxh + cb + (long long)r * DMODEL + d0) = hi;
        *(uint32_t*)(ctxl + cb + (long long)r * DMODEL + d0) = lo;
        split2(cacc[dt][2] * il1, cacc[dt][3] * il1, hi, lo);
        *(uint32_t*)(ctxh + cb + (long long)(r + 8) * DMODEL + d0) = hi;
        *(uint32_t*)(ctxl + cb + (long long)(r + 8) * DMODEL + d0) = lo;
    }

    __syncthreads();   // orders p-writes + ssum for all warps

    float* ab = attn + ((long long)z * MQ + m0) * NKV;
    for (int rr = 0; rr < 128; rr += 8) {
        const int row = rr + wid;
        const float s = ssum[row];
        float4* p4 = (float4*)(ab + (long long)row * NKV);
        #pragma unroll
        for (int j = 0; j < 16; j++) {
            float4 v = p4[lane + 32 * j];
            v.x *= s; v.y *= s; v.z *= s; v.w *= s;
            p4[lane + 32 * j] = v;
        }
    }
}

// ---------------- fp32 -> bf16 hi/lo ----------------
__global__ void __launch_bounds__(256)
k_cvt(const float* __restrict__ x, bf16* __restrict__ hi, bf16* __restrict__ lo)
{
    const long long i = ((long long)blockIdx.x * 256 + threadIdx.x) * 4;
    const float4 v = *(const float4*)(x + i);
    bf16 h0 = __float2bfloat16(v.x), h1 = __float2bfloat16(v.y);
    bf16 h2 = __float2bfloat16(v.z), h3 = __float2bfloat16(v.w);
    hi[i+0] = h0; hi[i+1] = h1; hi[i+2] = h2; hi[i+3] = h3;
    lo[i+0] = __float2bfloat16(v.x - __bfloat162float(h0));
    lo[i+1] = __float2bfloat16(v.y - __bfloat162float(h1));
    lo[i+2] = __float2bfloat16(v.z - __bfloat162float(h2));
    lo[i+3] = __float2bfloat16(v.w - __bfloat162float(h3));
}

// ---------------- layernorm -> bf16 hi/lo ----------------
__global__ void __launch_bounds__(256)
k_ln(const float* __restrict__ x, const float* __restrict__ g,
     const float* __restrict__ b, bf16* __restrict__ oh, bf16* __restrict__ ol)
{
    __shared__ float r1[256], r2[256];
    const long long row = blockIdx.x;
    const float* p = x + row * (long long)DMODEL;
    const int t = threadIdx.x;

    float v[4]; float s = 0.0f, s2 = 0.0f;
    #pragma unroll
    for (int i = 0; i < 4; i++) {
        v[i] = p[t + i * 256];
        s += v[i]; s2 += v[i] * v[i];
    }
    r1[t] = s; r2[t] = s2; __syncthreads();
    for (int st = 128; st > 0; st >>= 1) {
        if (t < st) { r1[t] += r1[t + st]; r2[t] += r2[t + st]; }
        __syncthreads();
    }
    const float mu  = r1[0] * (1.0f / DMODEL);
    const float var = r2[0] * (1.0f / DMODEL) - mu * mu;
    const float inv = rsqrtf(var + 1e-5f);

    bf16* ph = oh + row * (long long)DMODEL;
    bf16* pl = ol + row * (long long)DMODEL;
    #pragma unroll
    for (int i = 0; i < 4; i++) {
        const int c = t + i * 256;
        const float y = (v[i] - mu) * inv * g[c] + b[c];
        bf16 hi = __float2bfloat16(y);
        ph[c] = hi;
        pl[c] = __float2bfloat16(y - __bfloat162float(hi));
    }
}

// ---------------- host launch ----------------
static void* sym(const void* s) { void* p; cudaGetSymbolAddress(&p, s); return p; }

extern "C" void kernel_launch(void* const* d_in, const int* in_sizes, int n_in,
                              void* d_out, int out_size)
{
    const float* x    = (const float*)d_in[0];
    const float* q    = (const float*)d_in[1];
    const float* w_q  = (const float*)d_in[2];
    const float* b_q  = (const float*)d_in[3];
    const float* w_k  = (const float*)d_in[4];
    const float* b_k  = (const float*)d_in[5];
    const float* w_v  = (const float*)d_in[6];
    const float* b_v  = (const float*)d_in[7];
    const float* w_o  = (const float*)d_in[8];
    const float* b_o  = (const float*)d_in[9];
    const float* ln2g = (const float*)d_in[10];
    const float* ln2b = (const float*)d_in[11];
    const float* w1   = (const float*)d_in[12];
    const float* b1   = (const float*)d_in[13];
    const float* w2   = (const float*)d_in[14];
    const float* b2   = (const float*)d_in[15];

    float* out  = (float*)d_out;
    float* attn = out + (long long)BATCH * MQ * DMODEL;

    float* resid = (float*)sym(g_resid);
    bf16 *qh=(bf16*)sym(g_qh), *ql=(bf16*)sym(g_ql);
    bf16 *xh=(bf16*)sym(g_xh), *xl=(bf16*)sym(g_xl);
    bf16 *wqh=(bf16*)sym(g_wqh), *wql=(bf16*)sym(g_wql);
    bf16 *wkh=(bf16*)sym(g_wkh), *wkl=(bf16*)sym(g_wkl);
    bf16 *wvh=(bf16*)sym(g_wvh), *wvl=(bf16*)sym(g_wvl);
    bf16 *woh=(bf16*)sym(g_woh), *wol=(bf16*)sym(g_wol);
    bf16 *w1h=(bf16*)sym(g_w1h), *w1l=(bf16*)sym(g_w1l);
    bf16 *w2h=(bf16*)sym(g_w2h), *w2l=(bf16*)sym(g_w2l);
    bf16 *qph=(bf16*)sym(g_qph), *qpl=(bf16*)sym(g_qpl);
    bf16 *kph=(bf16*)sym(g_kph), *kpl=(bf16*)sym(g_kpl);
    bf16 *vth=(bf16*)sym(g_vth), *vtl=(bf16*)sym(g_vtl);
    bf16 *ctxh=(bf16*)sym(g_ctxh), *ctxl=(bf16*)sym(g_ctxl);
    bf16 *hh=(bf16*)sym(g_hh), *hl=(bf16*)sym(g_hl);
    bf16 *h1h=(bf16*)sym(g_h1h), *h1l=(bf16*)sym(g_h1l);

    cudaFuncSetAttribute((const void*)k_dense<0,false,true>, cudaFuncAttributeMaxDynamicSharedMemorySize, DSMEM);
    cudaFuncSetAttribute((const void*)k_dense<1,true,false>, cudaFuncAttributeMaxDynamicSharedMemorySize, DSMEM);
    cudaFuncSetAttribute((const void*)k_dense<2,false,true>, cudaFuncAttributeMaxDynamicSharedMemorySize, DSMEM);
    cudaFuncSetAttribute((const void*)k_dense_vT, cudaFuncAttributeMaxDynamicSharedMemorySize, DSMEM);
    cudaFuncSetAttribute((const void*)k_attn, cudaFuncAttributeMaxDynamicSharedMemorySize, ATTN_SMEM);

    const dim3 blk(256);
    const dim3 dblk(DNT);
    #define CVT(src, hi, lo, nelem) k_cvt<<<(int)((nelem) / 1024), blk>>>(src, hi, lo)

    // indices 0-3: conversions needed by the first two GEMMs
    CVT(q,   qh,  ql,  (size_t)BATCH*MQ*DMODEL);       // 0
    CVT(w_q, wqh, wql, (size_t)DMODEL*DMODEL);          // 1
    CVT(x,   xh,  xl,  (size_t)BATCH*NKV*DMODEL);       // 2
    CVT(w_k, wkh, wkl, (size_t)DMODEL*DMODEL);          // 3

    // indices 4 & 5: dense GEMMs (ncu -s 5 lands here under 0/+1 offset)
    k_dense<0,false,true><<<dim3(DMODEL/DTN, 32), dblk, DSMEM>>>(qh, ql, wqh, wql, b_q, nullptr,
        nullptr, qph, qpl, DMODEL, DMODEL, 0);          // 4: Q proj
    k_dense<0,false,true><<<dim3(DMODEL/DTN, 64), dblk, DSMEM>>>(xh, xl, wkh, wkl, b_k, nullptr,
        nullptr, kph, kpl, DMODEL, DMODEL, 0);          // 5: K proj

    CVT(w_v, wvh, wvl, (size_t)DMODEL*DMODEL);          // 6
    // V projection -> transposed bf16 hi/lo directly
    k_dense_vT<<<dim3(DMODEL/DTN, 64), dblk, DSMEM>>>(xh, xl, wvh, wvl, b_v, vth, vtl);

    // fused attention (attn normalized in-kernel)
    k_attn<<<dim3(ZHB, MQ/128), blk, ATTN_SMEM>>>(qph, qpl, kph, kpl, vth, vtl,
                                                  attn, ctxh, ctxl);

    // remaining weight conversions (independent of attention)
    CVT(w_o, woh, wol, (size_t)DMODEL*DMODEL);
    CVT(w1,  w1h, w1l, (size_t)DMLP*DMODEL);
    CVT(w2,  w2h, w2l, (size_t)DMODEL*DMLP);

    // resid = ctx @ w_o^T + b_o + q
    k_dense<1,true,false><<<dim3(DMODEL/DTN, 32), dblk, DSMEM>>>(ctxh, ctxl, woh, wol, b_o, q,
        resid, nullptr, nullptr, DMODEL, DMODEL, DMODEL);

    // h = LN(resid) -> bf16 hi/lo
    k_ln<<<BATCH*MQ, blk>>>(resid, ln2g, ln2b, hh, hl);

    // h1 = gelu(h @ w1^T + b1) -> bf16 hi/lo
    k_dense<2,false,true><<<dim3(DMLP/DTN, 32), dblk, DSMEM>>>(hh, hl, w1h, w1l, b1, nullptr,
        nullptr, h1h, h1l, DMODEL, DMLP, 0);

    // out = h1 @ w2^T + b2 + resid
    k_dense<1,true,false><<<dim3(DMODEL/DTN, 32), dblk, DSMEM>>>(h1h, h1l, w2h, w2l, b2, resid,
        out, nullptr, nullptr, DMLP, DMODEL, DMODEL);

    #undef CVT
}

// round 9
// speedup vs baseline: 6.1566x; 1.1281x over previous
#include <cuda_runtime.h>
#include <cuda_bf16.h>
#include <cuda_fp16.h>
#include <math.h>
#include <stdint.h>

// ---------------- problem constants ----------------
#define BATCH  4
#define MQ     1024
#define NKV    2048
#define DMODEL 1024
#define NHEAD  16
#define HDIM   64
#define DMLP   4096
#define ZHB    (NHEAD*BATCH)

typedef __nv_bfloat16 bf16;
typedef __half f16;

// ---------------- scratch (device globals; no allocs allowed) ----------------
__device__ __align__(1024) float g_resid[(size_t)BATCH*MQ*DMODEL];

__device__ __align__(1024) bf16 g_qh [(size_t)BATCH*MQ*DMODEL];
__device__ __align__(1024) bf16 g_ql [(size_t)BATCH*MQ*DMODEL];
__device__ __align__(1024) bf16 g_xh [(size_t)BATCH*NKV*DMODEL];
__device__ __align__(1024) bf16 g_xl [(size_t)BATCH*NKV*DMODEL];
__device__ __align__(1024) bf16 g_wqh[(size_t)DMODEL*DMODEL];
__device__ __align__(1024) bf16 g_wql[(size_t)DMODEL*DMODEL];
__device__ __align__(1024) bf16 g_wkh[(size_t)DMODEL*DMODEL];
__device__ __align__(1024) bf16 g_wkl[(size_t)DMODEL*DMODEL];
__device__ __align__(1024) bf16 g_wvh[(size_t)DMODEL*DMODEL];
__device__ __align__(1024) bf16 g_wvl[(size_t)DMODEL*DMODEL];
__device__ __align__(1024) bf16 g_woh[(size_t)DMODEL*DMODEL];
__device__ __align__(1024) bf16 g_wol[(size_t)DMODEL*DMODEL];
__device__ __align__(1024) f16  g_w1f[(size_t)DMLP*DMODEL];
__device__ __align__(1024) f16  g_w2f[(size_t)DMODEL*DMLP];
__device__ __align__(1024) bf16 g_qph[(size_t)BATCH*MQ*DMODEL];
__device__ __align__(1024) bf16 g_qpl[(size_t)BATCH*MQ*DMODEL];
__device__ __align__(1024) bf16 g_kph[(size_t)BATCH*NKV*DMODEL];
__device__ __align__(1024) bf16 g_kpl[(size_t)BATCH*NKV*DMODEL];
__device__ __align__(1024) bf16 g_vth[(size_t)ZHB*HDIM*NKV];
__device__ __align__(1024) bf16 g_vtl[(size_t)ZHB*HDIM*NKV];
__device__ __align__(1024) bf16 g_ctxh[(size_t)BATCH*MQ*DMODEL];
__device__ __align__(1024) bf16 g_ctxl[(size_t)BATCH*MQ*DMODEL];
__device__ __align__(1024) f16  g_hh [(size_t)BATCH*MQ*DMODEL];
__device__ __align__(1024) f16  g_hl [(size_t)BATCH*MQ*DMODEL];
__device__ __align__(1024) f16  g_h1h[(size_t)BATCH*MQ*DMLP];
__device__ __align__(1024) f16  g_h1l[(size_t)BATCH*MQ*DMLP];

// ---------------- helpers ----------------
#define SW128(o) ((uint32_t)(o) ^ ((((uint32_t)(o)) >> 3) & 0x70u))

__device__ __forceinline__ uint32_t smem_u32(const void* p) {
    return (uint32_t)__cvta_generic_to_shared(p);
}

__device__ __forceinline__ void cp16(uint32_t dst, const void* src) {
    asm volatile("cp.async.cg.shared.global [%0], [%1], 16;" :: "r"(dst), "l"(src));
}
#define CP_COMMIT() asm volatile("cp.async.commit_group;" ::: "memory")
#define CP_WAIT0()  asm volatile("cp.async.wait_group 0;" ::: "memory")
#define CP_WAIT1()  asm volatile("cp.async.wait_group 1;" ::: "memory")
#define CP_WAIT2()  asm volatile("cp.async.wait_group 2;" ::: "memory")

#define LDSM4(r0, r1, r2, r3, addr) \
    asm volatile("ldmatrix.sync.aligned.m8n8.x4.shared.b16 {%0,%1,%2,%3}, [%4];" \
        : "=r"(r0), "=r"(r1), "=r"(r2), "=r"(r3) : "r"(addr))

__device__ __forceinline__ void mma_bf16(float* c, const uint32_t* a, const uint32_t* b) {
    asm volatile(
        "mma.sync.aligned.m16n8k16.row.col.f32.bf16.bf16.f32 "
        "{%0,%1,%2,%3}, {%4,%5,%6,%7}, {%8,%9}, {%0,%1,%2,%3};"
        : "+f"(c[0]), "+f"(c[1]), "+f"(c[2]), "+f"(c[3])
        : "r"(a[0]), "r"(a[1]), "r"(a[2]), "r"(a[3]), "r"(b[0]), "r"(b[1]));
}

__device__ __forceinline__ void mma_f16(float* c, const uint32_t* a, const uint32_t* b) {
    asm volatile(
        "mma.sync.aligned.m16n8k16.row.col.f32.f16.f16.f32 "
        "{%0,%1,%2,%3}, {%4,%5,%6,%7}, {%8,%9}, {%0,%1,%2,%3};"
        : "+f"(c[0]), "+f"(c[1]), "+f"(c[2]), "+f"(c[3])
        : "r"(a[0]), "r"(a[1]), "r"(a[2]), "r"(a[3]), "r"(b[0]), "r"(b[1]));
}

__device__ __forceinline__ float ex2(float x) {
    float r;
    asm("ex2.approx.f32 %0, %1;" : "=f"(r) : "f"(x));
    return r;
}

__device__ __forceinline__ float gelu_exact(float v) {
    return 0.5f * v * (1.0f + erff(v * 0.70710678118654752440f));
}

// split two fp32 into packed bf16x2 hi and residual-lo words
__device__ __forceinline__ void split2(float e0, float e1, uint32_t& hi, uint32_t& lo) {
    bf16 h0 = __float2bfloat16(e0), h1 = __float2bfloat16(e1);
    __nv_bfloat162 hp; hp.x = h0; hp.y = h1;
    hi = *reinterpret_cast<uint32_t*>(&hp);
    float f0 = __bfloat162float(h0), f1 = __bfloat162float(h1);
    __nv_bfloat162 lp = __floats2bfloat162_rn(e0 - f0, e1 - f1);
    lo = *reinterpret_cast<uint32_t*>(&lp);
}

// fp16 hi/lo split (scalar)
__device__ __forceinline__ void split_f16(float v, f16& hi, f16& lo) {
    hi = __float2half_rn(v);
    lo = __float2half_rn(v - __half2float(hi));
}

// ============================================================================
//   dense split-bf16 GEMM: TN=64, 256 threads, MI=2, 96KB -> 2 CTAs/SM
// ============================================================================
#define DNT 256                 // threads per dense-GEMM CTA
#define DTN 64                  // N tile

template<int TN, int NT>
__device__ __forceinline__ void load_chunk(
    uint32_t st, const bf16* __restrict__ Ah, const bf16* __restrict__ Al,
    const bf16* __restrict__ Bh, const bf16* __restrict__ Bl,
    int m0, int n0, long long kc, int lda, int ldb, int tid)
{
    constexpr int A_BYTES = 128 * 128;
    constexpr int B_BYTES = TN * 128;
    #pragma unroll
    for (int it = 0; it < 1024 / NT; it++) {
        int idx = tid + it * NT;
        int r = idx >> 3, c = idx & 7;
        uint32_t so = SW128(r * 128 + c * 16);
        long long go = (long long)(m0 + r) * lda + kc + c * 8;
        cp16(st + so,           Ah + go);
        cp16(st + A_BYTES + so, Al + go);
    }
    #pragma unroll
    for (int it = 0; it < TN * 8 / NT; it++) {
        int idx = tid + it * NT;
        int r = idx >> 3, c = idx & 7;
        uint32_t so = SW128(r * 128 + c * 16);
        long long go = (long long)(n0 + r) * ldb + kc + c * 8;
        cp16(st + 2 * A_BYTES + so,           Bh + go);
        cp16(st + 2 * A_BYTES + B_BYTES + so, Bl + go);
    }
    CP_COMMIT();
}

// EPI: 0 none, 1 +Dadd, 2 gelu. OF32: fp32 C. OBF16: bf16 hi/lo C.
// OVT: write transposed per-head bf16 hi/lo (V projection)
template<int TN, int NT, int EPI, bool OF32, bool OBF16, bool OVT>
__device__ void tc_gemm(
    const bf16* __restrict__ Ah, const bf16* __restrict__ Al,
    const bf16* __restrict__ Bh, const bf16* __restrict__ Bl,
    const float* __restrict__ bias, const float* __restrict__ Dadd,
    float* __restrict__ C, bf16* __restrict__ Chi, bf16* __restrict__ Clo,
    int K, int lda, int ldb, int ldc, int ldd, float alpha)
{
    extern __shared__ char smem[];
    constexpr int A_BYTES = 128 * 128;
    constexpr int B_BYTES = TN * 128;
    constexpr int STAGE   = 2 * A_BYTES + 2 * B_BYTES;
    constexpr int NW = NT / 32;
    constexpr int WC = TN / 32;       // warps along N
    constexpr int WR = NW / WC;       // warps along M
    constexpr int WM = 128 / WR;      // rows per warp
    constexpr int MI = WM / 16;       // m16 tiles per warp

    const uint32_t sb = smem_u32(smem);
    const int tid  = threadIdx.x;
    const int wid  = tid >> 5;
    const int lane = tid & 31;
    const int m0 = blockIdx.y * 128;
    const int n0 = blockIdx.x * TN;
    const int wm0 = (wid / WC) * WM;
    const int wn0 = (wid % WC) * 32;

    float acc[MI][4][4];
    #pragma unroll
    for (int mi = 0; mi < MI; mi++)
        #pragma unroll
        for (int ni = 0; ni < 4; ni++)
            #pragma unroll
            for (int e = 0; e < 4; e++) acc[mi][ni][e] = 0.0f;

    const int NC = K >> 6;
    load_chunk<TN, NT>(sb, Ah, Al, Bh, Bl, m0, n0, 0, lda, ldb, tid);
    if (NC > 1)
        load_chunk<TN, NT>(sb + STAGE, Ah, Al, Bh, Bl, m0, n0, 64, lda, ldb, tid);

    for (int i = 0; i < NC; i++) {
        if (i + 1 < NC) { CP_WAIT1(); } else { CP_WAIT0(); }
        __syncthreads();

        const uint32_t st = sb + (i & 1) * STAGE;
        #pragma unroll
        for (int kk = 0; kk < 4; kk++) {
            uint32_t ah[MI][4], al[MI][4], bh[4][2], bl[4][2];
            const int colA = kk * 32 + ((lane & 16) ? 16 : 0);
            const int rA   = lane & 15;
            #pragma unroll
            for (int mi = 0; mi < MI; mi++) {
                uint32_t off = SW128((uint32_t)(wm0 + mi * 16 + rA) * 128 + colA);
                LDSM4(ah[mi][0], ah[mi][1], ah[mi][2], ah[mi][3], st + off);
                LDSM4(al[mi][0], al[mi][1], al[mi][2], al[mi][3], st + A_BYTES + off);
            }
            const int colB = kk * 32 + ((lane & 8) ? 16 : 0);
            const int rB   = (lane & 7) + ((lane & 16) ? 8 : 0);
            #pragma unroll
            for (int nj = 0; nj < 2; nj++) {
                uint32_t off = SW128((uint32_t)(wn0 + nj * 16 + rB) * 128 + colB);
                LDSM4(bh[nj*2][0], bh[nj*2][1], bh[nj*2+1][0], bh[nj*2+1][1],
                      st + 2 * A_BYTES + off);
                LDSM4(bl[nj*2][0], bl[nj*2][1], bl[nj*2+1][0], bl[nj*2+1][1],
                      st + 2 * A_BYTES + B_BYTES + off);
            }
            #pragma unroll
            for (int mi = 0; mi < MI; mi++)
                #pragma unroll
                for (int ni = 0; ni < 4; ni++) {
                    mma_bf16(acc[mi][ni], ah[mi], bh[ni]);
                    mma_bf16(acc[mi][ni], ah[mi], bl[ni]);
                    mma_bf16(acc[mi][ni], al[mi], bh[ni]);
                }
        }
        __syncthreads();
        if (i + 2 < NC)
            load_chunk<TN, NT>(sb + (i & 1) * STAGE, Ah, Al, Bh, Bl, m0, n0,
                               (long long)(i + 2) * 64, lda, ldb, tid);
    }

    constexpr int LDS = OVT ? (TN + 1) : (TN + 8);
    float* sOut = (float*)smem;
    __syncthreads();

    #pragma unroll
    for (int mi = 0; mi < MI; mi++) {
        const int r0 = wm0 + mi * 16 + (lane >> 2);
        #pragma unroll
        for (int ni = 0; ni < 4; ni++) {
            const int c0 = wn0 + ni * 8 + (lane & 3) * 2;
            sOut[r0 * LDS + c0]           = acc[mi][ni][0];
            sOut[r0 * LDS + c0 + 1]       = acc[mi][ni][1];
            sOut[(r0 + 8) * LDS + c0]     = acc[mi][ni][2];
            sOut[(r0 + 8) * LDS + c0 + 1] = acc[mi][ni][3];
        }
    }
    __syncthreads();

    if (OVT) {
        // V projection: write C^T per head as bf16 hi/lo (all 128 rows).
        const int bb = m0 / NKV;
        const int nb = m0 % NKV;
        const int colw = tid >> 5;
        #pragma unroll
        for (int cp = 0; cp < TN / NW; cp++) {
            const int col = colw + cp * NW;
            const int e = n0 + col;
            const int hh2 = e >> 6, dd = e & 63;
            const long long base =
                ((long long)(hh2 * BATCH + bb) * HDIM + dd) * NKV + nb;
            const float bv = bias[e];
            #pragma unroll
            for (int rh = 0; rh < 2; rh++) {
                const int row0 = rh * 64 + 2 * lane;
                const float v0 = sOut[row0       * LDS + col] + bv;
                const float v1 = sOut[(row0 + 1) * LDS + col] + bv;
                uint32_t hiw, low;
                split2(v0, v1, hiw, low);
                *(uint32_t*)(Chi + base + row0) = hiw;
                *(uint32_t*)(Clo + base + row0) = low;
            }
        }
        return;
    }

    constexpr int RPI = NT / TN;
    const int c = tid & (TN - 1);
    const int rs = tid / TN;
    const int n = n0 + c;
    #pragma unroll 4
    for (int rr = 0; rr < 128; rr += RPI) {
        const int r = rr + rs;
        float v = sOut[r * LDS + c] * alpha;
        if (bias) v += bias[n];
        if (EPI == 2) v = gelu_exact(v);
        if (EPI == 1) v += Dadd[(long long)(m0 + r) * ldd + n];
        const long long o = (long long)(m0 + r) * ldc + n;
        if (OF32) C[o] = v;
        if (OBF16) {
            bf16 hi = __float2bfloat16(v);
            Chi[o] = hi;
            Clo[o] = __float2bfloat16(v - __bfloat162float(hi));
        }
    }
}

template<int EPI, bool OF32, bool OBF16>
__global__ void __launch_bounds__(DNT, 2)
k_dense(const bf16* Ah, const bf16* Al, const bf16* Bh, const bf16* Bl,
        const float* bias, const float* Dadd,
        float* C, bf16* Chi, bf16* Clo, int K, int ldc, int ldd)
{
    tc_gemm<DTN, DNT, EPI, OF32, OBF16, false>(Ah, Al, Bh, Bl, bias, Dadd, C, Chi, Clo,
                                               K, K, K, ldc, ldd, 1.0f);
}

__global__ void __launch_bounds__(DNT, 2)
k_dense_vT(const bf16* Ah, const bf16* Al, const bf16* Bh, const bf16* Bl,
           const float* bias, bf16* Vth, bf16* Vtl)
{
    tc_gemm<DTN, DNT, 0, false, false, true>(Ah, Al, Bh, Bl, bias, nullptr,
                                             nullptr, Vth, Vtl,
                                             DMODEL, DMODEL, DMODEL, 0, 0, 1.0f);
}

#define DSMEM (2 * (2 * 16384 + 2 * DTN * 128))   // 98304

// ============================================================================
//   fp16 2-term GEMM for the MLP: A split hi/lo fp16, B single fp16.
//   Error = B quantization (~2.8e-4) — safe for the MLP (diluted at output).
//   EPI: 1 = +Dadd, fp32 out.  2 = gelu, fp16 hi/lo out.
// ============================================================================
template<int EPI>
__device__ void tc_gemm2(
    const f16* __restrict__ Ah, const f16* __restrict__ Al,
    const f16* __restrict__ Bs,
    const float* __restrict__ bias, const float* __restrict__ Dadd,
    float* __restrict__ C, f16* __restrict__ Chi, f16* __restrict__ Clo,
    int K, int lda, int ldb, int ldc, int ldd)
{
    extern __shared__ char smem[];
    constexpr int TN = 64;
    constexpr int A_BYTES = 128 * 128;
    constexpr int B_BYTES = TN * 128;
    constexpr int STAGE   = 2 * A_BYTES + B_BYTES;   // 40960
    constexpr int MI = 2;                            // 8 warps, WC=2, WM=32

    const uint32_t sb = smem_u32(smem);
    const int tid  = threadIdx.x;
    const int wid  = tid >> 5;
    const int lane = tid & 31;
    const int m0 = blockIdx.y * 128;
    const int n0 = blockIdx.x * TN;
    const int wm0 = (wid / 2) * 32;
    const int wn0 = (wid % 2) * 32;

    float acc[MI][4][4];
    #pragma unroll
    for (int mi = 0; mi < MI; mi++)
        #pragma unroll
        for (int ni = 0; ni < 4; ni++)
            #pragma unroll
            for (int e = 0; e < 4; e++) acc[mi][ni][e] = 0.0f;

    auto load2 = [&](uint32_t st, long long kc) {
        #pragma unroll
        for (int it = 0; it < 4; it++) {
            int idx = tid + it * 256;
            int r = idx >> 3, c = idx & 7;
            uint32_t so = SW128(r * 128 + c * 16);
            long long go = (long long)(m0 + r) * lda + kc + c * 8;
            cp16(st + so,           Ah + go);
            cp16(st + A_BYTES + so, Al + go);
        }
        #pragma unroll
        for (int it = 0; it < 2; it++) {
            int idx = tid + it * 256;
            int r = idx >> 3, c = idx & 7;
            uint32_t so = SW128(r * 128 + c * 16);
            long long go = (long long)(n0 + r) * ldb + kc + c * 8;
            cp16(st + 2 * A_BYTES + so, Bs + go);
        }
        CP_COMMIT();
    };

    const int NC = K >> 6;
    load2(sb, 0);
    if (NC > 1) load2(sb + STAGE, 64);

    for (int i = 0; i < NC; i++) {
        if (i + 1 < NC) { CP_WAIT1(); } else { CP_WAIT0(); }
        __syncthreads();

        const uint32_t st = sb + (i & 1) * STAGE;
        #pragma unroll
        for (int kk = 0; kk < 4; kk++) {
            uint32_t ah[MI][4], al[MI][4], bh[4][2];
            const int colA = kk * 32 + ((lane & 16) ? 16 : 0);
            const int rA   = lane & 15;
            #pragma unroll
            for (int mi = 0; mi < MI; mi++) {
                uint32_t off = SW128((uint32_t)(wm0 + mi * 16 + rA) * 128 + colA);
                LDSM4(ah[mi][0], ah[mi][1], ah[mi][2], ah[mi][3], st + off);
                LDSM4(al[mi][0], al[mi][1], al[mi][2], al[mi][3], st + A_BYTES + off);
            }
            const int colB = kk * 32 + ((lane & 8) ? 16 : 0);
            const int rB   = (lane & 7) + ((lane & 16) ? 8 : 0);
            #pragma unroll
            for (int nj = 0; nj < 2; nj++) {
                uint32_t off = SW128((uint32_t)(wn0 + nj * 16 + rB) * 128 + colB);
                LDSM4(bh[nj*2][0], bh[nj*2][1], bh[nj*2+1][0], bh[nj*2+1][1],
                      st + 2 * A_BYTES + off);
            }
            #pragma unroll
            for (int mi = 0; mi < MI; mi++)
                #pragma unroll
                for (int ni = 0; ni < 4; ni++) {
                    mma_f16(acc[mi][ni], ah[mi], bh[ni]);
                    mma_f16(acc[mi][ni], al[mi], bh[ni]);
                }
        }
        __syncthreads();
        if (i + 2 < NC) load2(sb + (i & 1) * STAGE, (long long)(i + 2) * 64);
    }

    constexpr int LDS = TN + 8;
    float* sOut = (float*)smem;
    __syncthreads();

    #pragma unroll
    for (int mi = 0; mi < MI; mi++) {
        const int r0 = wm0 + mi * 16 + (lane >> 2);
        #pragma unroll
        for (int ni = 0; ni < 4; ni++) {
            const int c0 = wn0 + ni * 8 + (lane & 3) * 2;
            sOut[r0 * LDS + c0]           = acc[mi][ni][0];
            sOut[r0 * LDS + c0 + 1]       = acc[mi][ni][1];
            sOut[(r0 + 8) * LDS + c0]     = acc[mi][ni][2];
            sOut[(r0 + 8) * LDS + c0 + 1] = acc[mi][ni][3];
        }
    }
    __syncthreads();

    const int c = tid & (TN - 1);
    const int rs = tid / TN;
    const int n = n0 + c;
    #pragma unroll 4
    for (int rr = 0; rr < 128; rr += 4) {
        const int r = rr + rs;
        float v = sOut[r * LDS + c] + bias[n];
        const long long o = (long long)(m0 + r) * ldc + n;
        if (EPI == 2) {
            v = gelu_exact(v);
            f16 hi, lo;
            split_f16(v, hi, lo);
            Chi[o] = hi;
            Clo[o] = lo;
        } else {
            C[o] = v + Dadd[(long long)(m0 + r) * ldd + n];
        }
    }
}

template<int EPI>
__global__ void __launch_bounds__(256, 2)
k_dense2(const f16* Ah, const f16* Al, const f16* Bs,
         const float* bias, const float* Dadd,
         float* C, f16* Chi, f16* Clo, int K, int ldc, int ldd)
{
    tc_gemm2<EPI>(Ah, Al, Bs, bias, Dadd, C, Chi, Clo, K, K, K, ldc, ldd);
}

#define DSMEM2 (2 * (2 * 16384 + 64 * 128))   // 81920

// ============================================================================
//   fused attention (unchanged from round 8)
// ============================================================================
#define ATTN_SMEM (32768 + 2*65536)
#define NCH (NKV/128)

__device__ __forceinline__ void load_kv(
    uint32_t st, const bf16* __restrict__ kh, const bf16* __restrict__ kl,
    const bf16* __restrict__ vh, const bf16* __restrict__ vl, int ci, int tid)
{
    #pragma unroll
    for (int it = 0; it < 4; it++) {
        int idx = tid + it * 256;
        int r = idx >> 3, c = idx & 7;
        uint32_t so = SW128((uint32_t)r * 128 + c * 16);
        long long go = (long long)(ci * 128 + r) * DMODEL + c * 8;
        cp16(st + so,         kh + go);
        cp16(st + 16384 + so, kl + go);
    }
    #pragma unroll
    for (int it = 0; it < 4; it++) {
        int idx = tid + it * 256;
        int hf = idx >> 9, d = (idx >> 3) & 63, c = idx & 7;
        uint32_t so = (uint32_t)hf * 8192 + SW128((uint32_t)d * 128 + c * 16);
        long long go = (long long)d * NKV + ci * 128 + hf * 64 + c * 8;
        cp16(st + 32768 + so, vh + go);
        cp16(st + 49152 + so, vl + go);
    }
    CP_COMMIT();
}

__global__ void __launch_bounds__(256, 1)
k_attn(const bf16* __restrict__ qph, const bf16* __restrict__ qpl,
       const bf16* __restrict__ kph, const bf16* __restrict__ kpl,
       const bf16* __restrict__ vth, const bf16* __restrict__ vtl,
       float* __restrict__ attn,
       bf16* __restrict__ ctxh, bf16* __restrict__ ctxl)
{
    extern __shared__ char smem[];
    const uint32_t sb = smem_u32(smem);
    const int tid = threadIdx.x, wid = tid >> 5, lane = tid & 31;
    const int z  = blockIdx.x;
    const int h  = z / BATCH, b = z % BATCH;
    const int m0 = blockIdx.y * 128;
    const int wm0 = wid * 16;

    const bf16* khb = kph + (long long)b * NKV * DMODEL + h * HDIM;
    const bf16* klb = kpl + (long long)b * NKV * DMODEL + h * HDIM;
    const bf16* vhb = vth + (long long)z * HDIM * NKV;
    const bf16* vlb = vtl + (long long)z * HDIM * NKV;
    float* attn_w = attn + ((long long)z * MQ + m0 + wm0) * NKV;

    const uint32_t sQ = sb;
    const uint32_t sS = sb + 32768;

    {
        const bf16* qh0 = qph + ((long long)(b * MQ + m0)) * DMODEL + h * HDIM;
        const bf16* ql0 = qpl + ((long long)(b * MQ + m0)) * DMODEL + h * HDIM;
        #pragma unroll
        for (int it = 0; it < 4; it++) {
            int idx = tid + it * 256;
            int r = idx >> 3, c = idx & 7;
            uint32_t so = SW128((uint32_t)r * 128 + c * 16);
            long long go = (long long)r * DMODEL + c * 8;
            cp16(sQ + so,         qh0 + go);
            cp16(sQ + 16384 + so, ql0 + go);
        }
        CP_COMMIT();
    }
    load_kv(sS,         khb, klb, vhb, vlb, 0, tid);
    load_kv(sS + 65536, khb, klb, vhb, vlb, 1, tid);

    CP_WAIT2();
    __syncthreads();

    uint32_t qfh[4][4], qfl[4][4];
    {
        const int rA = lane & 15;
        #pragma unroll
        for (int kk = 0; kk < 4; kk++) {
            const int colA = kk * 32 + ((lane & 16) ? 16 : 0);
            uint32_t off = SW128((uint32_t)(wm0 + rA) * 128 + colA);
            LDSM4(qfh[kk][0], qfh[kk][1], qfh[kk][2], qfh[kk][3], sQ + off);
            LDSM4(qfl[kk][0], qfl[kk][1], qfl[kk][2], qfl[kk][3], sQ + 16384 + off);
        }
    }

    float cacc[8][4];
    #pragma unroll
    for (int i = 0; i < 8; i++)
        #pragma unroll
        for (int e = 0; e < 4; e++) cacc[i][e] = 0.0f;
    float lp0 = 0.0f, lp1 = 0.0f;

    const int rB   = (lane & 7) + ((lane & 16) ? 8 : 0);
    const int r    = lane >> 2;
    const int c2   = (lane & 3) * 2;
    const float CE = 0.125f * 1.4426950408889634f;

    for (int ci = 0; ci < NCH; ci++) {
        if (ci + 1 < NCH) { CP_WAIT1(); } else { CP_WAIT0(); }
        __syncthreads();
        const uint32_t st = sS + (ci & 1) * 65536;

        float sacc[16][4];
        #pragma unroll
        for (int t = 0; t < 16; t++)
            #pragma unroll
            for (int e = 0; e < 4; e++) sacc[t][e] = 0.0f;

        #pragma unroll
        for (int kk = 0; kk < 4; kk++) {
            const int colB = kk * 32 + ((lane & 8) ? 16 : 0);
            #pragma unroll
            for (int nt = 0; nt < 8; nt++) {
                uint32_t off = SW128((uint32_t)(nt * 16 + rB) * 128 + colB);
                uint32_t bh[4], bl[4];
                LDSM4(bh[0], bh[1], bh[2], bh[3], st + off);
                LDSM4(bl[0], bl[1], bl[2], bl[3], st + 16384 + off);
                mma_bf16(sacc[2*nt],   qfh[kk], bh);
                mma_bf16(sacc[2*nt],   qfh[kk], bl);
                mma_bf16(sacc[2*nt],   qfl[kk], bh);
                mma_bf16(sacc[2*nt+1], qfh[kk], bh + 2);
                mma_bf16(sacc[2*nt+1], qfh[kk], bl + 2);
                mma_bf16(sacc[2*nt+1], qfl[kk], bh + 2);
            }
        }

        float* a0 = attn_w + (long long)r * NKV + ci * 128;
        float* a1 = a0 + 8 * NKV;
        #pragma unroll
        for (int t = 0; t < 16; t++) {
            float p0 = ex2(sacc[t][0] * CE);
            float p1 = ex2(sacc[t][1] * CE);
            float p2 = ex2(sacc[t][2] * CE);
            float p3 = ex2(sacc[t][3] * CE);
            sacc[t][0] = p0; sacc[t][1] = p1; sacc[t][2] = p2; sacc[t][3] = p3;
            lp0 += p0 + p1;  lp1 += p2 + p3;
            *(float2*)(a0 + t * 8 + c2) = make_float2(p0, p1);
            *(float2*)(a1 + t * 8 + c2) = make_float2(p2, p3);
        }

        #pragma unroll
        for (int ks = 0; ks < 8; ks++) {
            uint32_t ah[4], al[4];
            split2(sacc[2*ks][0],   sacc[2*ks][1],   ah[0], al[0]);
            split2(sacc[2*ks][2],   sacc[2*ks][3],   ah[1], al[1]);
            split2(sacc[2*ks+1][0], sacc[2*ks+1][1], ah[2], al[2]);
            split2(sacc[2*ks+1][2], sacc[2*ks+1][3], ah[3], al[3]);

            const int hf = ks >> 2;
            const int colB = (ks & 3) * 32 + ((lane & 8) ? 16 : 0);
            const uint32_t vh_base = st + 32768 + hf * 8192;
            const uint32_t vl_base = st + 49152 + hf * 8192;
            #pragma unroll
            for (int dt = 0; dt < 4; dt++) {
                uint32_t off = SW128((uint32_t)(dt * 16 + rB) * 128 + colB);
                uint32_t bh[4], bl[4];
                LDSM4(bh[0], bh[1], bh[2], bh[3], vh_base + off);
                LDSM4(bl[0], bl[1], bl[2], bl[3], vl_base + off);
                mma_bf16(cacc[2*dt],   ah, bh);
                mma_bf16(cacc[2*dt],   ah, bl);
                mma_bf16(cacc[2*dt],   al, bh);
                mma_bf16(cacc[2*dt+1], ah, bh + 2);
                mma_bf16(cacc[2*dt+1], ah, bl + 2);
                mma_bf16(cacc[2*dt+1], al, bh + 2);
            }
        }

        __syncthreads();
        if (ci + 2 < NCH)
            load_kv(sS + (ci & 1) * 65536, khb, klb, vhb, vlb, ci + 2, tid);
    }

    lp0 += __shfl_xor_sync(0xFFFFFFFFu, lp0, 1);
    lp0 += __shfl_xor_sync(0xFFFFFFFFu, lp0, 2);
    lp1 += __shfl_xor_sync(0xFFFFFFFFu, lp1, 1);
    lp1 += __shfl_xor_sync(0xFFFFFFFFu, lp1, 2);
    const float il0 = 1.0f / lp0, il1 = 1.0f / lp1;

    float* ssum = (float*)smem;
    if ((lane & 3) == 0) {
        ssum[wm0 + r]     = il0;
        ssum[wm0 + r + 8] = il1;
    }

    const long long cb = ((long long)(b * MQ + m0 + wm0)) * DMODEL + h * HDIM;
    #pragma unroll
    for (int dt = 0; dt < 8; dt++) {
        const int d0 = dt * 8 + c2;
        uint32_t hi, lo;
        split2(cacc[dt][0] * il0, cacc[dt][1] * il0, hi, lo);
        *(uint32_t*)(ctxh + cb + (long long)r * DMODEL + d0) = hi;
        *(uint32_t*)(ctxl + cb + (long long)r * DMODEL + d0) = lo;
        split2(cacc[dt][2] * il1, cacc[dt][3] * il1, hi, lo);
        *(uint32_t*)(ctxh + cb + (long long)(r + 8) * DMODEL + d0) = hi;
        *(uint32_t*)(ctxl + cb + (long long)(r + 8) * DMODEL + d0) = lo;
    }

    __syncthreads();

    float* ab = attn + ((long long)z * MQ + m0) * NKV;
    for (int rr = 0; rr < 128; rr += 8) {
        const int row = rr + wid;
        const float s = ssum[row];
        float4* p4 = (float4*)(ab + (long long)row * NKV);
        #pragma unroll
        for (int j = 0; j < 16; j++) {
            float4 v = p4[lane + 32 * j];
            v.x *= s; v.y *= s; v.z *= s; v.w *= s;
            p4[lane + 32 * j] = v;
        }
    }
}

// ---------------- fp32 -> bf16 hi/lo ----------------
__global__ void __launch_bounds__(256)
k_cvt(const float* __restrict__ x, bf16* __restrict__ hi, bf16* __restrict__ lo)
{
    const long long i = ((long long)blockIdx.x * 256 + threadIdx.x) * 4;
    const float4 v = *(const float4*)(x + i);
    bf16 h0 = __float2bfloat16(v.x), h1 = __float2bfloat16(v.y);
    bf16 h2 = __float2bfloat16(v.z), h3 = __float2bfloat16(v.w);
    hi[i+0] = h0; hi[i+1] = h1; hi[i+2] = h2; hi[i+3] = h3;
    lo[i+0] = __float2bfloat16(v.x - __bfloat162float(h0));
    lo[i+1] = __float2bfloat16(v.y - __bfloat162float(h1));
    lo[i+2] = __float2bfloat16(v.z - __bfloat162float(h2));
    lo[i+3] = __float2bfloat16(v.w - __bfloat162float(h3));
}

// ---------------- fp32 -> single fp16 ----------------
__global__ void __launch_bounds__(256)
k_cvt16(const float* __restrict__ x, f16* __restrict__ o)
{
    const long long i = ((long long)blockIdx.x * 256 + threadIdx.x) * 4;
    const float4 v = *(const float4*)(x + i);
    o[i+0] = __float2half_rn(v.x);
    o[i+1] = __float2half_rn(v.y);
    o[i+2] = __float2half_rn(v.z);
    o[i+3] = __float2half_rn(v.w);
}

// ---------------- layernorm -> fp16 hi/lo ----------------
__global__ void __launch_bounds__(256)
k_ln(const float* __restrict__ x, const float* __restrict__ g,
     const float* __restrict__ b, f16* __restrict__ oh, f16* __restrict__ ol)
{
    __shared__ float r1[256], r2[256];
    const long long row = blockIdx.x;
    const float* p = x + row * (long long)DMODEL;
    const int t = threadIdx.x;

    float v[4]; float s = 0.0f, s2 = 0.0f;
    #pragma unroll
    for (int i = 0; i < 4; i++) {
        v[i] = p[t + i * 256];
        s += v[i]; s2 += v[i] * v[i];
    }
    r1[t] = s; r2[t] = s2; __syncthreads();
    for (int st = 128; st > 0; st >>= 1) {
        if (t < st) { r1[t] += r1[t + st]; r2[t] += r2[t + st]; }
        __syncthreads();
    }
    const float mu  = r1[0] * (1.0f / DMODEL);
    const float var = r2[0] * (1.0f / DMODEL) - mu * mu;
    const float inv = rsqrtf(var + 1e-5f);

    f16* ph = oh + row * (long long)DMODEL;
    f16* pl = ol + row * (long long)DMODEL;
    #pragma unroll
    for (int i = 0; i < 4; i++) {
        const int c = t + i * 256;
        const float y = (v[i] - mu) * inv * g[c] + b[c];
        f16 hi, lo;
        split_f16(y, hi, lo);
        ph[c] = hi;
        pl[c] = lo;
    }
}

// ---------------- host launch ----------------
static void* sym(const void* s) { void* p; cudaGetSymbolAddress(&p, s); return p; }

extern "C" void kernel_launch(void* const* d_in, const int* in_sizes, int n_in,
                              void* d_out, int out_size)
{
    const float* x    = (const float*)d_in[0];
    const float* q    = (const float*)d_in[1];
    const float* w_q  = (const float*)d_in[2];
    const float* b_q  = (const float*)d_in[3];
    const float* w_k  = (const float*)d_in[4];
    const float* b_k  = (const float*)d_in[5];
    const float* w_v  = (const float*)d_in[6];
    const float* b_v  = (const float*)d_in[7];
    const float* w_o  = (const float*)d_in[8];
    const float* b_o  = (const float*)d_in[9];
    const float* ln2g = (const float*)d_in[10];
    const float* ln2b = (const float*)d_in[11];
    const float* w1   = (const float*)d_in[12];
    const float* b1   = (const float*)d_in[13];
    const float* w2   = (const float*)d_in[14];
    const float* b2   = (const float*)d_in[15];

    float* out  = (float*)d_out;
    float* attn = out + (long long)BATCH * MQ * DMODEL;

    float* resid = (float*)sym(g_resid);
    bf16 *qh=(bf16*)sym(g_qh), *ql=(bf16*)sym(g_ql);
    bf16 *xh=(bf16*)sym(g_xh), *xl=(bf16*)sym(g_xl);
    bf16 *wqh=(bf16*)sym(g_wqh), *wql=(bf16*)sym(g_wql);
    bf16 *wkh=(bf16*)sym(g_wkh), *wkl=(bf16*)sym(g_wkl);
    bf16 *wvh=(bf16*)sym(g_wvh), *wvl=(bf16*)sym(g_wvl);
    bf16 *woh=(bf16*)sym(g_woh), *wol=(bf16*)sym(g_wol);
    f16  *w1f=(f16*)sym(g_w1f), *w2f=(f16*)sym(g_w2f);
    bf16 *qph=(bf16*)sym(g_qph), *qpl=(bf16*)sym(g_qpl);
    bf16 *kph=(bf16*)sym(g_kph), *kpl=(bf16*)sym(g_kpl);
    bf16 *vth=(bf16*)sym(g_vth), *vtl=(bf16*)sym(g_vtl);
    bf16 *ctxh=(bf16*)sym(g_ctxh), *ctxl=(bf16*)sym(g_ctxl);
    f16  *hh=(f16*)sym(g_hh), *hl=(f16*)sym(g_hl);
    f16  *h1h=(f16*)sym(g_h1h), *h1l=(f16*)sym(g_h1l);

    cudaFuncSetAttribute((const void*)k_dense<0,false,true>, cudaFuncAttributeMaxDynamicSharedMemorySize, DSMEM);
    cudaFuncSetAttribute((const void*)k_dense<1,true,false>, cudaFuncAttributeMaxDynamicSharedMemorySize, DSMEM);
    cudaFuncSetAttribute((const void*)k_dense_vT, cudaFuncAttributeMaxDynamicSharedMemorySize, DSMEM);
    cudaFuncSetAttribute((const void*)k_dense2<1>, cudaFuncAttributeMaxDynamicSharedMemorySize, DSMEM2);
    cudaFuncSetAttribute((const void*)k_dense2<2>, cudaFuncAttributeMaxDynamicSharedMemorySize, DSMEM2);
    cudaFuncSetAttribute((const void*)k_attn, cudaFuncAttributeMaxDynamicSharedMemorySize, ATTN_SMEM);

    const dim3 blk(256);
    const dim3 dblk(DNT);
    #define CVT(src, hi, lo, nelem) k_cvt<<<(int)((nelem) / 1024), blk>>>(src, hi, lo)

    // indices 0-4: conversions; indices 5-7: dense GEMMs (for ncu sampling)
    CVT(x,   xh,  xl,  (size_t)BATCH*NKV*DMODEL);       // 0
    CVT(w_v, wvh, wvl, (size_t)DMODEL*DMODEL);          // 1
    CVT(w_k, wkh, wkl, (size_t)DMODEL*DMODEL);          // 2
    CVT(q,   qh,  ql,  (size_t)BATCH*MQ*DMODEL);        // 3
    CVT(w_q, wqh, wql, (size_t)DMODEL*DMODEL);          // 4

    // V projection -> transposed bf16 hi/lo directly                 (5)
    k_dense_vT<<<dim3(DMODEL/DTN, 64), dblk, DSMEM>>>(xh, xl, wvh, wvl, b_v, vth, vtl);
    // K projection                                                   (6)
    k_dense<0,false,true><<<dim3(DMODEL/DTN, 64), dblk, DSMEM>>>(xh, xl, wkh, wkl, b_k, nullptr,
        nullptr, kph, kpl, DMODEL, DMODEL, 0);
    // Q projection                                                   (7)
    k_dense<0,false,true><<<dim3(DMODEL/DTN, 32), dblk, DSMEM>>>(qh, ql, wqh, wql, b_q, nullptr,
        nullptr, qph, qpl, DMODEL, DMODEL, 0);

    // fused attention (attn normalized in-kernel)
    k_attn<<<dim3(ZHB, MQ/128), blk, ATTN_SMEM>>>(qph, qpl, kph, kpl, vth, vtl,
                                                  attn, ctxh, ctxl);

    // remaining weight conversions
    CVT(w_o, woh, wol, (size_t)DMODEL*DMODEL);
    k_cvt16<<<(int)((size_t)DMLP*DMODEL/1024), blk>>>(w1, w1f);
    k_cvt16<<<(int)((size_t)DMODEL*DMLP/1024), blk>>>(w2, w2f);

    // resid = ctx @ w_o^T + b_o + q   (bf16 3-term)
    k_dense<1,true,false><<<dim3(DMODEL/DTN, 32), dblk, DSMEM>>>(ctxh, ctxl, woh, wol, b_o, q,
        resid, nullptr, nullptr, DMODEL, DMODEL, DMODEL);

    // h = LN(resid) -> fp16 hi/lo
    k_ln<<<BATCH*MQ, blk>>>(resid, ln2g, ln2b, hh, hl);

    // h1 = gelu(h @ w1^T + b1) -> fp16 hi/lo   (fp16 2-term)
    k_dense2<2><<<dim3(DMLP/DTN, 32), dblk, DSMEM2>>>(hh, hl, w1f, b1, nullptr,
        nullptr, h1h, h1l, DMODEL, DMLP, 0);

    // out = h1 @ w2^T + b2 + resid             (fp16 2-term)
    k_dense2<1><<<dim3(DMODEL/DTN, 32), dblk, DSMEM2>>>(h1h, h1l, w2f, b2, resid,
        out, nullptr, nullptr, DMLP, DMODEL, DMODEL);

    #undef CVT
}

// round 10
// speedup vs baseline: 7.2122x; 1.1715x over previous
#include <cuda_runtime.h>
#include <cuda_fp16.h>
#include <math.h>
#include <stdint.h>

// ---------------- problem constants ----------------
#define BATCH  4
#define MQ     1024
#define NKV    2048
#define DMODEL 1024
#define NHEAD  16
#define HDIM   64
#define DMLP   4096
#define ZHB    (NHEAD*BATCH)

typedef __half f16;

// ---------------- scratch (device globals; no allocs allowed) ----------------
__device__ __align__(1024) float g_resid[(size_t)BATCH*MQ*DMODEL];

__device__ __align__(1024) f16 g_qh [(size_t)BATCH*MQ*DMODEL];
__device__ __align__(1024) f16 g_ql [(size_t)BATCH*MQ*DMODEL];
__device__ __align__(1024) f16 g_xh [(size_t)BATCH*NKV*DMODEL];
__device__ __align__(1024) f16 g_xl [(size_t)BATCH*NKV*DMODEL];
__device__ __align__(1024) f16 g_wqf[(size_t)DMODEL*DMODEL];
__device__ __align__(1024) f16 g_wkf[(size_t)DMODEL*DMODEL];
__device__ __align__(1024) f16 g_wvf[(size_t)DMODEL*DMODEL];
__device__ __align__(1024) f16 g_wof[(size_t)DMODEL*DMODEL];
__device__ __align__(1024) f16 g_w1f[(size_t)DMLP*DMODEL];
__device__ __align__(1024) f16 g_w2f[(size_t)DMODEL*DMLP];
__device__ __align__(1024) f16 g_qph[(size_t)BATCH*MQ*DMODEL];
__device__ __align__(1024) f16 g_qpl[(size_t)BATCH*MQ*DMODEL];
__device__ __align__(1024) f16 g_kpf[(size_t)BATCH*NKV*DMODEL];
__device__ __align__(1024) f16 g_vtf[(size_t)ZHB*HDIM*NKV];
__device__ __align__(1024) f16 g_ctxh[(size_t)BATCH*MQ*DMODEL];
__device__ __align__(1024) f16 g_ctxl[(size_t)BATCH*MQ*DMODEL];
__device__ __align__(1024) f16 g_hh [(size_t)BATCH*MQ*DMODEL];
__device__ __align__(1024) f16 g_hl [(size_t)BATCH*MQ*DMODEL];
__device__ __align__(1024) f16 g_h1h[(size_t)BATCH*MQ*DMLP];
__device__ __align__(1024) f16 g_h1l[(size_t)BATCH*MQ*DMLP];

// ---------------- helpers ----------------
#define SW128(o) ((uint32_t)(o) ^ ((((uint32_t)(o)) >> 3) & 0x70u))

__device__ __forceinline__ uint32_t smem_u32(const void* p) {
    return (uint32_t)__cvta_generic_to_shared(p);
}

__device__ __forceinline__ void cp16(uint32_t dst, const void* src) {
    asm volatile("cp.async.cg.shared.global [%0], [%1], 16;" :: "r"(dst), "l"(src));
}
#define CP_COMMIT() asm volatile("cp.async.commit_group;" ::: "memory")
#define CP_WAIT0()  asm volatile("cp.async.wait_group 0;" ::: "memory")
#define CP_WAIT1()  asm volatile("cp.async.wait_group 1;" ::: "memory")
#define CP_WAIT2()  asm volatile("cp.async.wait_group 2;" ::: "memory")

#define LDSM4(r0, r1, r2, r3, addr) \
    asm volatile("ldmatrix.sync.aligned.m8n8.x4.shared.b16 {%0,%1,%2,%3}, [%4];" \
        : "=r"(r0), "=r"(r1), "=r"(r2), "=r"(r3) : "r"(addr))

__device__ __forceinline__ void mma_f16(float* c, const uint32_t* a, const uint32_t* b) {
    asm volatile(
        "mma.sync.aligned.m16n8k16.row.col.f32.f16.f16.f32 "
        "{%0,%1,%2,%3}, {%4,%5,%6,%7}, {%8,%9}, {%0,%1,%2,%3};"
        : "+f"(c[0]), "+f"(c[1]), "+f"(c[2]), "+f"(c[3])
        : "r"(a[0]), "r"(a[1]), "r"(a[2]), "r"(a[3]), "r"(b[0]), "r"(b[1]));
}

__device__ __forceinline__ float ex2(float x) {
    float r;
    asm("ex2.approx.f32 %0, %1;" : "=f"(r) : "f"(x));
    return r;
}

__device__ __forceinline__ float gelu_exact(float v) {
    return 0.5f * v * (1.0f + erff(v * 0.70710678118654752440f));
}

// split two fp32 into packed f16x2 hi and residual-lo words
__device__ __forceinline__ void split2h(float e0, float e1, uint32_t& hi, uint32_t& lo) {
    __half2 hp = __floats2half2_rn(e0, e1);
    hi = *reinterpret_cast<uint32_t*>(&hp);
    float f0 = __half2float(__low2half(hp));
    float f1 = __half2float(__high2half(hp));
    __half2 lp = __floats2half2_rn(e0 - f0, e1 - f1);
    lo = *reinterpret_cast<uint32_t*>(&lp);
}

__device__ __forceinline__ void split_f16(float v, f16& hi, f16& lo) {
    hi = __float2half_rn(v);
    lo = __float2half_rn(v - __half2float(hi));
}

// ============================================================================
//   unified fp16 2-term GEMM: A hi/lo fp16, B single fp16.
//   TN=64, 256 threads, MI=2, 80KB stages -> 2 CTAs/SM.
//   C = A.B^T (+bias) with output modes.
// ============================================================================
#define DNT 256
#define DTN 64
#define OUT_F32ADD 0   // fp32, + Dadd
#define OUT_F16HL  1   // fp16 hi/lo (optional gelu via EPI=2)
#define OUT_F16    2   // single fp16
#define OUT_VT     3   // transposed per-head single fp16 (V projection)

template<int EPI, int OUT>
__device__ void tc_gemm2(
    const f16* __restrict__ Ah, const f16* __restrict__ Al,
    const f16* __restrict__ Bs,
    const float* __restrict__ bias, const float* __restrict__ Dadd,
    float* __restrict__ C, f16* __restrict__ Chi, f16* __restrict__ Clo,
    int K, int lda, int ldb, int ldc, int ldd)
{
    extern __shared__ char smem[];
    constexpr int TN = DTN;
    constexpr int A_BYTES = 128 * 128;
    constexpr int B_BYTES = TN * 128;
    constexpr int STAGE   = 2 * A_BYTES + B_BYTES;   // 40960
    constexpr int MI = 2;

    const uint32_t sb = smem_u32(smem);
    const int tid  = threadIdx.x;
    const int wid  = tid >> 5;
    const int lane = tid & 31;
    const int m0 = blockIdx.y * 128;
    const int n0 = blockIdx.x * TN;
    const int wm0 = (wid / 2) * 32;
    const int wn0 = (wid % 2) * 32;

    float acc[MI][4][4];
    #pragma unroll
    for (int mi = 0; mi < MI; mi++)
        #pragma unroll
        for (int ni = 0; ni < 4; ni++)
            #pragma unroll
            for (int e = 0; e < 4; e++) acc[mi][ni][e] = 0.0f;

    auto load2 = [&](uint32_t st, long long kc) {
        #pragma unroll
        for (int it = 0; it < 4; it++) {
            int idx = tid + it * 256;
            int r = idx >> 3, c = idx & 7;
            uint32_t so = SW128(r * 128 + c * 16);
            long long go = (long long)(m0 + r) * lda + kc + c * 8;
            cp16(st + so,           Ah + go);
            cp16(st + A_BYTES + so, Al + go);
        }
        #pragma unroll
        for (int it = 0; it < 2; it++) {
            int idx = tid + it * 256;
            int r = idx >> 3, c = idx & 7;
            uint32_t so = SW128(r * 128 + c * 16);
            long long go = (long long)(n0 + r) * ldb + kc + c * 8;
            cp16(st + 2 * A_BYTES + so, Bs + go);
        }
        CP_COMMIT();
    };

    const int NC = K >> 6;
    load2(sb, 0);
    if (NC > 1) load2(sb + STAGE, 64);

    for (int i = 0; i < NC; i++) {
        if (i + 1 < NC) { CP_WAIT1(); } else { CP_WAIT0(); }
        __syncthreads();

        const uint32_t st = sb + (i & 1) * STAGE;
        #pragma unroll
        for (int kk = 0; kk < 4; kk++) {
            uint32_t ah[MI][4], al[MI][4], bh[4][2];
            const int colA = kk * 32 + ((lane & 16) ? 16 : 0);
            const int rA   = lane & 15;
            #pragma unroll
            for (int mi = 0; mi < MI; mi++) {
                uint32_t off = SW128((uint32_t)(wm0 + mi * 16 + rA) * 128 + colA);
                LDSM4(ah[mi][0], ah[mi][1], ah[mi][2], ah[mi][3], st + off);
                LDSM4(al[mi][0], al[mi][1], al[mi][2], al[mi][3], st + A_BYTES + off);
            }
            const int colB = kk * 32 + ((lane & 8) ? 16 : 0);
            const int rB   = (lane & 7) + ((lane & 16) ? 8 : 0);
            #pragma unroll
            for (int nj = 0; nj < 2; nj++) {
                uint32_t off = SW128((uint32_t)(wn0 + nj * 16 + rB) * 128 + colB);
                LDSM4(bh[nj*2][0], bh[nj*2][1], bh[nj*2+1][0], bh[nj*2+1][1],
                      st + 2 * A_BYTES + off);
            }
            #pragma unroll
            for (int mi = 0; mi < MI; mi++)
                #pragma unroll
                for (int ni = 0; ni < 4; ni++) {
                    mma_f16(acc[mi][ni], ah[mi], bh[ni]);
                    mma_f16(acc[mi][ni], al[mi], bh[ni]);
                }
        }
        __syncthreads();
        if (i + 2 < NC) load2(sb + (i & 1) * STAGE, (long long)(i + 2) * 64);
    }

    constexpr int LDS = (OUT == OUT_VT) ? (TN + 1) : (TN + 8);
    float* sOut = (float*)smem;
    __syncthreads();

    #pragma unroll
    for (int mi = 0; mi < MI; mi++) {
        const int r0 = wm0 + mi * 16 + (lane >> 2);
        #pragma unroll
        for (int ni = 0; ni < 4; ni++) {
            const int c0 = wn0 + ni * 8 + (lane & 3) * 2;
            sOut[r0 * LDS + c0]           = acc[mi][ni][0];
            sOut[r0 * LDS + c0 + 1]       = acc[mi][ni][1];
            sOut[(r0 + 8) * LDS + c0]     = acc[mi][ni][2];
            sOut[(r0 + 8) * LDS + c0 + 1] = acc[mi][ni][3];
        }
    }
    __syncthreads();

    if (OUT == OUT_VT) {
        // write C^T per head as single fp16 (all 128 rows)
        const int bb = m0 / NKV;
        const int nb = m0 % NKV;
        const int colw = tid >> 5;
        #pragma unroll
        for (int cp = 0; cp < 8; cp++) {
            const int col = colw + cp * 8;
            const int e = n0 + col;
            const int hh2 = e >> 6, dd = e & 63;
            const long long base =
                ((long long)(hh2 * BATCH + bb) * HDIM + dd) * NKV + nb;
            const float bv = bias[e];
            #pragma unroll
            for (int rh = 0; rh < 2; rh++) {
                const int row0 = rh * 64 + 2 * lane;
                const float v0 = sOut[row0       * LDS + col] + bv;
                const float v1 = sOut[(row0 + 1) * LDS + col] + bv;
                __half2 hp = __floats2half2_rn(v0, v1);
                *(uint32_t*)(Chi + base + row0) = *reinterpret_cast<uint32_t*>(&hp);
            }
        }
        return;
    }

    const int c = tid & (TN - 1);
    const int rs = tid / TN;
    const int n = n0 + c;
    #pragma unroll 4
    for (int rr = 0; rr < 128; rr += 4) {
        const int r = rr + rs;
        float v = sOut[r * LDS + c] + bias[n];
        const long long o = (long long)(m0 + r) * ldc + n;
        if (OUT == OUT_F32ADD) {
            C[o] = v + Dadd[(long long)(m0 + r) * ldd + n];
        } else if (OUT == OUT_F16HL) {
            if (EPI == 2) v = gelu_exact(v);
            f16 hi, lo;
            split_f16(v, hi, lo);
            Chi[o] = hi;
            Clo[o] = lo;
        } else {  // OUT_F16
            Chi[o] = __float2half_rn(v);
        }
    }
}

template<int EPI, int OUT>
__global__ void __launch_bounds__(DNT, 2)
k_gemm(const f16* Ah, const f16* Al, const f16* Bs,
       const float* bias, const float* Dadd,
       float* C, f16* Chi, f16* Clo, int K, int ldc, int ldd)
{
    tc_gemm2<EPI, OUT>(Ah, Al, Bs, bias, Dadd, C, Chi, Clo, K, K, K, ldc, ldd);
}

#define DSMEM2 (2 * (2 * 16384 + DTN * 128))   // 81920

// ============================================================================
//   fused attention, fp16 2-term: S = QhK + QlK; PV = PhV + PlV.
//   K, V single fp16 in smem. attn normalized in-kernel.
// ============================================================================
#define ATTN_SMEM (32768 + 2*32768)   // Q hi/lo + 2 stages x (K 16K + V 16K)
#define NCH (NKV/128)

__device__ __forceinline__ void load_kv(
    uint32_t st, const f16* __restrict__ kp, const f16* __restrict__ vt,
    int ci, int tid)
{
    #pragma unroll
    for (int it = 0; it < 4; it++) {
        int idx = tid + it * 256;
        int r = idx >> 3, c = idx & 7;
        uint32_t so = SW128((uint32_t)r * 128 + c * 16);
        long long go = (long long)(ci * 128 + r) * DMODEL + c * 8;
        cp16(st + so, kp + go);
    }
    #pragma unroll
    for (int it = 0; it < 4; it++) {
        int idx = tid + it * 256;
        int hf = idx >> 9, d = (idx >> 3) & 63, c = idx & 7;
        uint32_t so = (uint32_t)hf * 8192 + SW128((uint32_t)d * 128 + c * 16);
        long long go = (long long)d * NKV + ci * 128 + hf * 64 + c * 8;
        cp16(st + 16384 + so, vt + go);
    }
    CP_COMMIT();
}

__global__ void __launch_bounds__(256, 1)
k_attn(const f16* __restrict__ qph, const f16* __restrict__ qpl,
       const f16* __restrict__ kpf, const f16* __restrict__ vtf,
       float* __restrict__ attn,
       f16* __restrict__ ctxh, f16* __restrict__ ctxl)
{
    extern __shared__ char smem[];
    const uint32_t sb = smem_u32(smem);
    const int tid = threadIdx.x, wid = tid >> 5, lane = tid & 31;
    const int z  = blockIdx.x;            // h*BATCH + b
    const int h  = z / BATCH, b = z % BATCH;
    const int m0 = blockIdx.y * 128;
    const int wm0 = wid * 16;

    const f16* khb = kpf + (long long)b * NKV * DMODEL + h * HDIM;
    const f16* vtb = vtf + (long long)z * HDIM * NKV;
    float* attn_w = attn + ((long long)z * MQ + m0 + wm0) * NKV;

    const uint32_t sQ = sb;               // hi; +16384 lo
    const uint32_t sS = sb + 32768;       // stage base, stride 32768

    {
        const f16* qh0 = qph + ((long long)(b * MQ + m0)) * DMODEL + h * HDIM;
        const f16* ql0 = qpl + ((long long)(b * MQ + m0)) * DMODEL + h * HDIM;
        #pragma unroll
        for (int it = 0; it < 4; it++) {
            int idx = tid + it * 256;
            int r = idx >> 3, c = idx & 7;
            uint32_t so = SW128((uint32_t)r * 128 + c * 16);
            long long go = (long long)r * DMODEL + c * 8;
            cp16(sQ + so,         qh0 + go);
            cp16(sQ + 16384 + so, ql0 + go);
        }
        CP_COMMIT();
    }
    load_kv(sS,         khb, vtb, 0, tid);
    load_kv(sS + 32768, khb, vtb, 1, tid);

    CP_WAIT2();
    __syncthreads();

    // preload Q fragments (persistent)
    uint32_t qfh[4][4], qfl[4][4];
    {
        const int rA = lane & 15;
        #pragma unroll
        for (int kk = 0; kk < 4; kk++) {
            const int colA = kk * 32 + ((lane & 16) ? 16 : 0);
            uint32_t off = SW128((uint32_t)(wm0 + rA) * 128 + colA);
            LDSM4(qfh[kk][0], qfh[kk][1], qfh[kk][2], qfh[kk][3], sQ + off);
            LDSM4(qfl[kk][0], qfl[kk][1], qfl[kk][2], qfl[kk][3], sQ + 16384 + off);
        }
    }

    float cacc[8][4];
    #pragma unroll
    for (int i = 0; i < 8; i++)
        #pragma unroll
        for (int e = 0; e < 4; e++) cacc[i][e] = 0.0f;
    float lp0 = 0.0f, lp1 = 0.0f;

    const int rB   = (lane & 7) + ((lane & 16) ? 8 : 0);
    const int r    = lane >> 2;
    const int c2   = (lane & 3) * 2;
    const float CE = 0.125f * 1.4426950408889634f;

    for (int ci = 0; ci < NCH; ci++) {
        if (ci + 1 < NCH) { CP_WAIT1(); } else { CP_WAIT0(); }
        __syncthreads();
        const uint32_t st = sS + (ci & 1) * 32768;

        // ---- S = Q K^T (2-term) ----
        float sacc[16][4];
        #pragma unroll
        for (int t = 0; t < 16; t++)
            #pragma unroll
            for (int e = 0; e < 4; e++) sacc[t][e] = 0.0f;

        #pragma unroll
        for (int kk = 0; kk < 4; kk++) {
            const int colB = kk * 32 + ((lane & 8) ? 16 : 0);
            #pragma unroll
            for (int nt = 0; nt < 8; nt++) {
                uint32_t off = SW128((uint32_t)(nt * 16 + rB) * 128 + colB);
                uint32_t bh[4];
                LDSM4(bh[0], bh[1], bh[2], bh[3], st + off);
                mma_f16(sacc[2*nt],   qfh[kk], bh);
                mma_f16(sacc[2*nt],   qfl[kk], bh);
                mma_f16(sacc[2*nt+1], qfh[kk], bh + 2);
                mma_f16(sacc[2*nt+1], qfl[kk], bh + 2);
            }
        }

        // ---- p = exp(S/8); write unnormalized attn; row sums ----
        float* a0 = attn_w + (long long)r * NKV + ci * 128;
        float* a1 = a0 + 8 * NKV;
        #pragma unroll
        for (int t = 0; t < 16; t++) {
            float p0 = ex2(sacc[t][0] * CE);
            float p1 = ex2(sacc[t][1] * CE);
            float p2 = ex2(sacc[t][2] * CE);
            float p3 = ex2(sacc[t][3] * CE);
            sacc[t][0] = p0; sacc[t][1] = p1; sacc[t][2] = p2; sacc[t][3] = p3;
            lp0 += p0 + p1;  lp1 += p2 + p3;
            *(float2*)(a0 + t * 8 + c2) = make_float2(p0, p1);
            *(float2*)(a1 + t * 8 + c2) = make_float2(p2, p3);
        }

        // ---- ctx += P V (P split fp16 hi/lo in registers) ----
        #pragma unroll
        for (int ks = 0; ks < 8; ks++) {
            uint32_t ah[4], al[4];
            split2h(sacc[2*ks][0],   sacc[2*ks][1],   ah[0], al[0]);
            split2h(sacc[2*ks][2],   sacc[2*ks][3],   ah[1], al[1]);
            split2h(sacc[2*ks+1][0], sacc[2*ks+1][1], ah[2], al[2]);
            split2h(sacc[2*ks+1][2], sacc[2*ks+1][3], ah[3], al[3]);

            const int hf = ks >> 2;
            const int colB = (ks & 3) * 32 + ((lane & 8) ? 16 : 0);
            const uint32_t v_base = st + 16384 + hf * 8192;
            #pragma unroll
            for (int dt = 0; dt < 4; dt++) {
                uint32_t off = SW128((uint32_t)(dt * 16 + rB) * 128 + colB);
                uint32_t bh[4];
                LDSM4(bh[0], bh[1], bh[2], bh[3], v_base + off);
                mma_f16(cacc[2*dt],   ah, bh);
                mma_f16(cacc[2*dt],   al, bh);
                mma_f16(cacc[2*dt+1], ah, bh + 2);
                mma_f16(cacc[2*dt+1], al, bh + 2);
            }
        }

        __syncthreads();
        if (ci + 2 < NCH)
            load_kv(sS + (ci & 1) * 32768, khb, vtb, ci + 2, tid);
    }

    // ---- row sums -> inverse; ctx write (fp16 hi/lo); attn normalize ----
    lp0 += __shfl_xor_sync(0xFFFFFFFFu, lp0, 1);
    lp0 += __shfl_xor_sync(0xFFFFFFFFu, lp0, 2);
    lp1 += __shfl_xor_sync(0xFFFFFFFFu, lp1, 1);
    lp1 += __shfl_xor_sync(0xFFFFFFFFu, lp1, 2);
    const float il0 = 1.0f / lp0, il1 = 1.0f / lp1;

    float* ssum = (float*)smem;
    if ((lane & 3) == 0) {
        ssum[wm0 + r]     = il0;
        ssum[wm0 + r + 8] = il1;
    }

    const long long cb = ((long long)(b * MQ + m0 + wm0)) * DMODEL + h * HDIM;
    #pragma unroll
    for (int dt = 0; dt < 8; dt++) {
        const int d0 = dt * 8 + c2;
        uint32_t hi, lo;
        split2h(cacc[dt][0] * il0, cacc[dt][1] * il0, hi, lo);
        *(uint32_t*)(ctxh + cb + (long long)r * DMODEL + d0) = hi;
        *(uint32_t*)(ctxl + cb + (long long)r * DMODEL + d0) = lo;
        split2h(cacc[dt][2] * il1, cacc[dt][3] * il1, hi, lo);
        *(uint32_t*)(ctxh + cb + (long long)(r + 8) * DMODEL + d0) = hi;
        *(uint32_t*)(ctxl + cb + (long long)(r + 8) * DMODEL + d0) = lo;
    }

    __syncthreads();   // orders p-writes + ssum for all warps

    float* ab = attn + ((long long)z * MQ + m0) * NKV;
    for (int rr = 0; rr < 128; rr += 8) {
        const int row = rr + wid;
        const float s = ssum[row];
        float4* p4 = (float4*)(ab + (long long)row * NKV);
        #pragma unroll
        for (int j = 0; j < 16; j++) {
            float4 v = p4[lane + 32 * j];
            v.x *= s; v.y *= s; v.z *= s; v.w *= s;
            p4[lane + 32 * j] = v;
        }
    }
}

// ---------------- fp32 -> fp16 hi/lo ----------------
__global__ void __launch_bounds__(256)
k_cvt_hl(const float* __restrict__ x, f16* __restrict__ hi, f16* __restrict__ lo)
{
    const long long i = ((long long)blockIdx.x * 256 + threadIdx.x) * 4;
    const float4 v = *(const float4*)(x + i);
    f16 h0, l0, h1, l1, h2, l2, h3, l3;
    split_f16(v.x, h0, l0);
    split_f16(v.y, h1, l1);
    split_f16(v.z, h2, l2);
    split_f16(v.w, h3, l3);
    hi[i+0] = h0; hi[i+1] = h1; hi[i+2] = h2; hi[i+3] = h3;
    lo[i+0] = l0; lo[i+1] = l1; lo[i+2] = l2; lo[i+3] = l3;
}

// ---------------- fp32 -> single fp16 ----------------
__global__ void __launch_bounds__(256)
k_cvt16(const float* __restrict__ x, f16* __restrict__ o)
{
    const long long i = ((long long)blockIdx.x * 256 + threadIdx.x) * 4;
    const float4 v = *(const float4*)(x + i);
    o[i+0] = __float2half_rn(v.x);
    o[i+1] = __float2half_rn(v.y);
    o[i+2] = __float2half_rn(v.z);
    o[i+3] = __float2half_rn(v.w);
}

// ---------------- layernorm -> fp16 hi/lo ----------------
__global__ void __launch_bounds__(256)
k_ln(const float* __restrict__ x, const float* __restrict__ g,
     const float* __restrict__ b, f16* __restrict__ oh, f16* __restrict__ ol)
{
    __shared__ float r1[256], r2[256];
    const long long row = blockIdx.x;
    const float* p = x + row * (long long)DMODEL;
    const int t = threadIdx.x;

    float v[4]; float s = 0.0f, s2 = 0.0f;
    #pragma unroll
    for (int i = 0; i < 4; i++) {
        v[i] = p[t + i * 256];
        s += v[i]; s2 += v[i] * v[i];
    }
    r1[t] = s; r2[t] = s2; __syncthreads();
    for (int st = 128; st > 0; st >>= 1) {
        if (t < st) { r1[t] += r1[t + st]; r2[t] += r2[t + st]; }
        __syncthreads();
    }
    const float mu  = r1[0] * (1.0f / DMODEL);
    const float var = r2[0] * (1.0f / DMODEL) - mu * mu;
    const float inv = rsqrtf(var + 1e-5f);

    f16* ph = oh + row * (long long)DMODEL;
    f16* pl = ol + row * (long long)DMODEL;
    #pragma unroll
    for (int i = 0; i < 4; i++) {
        const int c = t + i * 256;
        const float y = (v[i] - mu) * inv * g[c] + b[c];
        f16 hi, lo;
        split_f16(y, hi, lo);
        ph[c] = hi;
        pl[c] = lo;
    }
}

// ---------------- host launch ----------------
static void* sym(const void* s) { void* p; cudaGetSymbolAddress(&p, s); return p; }

extern "C" void kernel_launch(void* const* d_in, const int* in_sizes, int n_in,
                              void* d_out, int out_size)
{
    const float* x    = (const float*)d_in[0];
    const float* q    = (const float*)d_in[1];
    const float* w_q  = (const float*)d_in[2];
    const float* b_q  = (const float*)d_in[3];
    const float* w_k  = (const float*)d_in[4];
    const float* b_k  = (const float*)d_in[5];
    const float* w_v  = (const float*)d_in[6];
    const float* b_v  = (const float*)d_in[7];
    const float* w_o  = (const float*)d_in[8];
    const float* b_o  = (const float*)d_in[9];
    const float* ln2g = (const float*)d_in[10];
    const float* ln2b = (const float*)d_in[11];
    const float* w1   = (const float*)d_in[12];
    const float* b1   = (const float*)d_in[13];
    const float* w2   = (const float*)d_in[14];
    const float* b2   = (const float*)d_in[15];

    float* out  = (float*)d_out;
    float* attn = out + (long long)BATCH * MQ * DMODEL;

    float* resid = (float*)sym(g_resid);
    f16 *qh=(f16*)sym(g_qh), *ql=(f16*)sym(g_ql);
    f16 *xh=(f16*)sym(g_xh), *xl=(f16*)sym(g_xl);
    f16 *wqf=(f16*)sym(g_wqf), *wkf=(f16*)sym(g_wkf);
    f16 *wvf=(f16*)sym(g_wvf), *wof=(f16*)sym(g_wof);
    f16 *w1f=(f16*)sym(g_w1f), *w2f=(f16*)sym(g_w2f);
    f16 *qph=(f16*)sym(g_qph), *qpl=(f16*)sym(g_qpl);
    f16 *kpf=(f16*)sym(g_kpf), *vtf=(f16*)sym(g_vtf);
    f16 *ctxh=(f16*)sym(g_ctxh), *ctxl=(f16*)sym(g_ctxl);
    f16 *hh=(f16*)sym(g_hh), *hl=(f16*)sym(g_hl);
    f16 *h1h=(f16*)sym(g_h1h), *h1l=(f16*)sym(g_h1l);

    cudaFuncSetAttribute((const void*)k_gemm<0,OUT_F16HL>, cudaFuncAttributeMaxDynamicSharedMemorySize, DSMEM2);
    cudaFuncSetAttribute((const void*)k_gemm<2,OUT_F16HL>, cudaFuncAttributeMaxDynamicSharedMemorySize, DSMEM2);
    cudaFuncSetAttribute((const void*)k_gemm<0,OUT_F16>,   cudaFuncAttributeMaxDynamicSharedMemorySize, DSMEM2);
    cudaFuncSetAttribute((const void*)k_gemm<0,OUT_VT>,    cudaFuncAttributeMaxDynamicSharedMemorySize, DSMEM2);
    cudaFuncSetAttribute((const void*)k_gemm<0,OUT_F32ADD>,cudaFuncAttributeMaxDynamicSharedMemorySize, DSMEM2);
    cudaFuncSetAttribute((const void*)k_attn, cudaFuncAttributeMaxDynamicSharedMemorySize, ATTN_SMEM);

    const dim3 blk(256);
    const dim3 dblk(DNT);

    // conversions
    k_cvt_hl<<<(int)((size_t)BATCH*NKV*DMODEL/1024), blk>>>(x, xh, xl);
    k_cvt16<<<(int)((size_t)DMODEL*DMODEL/1024), blk>>>(w_v, wvf);
    k_cvt16<<<(int)((size_t)DMODEL*DMODEL/1024), blk>>>(w_k, wkf);
    k_cvt_hl<<<(int)((size_t)BATCH*MQ*DMODEL/1024), blk>>>(q, qh, ql);
    k_cvt16<<<(int)((size_t)DMODEL*DMODEL/1024), blk>>>(w_q, wqf);

    // V projection -> transposed single fp16
    k_gemm<0,OUT_VT><<<dim3(DMODEL/DTN, 64), dblk, DSMEM2>>>(xh, xl, wvf, b_v, nullptr,
        nullptr, vtf, nullptr, DMODEL, 0, 0);
    // K projection -> single fp16
    k_gemm<0,OUT_F16><<<dim3(DMODEL/DTN, 64), dblk, DSMEM2>>>(xh, xl, wkf, b_k, nullptr,
        nullptr, kpf, nullptr, DMODEL, DMODEL, 0);
    // Q projection -> fp16 hi/lo
    k_gemm<0,OUT_F16HL><<<dim3(DMODEL/DTN, 32), dblk, DSMEM2>>>(qh, ql, wqf, b_q, nullptr,
        nullptr, qph, qpl, DMODEL, DMODEL, 0);

    // fused attention
    k_attn<<<dim3(ZHB, MQ/128), blk, ATTN_SMEM>>>(qph, qpl, kpf, vtf,
                                                  attn, ctxh, ctxl);

    // remaining weight conversions
    k_cvt16<<<(int)((size_t)DMODEL*DMODEL/1024), blk>>>(w_o, wof);
    k_cvt16<<<(int)((size_t)DMLP*DMODEL/1024), blk>>>(w1, w1f);
    k_cvt16<<<(int)((size_t)DMODEL*DMLP/1024), blk>>>(w2, w2f);

    // resid = ctx @ w_o^T + b_o + q
    k_gemm<0,OUT_F32ADD><<<dim3(DMODEL/DTN, 32), dblk, DSMEM2>>>(ctxh, ctxl, wof, b_o, q,
        resid, nullptr, nullptr, DMODEL, DMODEL, DMODEL);

    // h = LN(resid) -> fp16 hi/lo
    k_ln<<<BATCH*MQ, blk>>>(resid, ln2g, ln2b, hh, hl);

    // h1 = gelu(h @ w1^T + b1) -> fp16 hi/lo
    k_gemm<2,OUT_F16HL><<<dim3(DMLP/DTN, 32), dblk, DSMEM2>>>(hh, hl, w1f, b1, nullptr,
        nullptr, h1h, h1l, DMODEL, DMLP, 0);

    // out = h1 @ w2^T + b2 + resid
    k_gemm<0,OUT_F32ADD><<<dim3(DMODEL/DTN, 32), dblk, DSMEM2>>>(h1h, h1l, w2f, b2, resid,
        out, nullptr, nullptr, DMLP, DMODEL, DMODEL);
}

// round 11
// speedup vs baseline: 10.2531x; 1.4216x over previous
#include <cuda_runtime.h>
#include <cuda_fp16.h>
#include <math.h>
#include <stdint.h>

// ---------------- problem constants ----------------
#define BATCH  4
#define MQ     1024
#define NKV    2048
#define DMODEL 1024
#define NHEAD  16
#define HDIM   64
#define DMLP   4096
#define ZHB    (NHEAD*BATCH)

typedef __half f16;

// ---------------- scratch (device globals; no allocs allowed) ----------------
__device__ __align__(1024) float g_resid[(size_t)BATCH*MQ*DMODEL];

__device__ __align__(1024) f16 g_qf [(size_t)BATCH*MQ*DMODEL];
__device__ __align__(1024) f16 g_xf [(size_t)BATCH*NKV*DMODEL];
__device__ __align__(1024) f16 g_wqf[(size_t)DMODEL*DMODEL];
__device__ __align__(1024) f16 g_wkf[(size_t)DMODEL*DMODEL];
__device__ __align__(1024) f16 g_wvf[(size_t)DMODEL*DMODEL];
__device__ __align__(1024) f16 g_wof[(size_t)DMODEL*DMODEL];
__device__ __align__(1024) f16 g_w1f[(size_t)DMLP*DMODEL];
__device__ __align__(1024) f16 g_w2f[(size_t)DMODEL*DMLP];
__device__ __align__(1024) f16 g_qpf[(size_t)BATCH*MQ*DMODEL];
__device__ __align__(1024) f16 g_kpf[(size_t)BATCH*NKV*DMODEL];
__device__ __align__(1024) f16 g_vtf[(size_t)ZHB*HDIM*NKV];
__device__ __align__(1024) f16 g_ctxf[(size_t)BATCH*MQ*DMODEL];
__device__ __align__(1024) f16 g_hf [(size_t)BATCH*MQ*DMODEL];
__device__ __align__(1024) f16 g_h1f[(size_t)BATCH*MQ*DMLP];

// ---------------- helpers ----------------
#define SW128(o) ((uint32_t)(o) ^ ((((uint32_t)(o)) >> 3) & 0x70u))

__device__ __forceinline__ uint32_t smem_u32(const void* p) {
    return (uint32_t)__cvta_generic_to_shared(p);
}

__device__ __forceinline__ void cp16(uint32_t dst, const void* src) {
    asm volatile("cp.async.cg.shared.global [%0], [%1], 16;" :: "r"(dst), "l"(src));
}
#define CP_COMMIT() asm volatile("cp.async.commit_group;" ::: "memory")
#define CP_WAIT0()  asm volatile("cp.async.wait_group 0;" ::: "memory")
#define CP_WAIT1()  asm volatile("cp.async.wait_group 1;" ::: "memory")
#define CP_WAIT2()  asm volatile("cp.async.wait_group 2;" ::: "memory")

#define LDSM4(r0, r1, r2, r3, addr) \
    asm volatile("ldmatrix.sync.aligned.m8n8.x4.shared.b16 {%0,%1,%2,%3}, [%4];" \
        : "=r"(r0), "=r"(r1), "=r"(r2), "=r"(r3) : "r"(addr))

__device__ __forceinline__ void mma_f16(float* c, const uint32_t* a, const uint32_t* b) {
    asm volatile(
        "mma.sync.aligned.m16n8k16.row.col.f32.f16.f16.f32 "
        "{%0,%1,%2,%3}, {%4,%5,%6,%7}, {%8,%9}, {%0,%1,%2,%3};"
        : "+f"(c[0]), "+f"(c[1]), "+f"(c[2]), "+f"(c[3])
        : "r"(a[0]), "r"(a[1]), "r"(a[2]), "r"(a[3]), "r"(b[0]), "r"(b[1]));
}

__device__ __forceinline__ float ex2(float x) {
    float r;
    asm("ex2.approx.f32 %0, %1;" : "=f"(r) : "f"(x));
    return r;
}

__device__ __forceinline__ float gelu_exact(float v) {
    return 0.5f * v * (1.0f + erff(v * 0.70710678118654752440f));
}

__device__ __forceinline__ uint32_t pack2h(float e0, float e1) {
    __half2 hp = __floats2half2_rn(e0, e1);
    return *reinterpret_cast<uint32_t*>(&hp);
}

// ============================================================================
//   single-term fp16 GEMM: A fp16, B fp16, fp32 accumulate.
//   TN=64, 256 threads, MI=2, 48KB stages.
// ============================================================================
#define DNT 256
#define DTN 64
#define OUT_F32ADD 0   // fp32, + Dadd
#define OUT_F16    1   // single fp16 (EPI==2 -> gelu)
#define OUT_VT     2   // transposed per-head single fp16 (V projection)

template<int EPI, int OUT>
__device__ void tc_gemm1(
    const f16* __restrict__ A, const f16* __restrict__ Bs,
    const float* __restrict__ bias, const float* __restrict__ Dadd,
    float* __restrict__ C, f16* __restrict__ Cf,
    int K, int lda, int ldb, int ldc, int ldd)
{
    extern __shared__ char smem[];
    constexpr int TN = DTN;
    constexpr int A_BYTES = 128 * 128;           // 16384
    constexpr int B_BYTES = TN * 128;            // 8192
    constexpr int STAGE   = A_BYTES + B_BYTES;   // 24576
    constexpr int MI = 2;

    const uint32_t sb = smem_u32(smem);
    const int tid  = threadIdx.x;
    const int wid  = tid >> 5;
    const int lane = tid & 31;
    const int m0 = blockIdx.y * 128;
    const int n0 = blockIdx.x * TN;
    const int wm0 = (wid / 2) * 32;
    const int wn0 = (wid % 2) * 32;

    float acc[MI][4][4];
    #pragma unroll
    for (int mi = 0; mi < MI; mi++)
        #pragma unroll
        for (int ni = 0; ni < 4; ni++)
            #pragma unroll
            for (int e = 0; e < 4; e++) acc[mi][ni][e] = 0.0f;

    auto load1 = [&](uint32_t st, long long kc) {
        #pragma unroll
        for (int it = 0; it < 4; it++) {
            int idx = tid + it * 256;
            int r = idx >> 3, c = idx & 7;
            uint32_t so = SW128(r * 128 + c * 16);
            cp16(st + so, A + (long long)(m0 + r) * lda + kc + c * 8);
        }
        #pragma unroll
        for (int it = 0; it < 2; it++) {
            int idx = tid + it * 256;
            int r = idx >> 3, c = idx & 7;
            uint32_t so = SW128(r * 128 + c * 16);
            cp16(st + A_BYTES + so, Bs + (long long)(n0 + r) * ldb + kc + c * 8);
        }
        CP_COMMIT();
    };

    const int NC = K >> 6;
    load1(sb, 0);
    if (NC > 1) load1(sb + STAGE, 64);

    for (int i = 0; i < NC; i++) {
        if (i + 1 < NC) { CP_WAIT1(); } else { CP_WAIT0(); }
        __syncthreads();

        const uint32_t st = sb + (i & 1) * STAGE;
        #pragma unroll
        for (int kk = 0; kk < 4; kk++) {
            uint32_t ah[MI][4], bh[4][2];
            const int colA = kk * 32 + ((lane & 16) ? 16 : 0);
            const int rA   = lane & 15;
            #pragma unroll
            for (int mi = 0; mi < MI; mi++) {
                uint32_t off = SW128((uint32_t)(wm0 + mi * 16 + rA) * 128 + colA);
                LDSM4(ah[mi][0], ah[mi][1], ah[mi][2], ah[mi][3], st + off);
            }
            const int colB = kk * 32 + ((lane & 8) ? 16 : 0);
            const int rB   = (lane & 7) + ((lane & 16) ? 8 : 0);
            #pragma unroll
            for (int nj = 0; nj < 2; nj++) {
                uint32_t off = SW128((uint32_t)(wn0 + nj * 16 + rB) * 128 + colB);
                LDSM4(bh[nj*2][0], bh[nj*2][1], bh[nj*2+1][0], bh[nj*2+1][1],
                      st + A_BYTES + off);
            }
            #pragma unroll
            for (int mi = 0; mi < MI; mi++)
                #pragma unroll
                for (int ni = 0; ni < 4; ni++)
                    mma_f16(acc[mi][ni], ah[mi], bh[ni]);
        }
        __syncthreads();
        if (i + 2 < NC) load1(sb + (i & 1) * STAGE, (long long)(i + 2) * 64);
    }

    constexpr int LDS = (OUT == OUT_VT) ? (TN + 1) : (TN + 8);
    float* sOut = (float*)smem;
    __syncthreads();

    #pragma unroll
    for (int mi = 0; mi < MI; mi++) {
        const int r0 = wm0 + mi * 16 + (lane >> 2);
        #pragma unroll
        for (int ni = 0; ni < 4; ni++) {
            const int c0 = wn0 + ni * 8 + (lane & 3) * 2;
            sOut[r0 * LDS + c0]           = acc[mi][ni][0];
            sOut[r0 * LDS + c0 + 1]       = acc[mi][ni][1];
            sOut[(r0 + 8) * LDS + c0]     = acc[mi][ni][2];
            sOut[(r0 + 8) * LDS + c0 + 1] = acc[mi][ni][3];
        }
    }
    __syncthreads();

    if (OUT == OUT_VT) {
        // write C^T per head as single fp16 (all 128 rows per tile)
        const int bb = m0 / NKV;
        const int nb = m0 % NKV;
        const int colw = tid >> 5;
        #pragma unroll
        for (int cp = 0; cp < 8; cp++) {
            const int col = colw + cp * 8;
            const int e = n0 + col;
            const int hh2 = e >> 6, dd = e & 63;
            const long long base =
                ((long long)(hh2 * BATCH + bb) * HDIM + dd) * NKV + nb;
            const float bv = bias[e];
            #pragma unroll
            for (int rh = 0; rh < 2; rh++) {
                const int row0 = rh * 64 + 2 * lane;
                const float v0 = sOut[row0       * LDS + col] + bv;
                const float v1 = sOut[(row0 + 1) * LDS + col] + bv;
                *(uint32_t*)(Cf + base + row0) = pack2h(v0, v1);
            }
        }
        return;
    }

    const int c = tid & (TN - 1);
    const int rs = tid / TN;
    const int n = n0 + c;
    #pragma unroll 4
    for (int rr = 0; rr < 128; rr += 4) {
        const int r = rr + rs;
        float v = sOut[r * LDS + c] + bias[n];
        const long long o = (long long)(m0 + r) * ldc + n;
        if (OUT == OUT_F32ADD) {
            C[o] = v + Dadd[(long long)(m0 + r) * ldd + n];
        } else {
            if (EPI == 2) v = gelu_exact(v);
            Cf[o] = __float2half_rn(v);
        }
    }
}

template<int EPI, int OUT>
__global__ void __launch_bounds__(DNT)
k_gemm(const f16* A, const f16* Bs,
       const float* bias, const float* Dadd,
       float* C, f16* Cf, int K, int ldc, int ldd)
{
    tc_gemm1<EPI, OUT>(A, Bs, bias, Dadd, C, Cf, K, K, K, ldc, ldd);
}

#define DSMEM1 (2 * (16384 + DTN * 128))   // 49152

// ============================================================================
//   fused attention, single-term fp16: S = QK; PV; attn normalized in-kernel.
// ============================================================================
#define ATTN_SMEM (16384 + 2*32768)   // Q + 2 stages x (K 16K + V 16K) = 81920
#define NCH (NKV/128)

__device__ __forceinline__ void load_kv(
    uint32_t st, const f16* __restrict__ kp, const f16* __restrict__ vt,
    int ci, int tid)
{
    #pragma unroll
    for (int it = 0; it < 4; it++) {
        int idx = tid + it * 256;
        int r = idx >> 3, c = idx & 7;
        uint32_t so = SW128((uint32_t)r * 128 + c * 16);
        cp16(st + so, kp + (long long)(ci * 128 + r) * DMODEL + c * 8);
    }
    #pragma unroll
    for (int it = 0; it < 4; it++) {
        int idx = tid + it * 256;
        int hf = idx >> 9, d = (idx >> 3) & 63, c = idx & 7;
        uint32_t so = (uint32_t)hf * 8192 + SW128((uint32_t)d * 128 + c * 16);
        cp16(st + 16384 + so, vt + (long long)d * NKV + ci * 128 + hf * 64 + c * 8);
    }
    CP_COMMIT();
}

__global__ void __launch_bounds__(256, 1)
k_attn(const f16* __restrict__ qpf, const f16* __restrict__ kpf,
       const f16* __restrict__ vtf,
       float* __restrict__ attn, f16* __restrict__ ctxf)
{
    extern __shared__ char smem[];
    const uint32_t sb = smem_u32(smem);
    const int tid = threadIdx.x, wid = tid >> 5, lane = tid & 31;
    const int z  = blockIdx.x;            // h*BATCH + b
    const int h  = z / BATCH, b = z % BATCH;
    const int m0 = blockIdx.y * 128;
    const int wm0 = wid * 16;

    const f16* khb = kpf + (long long)b * NKV * DMODEL + h * HDIM;
    const f16* vtb = vtf + (long long)z * HDIM * NKV;
    float* attn_w = attn + ((long long)z * MQ + m0 + wm0) * NKV;

    const uint32_t sQ = sb;
    const uint32_t sS = sb + 16384;

    {
        const f16* q0 = qpf + ((long long)(b * MQ + m0)) * DMODEL + h * HDIM;
        #pragma unroll
        for (int it = 0; it < 4; it++) {
            int idx = tid + it * 256;
            int r = idx >> 3, c = idx & 7;
            uint32_t so = SW128((uint32_t)r * 128 + c * 16);
            cp16(sQ + so, q0 + (long long)r * DMODEL + c * 8);
        }
        CP_COMMIT();
    }
    load_kv(sS,         khb, vtb, 0, tid);
    load_kv(sS + 32768, khb, vtb, 1, tid);

    CP_WAIT2();
    __syncthreads();

    // preload Q fragments (persistent)
    uint32_t qf[4][4];
    {
        const int rA = lane & 15;
        #pragma unroll
        for (int kk = 0; kk < 4; kk++) {
            const int colA = kk * 32 + ((lane & 16) ? 16 : 0);
            uint32_t off = SW128((uint32_t)(wm0 + rA) * 128 + colA);
            LDSM4(qf[kk][0], qf[kk][1], qf[kk][2], qf[kk][3], sQ + off);
        }
    }

    float cacc[8][4];
    #pragma unroll
    for (int i = 0; i < 8; i++)
        #pragma unroll
        for (int e = 0; e < 4; e++) cacc[i][e] = 0.0f;
    float lp0 = 0.0f, lp1 = 0.0f;

    const int rB   = (lane & 7) + ((lane & 16) ? 8 : 0);
    const int r    = lane >> 2;
    const int c2   = (lane & 3) * 2;
    const float CE = 0.125f * 1.4426950408889634f;

    for (int ci = 0; ci < NCH; ci++) {
        if (ci + 1 < NCH) { CP_WAIT1(); } else { CP_WAIT0(); }
        __syncthreads();
        const uint32_t st = sS + (ci & 1) * 32768;

        // ---- S = Q K^T ----
        float sacc[16][4];
        #pragma unroll
        for (int t = 0; t < 16; t++)
            #pragma unroll
            for (int e = 0; e < 4; e++) sacc[t][e] = 0.0f;

        #pragma unroll
        for (int kk = 0; kk < 4; kk++) {
            const int colB = kk * 32 + ((lane & 8) ? 16 : 0);
            #pragma unroll
            for (int nt = 0; nt < 8; nt++) {
                uint32_t off = SW128((uint32_t)(nt * 16 + rB) * 128 + colB);
                uint32_t bh[4];
                LDSM4(bh[0], bh[1], bh[2], bh[3], st + off);
                mma_f16(sacc[2*nt],   qf[kk], bh);
                mma_f16(sacc[2*nt+1], qf[kk], bh + 2);
            }
        }

        // ---- p = exp(S/8); write unnormalized attn; row sums ----
        float* a0 = attn_w + (long long)r * NKV + ci * 128;
        float* a1 = a0 + 8 * NKV;
        #pragma unroll
        for (int t = 0; t < 16; t++) {
            float p0 = ex2(sacc[t][0] * CE);
            float p1 = ex2(sacc[t][1] * CE);
            float p2 = ex2(sacc[t][2] * CE);
            float p3 = ex2(sacc[t][3] * CE);
            sacc[t][0] = p0; sacc[t][1] = p1; sacc[t][2] = p2; sacc[t][3] = p3;
            lp0 += p0 + p1;  lp1 += p2 + p3;
            *(float2*)(a0 + t * 8 + c2) = make_float2(p0, p1);
            *(float2*)(a1 + t * 8 + c2) = make_float2(p2, p3);
        }

        // ---- ctx += P V (P packed single fp16) ----
        #pragma unroll
        for (int ks = 0; ks < 8; ks++) {
            uint32_t ah[4];
            ah[0] = pack2h(sacc[2*ks][0],   sacc[2*ks][1]);
            ah[1] = pack2h(sacc[2*ks][2],   sacc[2*ks][3]);
            ah[2] = pack2h(sacc[2*ks+1][0], sacc[2*ks+1][1]);
            ah[3] = pack2h(sacc[2*ks+1][2], sacc[2*ks+1][3]);

            const int hf = ks >> 2;
            const int colB = (ks & 3) * 32 + ((lane & 8) ? 16 : 0);
            const uint32_t v_base = st + 16384 + hf * 8192;
            #pragma unroll
            for (int dt = 0; dt < 4; dt++) {
                uint32_t off = SW128((uint32_t)(dt * 16 + rB) * 128 + colB);
                uint32_t bh[4];
                LDSM4(bh[0], bh[1], bh[2], bh[3], v_base + off);
                mma_f16(cacc[2*dt],   ah, bh);
                mma_f16(cacc[2*dt+1], ah, bh + 2);
            }
        }

        __syncthreads();
        if (ci + 2 < NCH)
            load_kv(sS + (ci & 1) * 32768, khb, vtb, ci + 2, tid);
    }

    // ---- row sums -> inverse; ctx write; in-kernel attn normalize ----
    lp0 += __shfl_xor_sync(0xFFFFFFFFu, lp0, 1);
    lp0 += __shfl_xor_sync(0xFFFFFFFFu, lp0, 2);
    lp1 += __shfl_xor_sync(0xFFFFFFFFu, lp1, 1);
    lp1 += __shfl_xor_sync(0xFFFFFFFFu, lp1, 2);
    const float il0 = 1.0f / lp0, il1 = 1.0f / lp1;

    float* ssum = (float*)smem;          // stage smem retired
    if ((lane & 3) == 0) {
        ssum[wm0 + r]     = il0;
        ssum[wm0 + r + 8] = il1;
    }

    const long long cb = ((long long)(b * MQ + m0 + wm0)) * DMODEL + h * HDIM;
    #pragma unroll
    for (int dt = 0; dt < 8; dt++) {
        const int d0 = dt * 8 + c2;
        *(uint32_t*)(ctxf + cb + (long long)r * DMODEL + d0) =
            pack2h(cacc[dt][0] * il0, cacc[dt][1] * il0);
        *(uint32_t*)(ctxf + cb + (long long)(r + 8) * DMODEL + d0) =
            pack2h(cacc[dt][2] * il1, cacc[dt][3] * il1);
    }

    __syncthreads();   // orders p-writes + ssum for all warps

    float* ab = attn + ((long long)z * MQ + m0) * NKV;
    for (int rr = 0; rr < 128; rr += 8) {
        const int row = rr + wid;
        const float s = ssum[row];
        float4* p4 = (float4*)(ab + (long long)row * NKV);
        #pragma unroll
        for (int j = 0; j < 16; j++) {
            float4 v = p4[lane + 32 * j];
            v.x *= s; v.y *= s; v.z *= s; v.w *= s;
            p4[lane + 32 * j] = v;
        }
    }
}

// ---------------- fp32 -> single fp16 ----------------
__global__ void __launch_bounds__(256)
k_cvt16(const float* __restrict__ x, f16* __restrict__ o)
{
    const long long i = ((long long)blockIdx.x * 256 + threadIdx.x) * 4;
    const float4 v = *(const float4*)(x + i);
    __half2 p0 = __floats2half2_rn(v.x, v.y);
    __half2 p1 = __floats2half2_rn(v.z, v.w);
    *(uint32_t*)(o + i)     = *reinterpret_cast<uint32_t*>(&p0);
    *(uint32_t*)(o + i + 2) = *reinterpret_cast<uint32_t*>(&p1);
}

// ---------------- layernorm -> single fp16 ----------------
__global__ void __launch_bounds__(256)
k_ln(const float* __restrict__ x, const float* __restrict__ g,
     const float* __restrict__ b, f16* __restrict__ o)
{
    __shared__ float r1[256], r2[256];
    const long long row = blockIdx.x;
    const float* p = x + row * (long long)DMODEL;
    const int t = threadIdx.x;

    float v[4]; float s = 0.0f, s2 = 0.0f;
    #pragma unroll
    for (int i = 0; i < 4; i++) {
        v[i] = p[t + i * 256];
        s += v[i]; s2 += v[i] * v[i];
    }
    r1[t] = s; r2[t] = s2; __syncthreads();
    for (int st = 128; st > 0; st >>= 1) {
        if (t < st) { r1[t] += r1[t + st]; r2[t] += r2[t + st]; }
        __syncthreads();
    }
    const float mu  = r1[0] * (1.0f / DMODEL);
    const float var = r2[0] * (1.0f / DMODEL) - mu * mu;
    const float inv = rsqrtf(var + 1e-5f);

    f16* po = o + row * (long long)DMODEL;
    #pragma unroll
    for (int i = 0; i < 4; i++) {
        const int c = t + i * 256;
        po[c] = __float2half_rn((v[i] - mu) * inv * g[c] + b[c]);
    }
}

// ---------------- host launch ----------------
static void* sym(const void* s) { void* p; cudaGetSymbolAddress(&p, s); return p; }

extern "C" void kernel_launch(void* const* d_in, const int* in_sizes, int n_in,
                              void* d_out, int out_size)
{
    const float* x    = (const float*)d_in[0];
    const float* q    = (const float*)d_in[1];
    const float* w_q  = (const float*)d_in[2];
    const float* b_q  = (const float*)d_in[3];
    const float* w_k  = (const float*)d_in[4];
    const float* b_k  = (const float*)d_in[5];
    const float* w_v  = (const float*)d_in[6];
    const float* b_v  = (const float*)d_in[7];
    const float* w_o  = (const float*)d_in[8];
    const float* b_o  = (const float*)d_in[9];
    const float* ln2g = (const float*)d_in[10];
    const float* ln2b = (const float*)d_in[11];
    const float* w1   = (const float*)d_in[12];
    const float* b1   = (const float*)d_in[13];
    const float* w2   = (const float*)d_in[14];
    const float* b2   = (const float*)d_in[15];

    float* out  = (float*)d_out;
    float* attn = out + (long long)BATCH * MQ * DMODEL;

    float* resid = (float*)sym(g_resid);
    f16 *qf=(f16*)sym(g_qf), *xf=(f16*)sym(g_xf);
    f16 *wqf=(f16*)sym(g_wqf), *wkf=(f16*)sym(g_wkf);
    f16 *wvf=(f16*)sym(g_wvf), *wof=(f16*)sym(g_wof);
    f16 *w1f=(f16*)sym(g_w1f), *w2f=(f16*)sym(g_w2f);
    f16 *qpf=(f16*)sym(g_qpf), *kpf=(f16*)sym(g_kpf), *vtf=(f16*)sym(g_vtf);
    f16 *ctxf=(f16*)sym(g_ctxf);
    f16 *hf=(f16*)sym(g_hf), *h1f=(f16*)sym(g_h1f);

    cudaFuncSetAttribute((const void*)k_gemm<0,OUT_F16>,   cudaFuncAttributeMaxDynamicSharedMemorySize, DSMEM1);
    cudaFuncSetAttribute((const void*)k_gemm<2,OUT_F16>,   cudaFuncAttributeMaxDynamicSharedMemorySize, DSMEM1);
    cudaFuncSetAttribute((const void*)k_gemm<0,OUT_VT>,    cudaFuncAttributeMaxDynamicSharedMemorySize, DSMEM1);
    cudaFuncSetAttribute((const void*)k_gemm<0,OUT_F32ADD>,cudaFuncAttributeMaxDynamicSharedMemorySize, DSMEM1);
    cudaFuncSetAttribute((const void*)k_attn, cudaFuncAttributeMaxDynamicSharedMemorySize, ATTN_SMEM);

    const dim3 blk(256);
    const dim3 dblk(DNT);
    #define C16(src, dst, nelem) k_cvt16<<<(int)((nelem) / 1024), blk>>>(src, dst)

    // conversions
    C16(x,   xf,  (size_t)BATCH*NKV*DMODEL);
    C16(w_v, wvf, (size_t)DMODEL*DMODEL);
    C16(w_k, wkf, (size_t)DMODEL*DMODEL);
    C16(q,   qf,  (size_t)BATCH*MQ*DMODEL);
    C16(w_q, wqf, (size_t)DMODEL*DMODEL);

    // V projection -> transposed single fp16
    k_gemm<0,OUT_VT><<<dim3(DMODEL/DTN, 64), dblk, DSMEM1>>>(xf, wvf, b_v, nullptr,
        nullptr, vtf, DMODEL, 0, 0);
    // K projection -> single fp16
    k_gemm<0,OUT_F16><<<dim3(DMODEL/DTN, 64), dblk, DSMEM1>>>(xf, wkf, b_k, nullptr,
        nullptr, kpf, DMODEL, DMODEL, 0);
    // Q projection -> single fp16
    k_gemm<0,OUT_F16><<<dim3(DMODEL/DTN, 32), dblk, DSMEM1>>>(qf, wqf, b_q, nullptr,
        nullptr, qpf, DMODEL, DMODEL, 0);

    // fused attention
    k_attn<<<dim3(ZHB, MQ/128), blk, ATTN_SMEM>>>(qpf, kpf, vtf, attn, ctxf);

    // remaining weight conversions
    C16(w_o, wof, (size_t)DMODEL*DMODEL);
    C16(w1,  w1f, (size_t)DMLP*DMODEL);
    C16(w2,  w2f, (size_t)DMODEL*DMLP);

    // resid = ctx @ w_o^T + b_o + q
    k_gemm<0,OUT_F32ADD><<<dim3(DMODEL/DTN, 32), dblk, DSMEM1>>>(ctxf, wof, b_o, q,
        resid, nullptr, DMODEL, DMODEL, DMODEL);

    // h = LN(resid) -> fp16
    k_ln<<<BATCH*MQ, blk>>>(resid, ln2g, ln2b, hf);

    // h1 = gelu(h @ w1^T + b1) -> fp16
    k_gemm<2,OUT_F16><<<dim3(DMLP/DTN, 32), dblk, DSMEM1>>>(hf, w1f, b1, nullptr,
        nullptr, h1f, DMODEL, DMLP, 0);

    // out = h1 @ w2^T + b2 + resid
    k_gemm<0,OUT_F32ADD><<<dim3(DMODEL/DTN, 32), dblk, DSMEM1>>>(h1f, w2f, b2, resid,
        out, nullptr, DMLP, DMODEL, DMODEL);

    #undef C16
}